// round 3
// baseline (speedup 1.0000x reference)
#include <cuda_runtime.h>

#define TOK   4096      // B*S tokens
#define DMOD  2048      // model dim
#define SEQ   2048      // sequence length
#define NHEAD 16
#define DKH   128       // head dim

// Scratch (device globals: allocation-free per harness rules)
__device__ float g_Qp[(size_t)TOK * DMOD];
__device__ float g_Kp[(size_t)TOK * DMOD];
__device__ float g_Vp[(size_t)TOK * DMOD];
__device__ float g_AO[(size_t)TOK * DMOD];

// ---------------------------------------------------------------------------
// Tiled fp32 GEMM + bias:  C[M,N] = A[M,K] @ B[K,N] + bias[N]
// 128x128 CTA tile, BK=16, 256 threads, 8x8 per thread.
// ---------------------------------------------------------------------------
__global__ __launch_bounds__(256, 2)
void gemm_bias_kernel(const float* __restrict__ A, const float* __restrict__ B,
                      const float* __restrict__ bias, float* __restrict__ C,
                      int M, int N, int Kdim)
{
    __shared__ float As[16][128];   // transposed A tile: As[k][m]
    __shared__ float Bs[16][128];   // Bs[k][n]

    const int tid = threadIdx.x;
    const int tn = tid & 15;        // 0..15 -> 8 output cols each
    const int tm = tid >> 4;        // 0..15 -> 8 output rows each
    const int m0 = blockIdx.y << 7;
    const int n0 = blockIdx.x << 7;

    float acc[8][8];
    #pragma unroll
    for (int i = 0; i < 8; i++)
        #pragma unroll
        for (int j = 0; j < 8; j++)
            acc[i][j] = 0.f;

    for (int k0 = 0; k0 < Kdim; k0 += 16) {
        // A tile: 128 rows x 16 cols = 512 float4, 2 per thread (coalesced)
        #pragma unroll
        for (int t = 0; t < 2; t++) {
            int f   = tid + t * 256;           // 0..511
            int row = f >> 2;                  // 0..127
            int kq  = (f & 3) << 2;            // 0,4,8,12
            float4 a = *(const float4*)&A[(size_t)(m0 + row) * Kdim + k0 + kq];
            As[kq + 0][row] = a.x;
            As[kq + 1][row] = a.y;
            As[kq + 2][row] = a.z;
            As[kq + 3][row] = a.w;
        }
        // B tile: 16 rows x 128 cols = 512 float4, 2 per thread (coalesced)
        #pragma unroll
        for (int t = 0; t < 2; t++) {
            int f   = tid + t * 256;
            int row = f >> 5;                  // 0..15
            int c4  = (f & 31) << 2;           // 0..124
            *(float4*)&Bs[row][c4] =
                *(const float4*)&B[(size_t)(k0 + row) * N + n0 + c4];
        }
        __syncthreads();

        #pragma unroll
        for (int k = 0; k < 16; k++) {
            float a[8], b[8];
            *(float4*)&a[0] = *(const float4*)&As[k][(tm << 3) + 0];
            *(float4*)&a[4] = *(const float4*)&As[k][(tm << 3) + 4];
            *(float4*)&b[0] = *(const float4*)&Bs[k][(tn << 3) + 0];
            *(float4*)&b[4] = *(const float4*)&Bs[k][(tn << 3) + 4];
            #pragma unroll
            for (int i = 0; i < 8; i++)
                #pragma unroll
                for (int j = 0; j < 8; j++)
                    acc[i][j] += a[i] * b[j];
        }
        __syncthreads();
    }

    // Epilogue with bias
    float bv[8];
    #pragma unroll
    for (int j = 0; j < 8; j++) bv[j] = bias[n0 + (tn << 3) + j];

    #pragma unroll
    for (int i = 0; i < 8; i++) {
        size_t row = (size_t)(m0 + (tm << 3) + i);
        float4 o0, o1;
        o0.x = acc[i][0] + bv[0]; o0.y = acc[i][1] + bv[1];
        o0.z = acc[i][2] + bv[2]; o0.w = acc[i][3] + bv[3];
        o1.x = acc[i][4] + bv[4]; o1.y = acc[i][5] + bv[5];
        o1.z = acc[i][6] + bv[6]; o1.w = acc[i][7] + bv[7];
        *(float4*)&C[row * N + n0 + (tn << 3) + 0] = o0;
        *(float4*)&C[row * N + n0 + (tn << 3) + 4] = o1;
    }
}

// ---------------------------------------------------------------------------
// Flash attention (fp32): per CTA: one (b, h), 64 query rows.
// Online softmax, row stats replicated across the 16 lanes owning a row.
// Thread map: tm = tid>>4 (row group: rows tm*4..tm*4+3), tx = tid&15.
//   S tile:  thread owns s[4][4] at cols tx*4..
//   O tile:  thread owns acc[4][8] at cols tx*8..
// ---------------------------------------------------------------------------
#define FA_BM 64
#define FA_BN 64
#define KSTRIDE 129   // padded K-tile stride (bank-conflict reduction)

__global__ __launch_bounds__(256, 2)
void flash_attn_kernel(const float* __restrict__ Q, const float* __restrict__ K,
                       const float* __restrict__ V, float* __restrict__ O)
{
    extern __shared__ float sm[];
    float* Qs = sm;                                 // [64][128]
    float* Ks = Qs + FA_BM * DKH;                   // [64][129]
    float* Vs = Ks + FA_BN * KSTRIDE;               // [64][128]
    float* Ps = Vs + FA_BN * DKH;                   // [64][64]

    const int tid = threadIdx.x;
    const int tx  = tid & 15;
    const int tm  = tid >> 4;
    const int b   = blockIdx.z;
    const int h   = blockIdx.y;
    const int q0  = blockIdx.x * FA_BM;

    const size_t base = ((size_t)b * SEQ) * DMOD + (size_t)h * DKH;
    const float scale = 0.08838834764831845f;   // 1/sqrt(128)

    // Load Q tile: 64x128 = 2048 float4, 8 per thread, coalesced
    #pragma unroll
    for (int t = 0; t < 8; t++) {
        int f   = tid + t * 256;
        int row = f >> 5;
        int c4  = (f & 31) << 2;
        *(float4*)&Qs[row * DKH + c4] =
            *(const float4*)&Q[base + (size_t)(q0 + row) * DMOD + c4];
    }

    float acc[4][8];
    #pragma unroll
    for (int i = 0; i < 4; i++)
        #pragma unroll
        for (int j = 0; j < 8; j++) acc[i][j] = 0.f;
    float m_i[4], l_i[4];
    #pragma unroll
    for (int i = 0; i < 4; i++) { m_i[i] = -1e30f; l_i[i] = 0.f; }

    for (int n0 = 0; n0 < SEQ; n0 += FA_BN) {
        // Load K (padded, scalar stores) and V (vector stores)
        #pragma unroll
        for (int t = 0; t < 8; t++) {
            int f   = tid + t * 256;
            int row = f >> 5;
            int c4  = (f & 31) << 2;
            float4 kv = *(const float4*)&K[base + (size_t)(n0 + row) * DMOD + c4];
            Ks[row * KSTRIDE + c4 + 0] = kv.x;
            Ks[row * KSTRIDE + c4 + 1] = kv.y;
            Ks[row * KSTRIDE + c4 + 2] = kv.z;
            Ks[row * KSTRIDE + c4 + 3] = kv.w;
            *(float4*)&Vs[row * DKH + c4] =
                *(const float4*)&V[base + (size_t)(n0 + row) * DMOD + c4];
        }
        __syncthreads();

        // S = (Q @ K^T)   thread: 4x4 micro-tile
        float s[4][4];
        #pragma unroll
        for (int i = 0; i < 4; i++)
            #pragma unroll
            for (int j = 0; j < 4; j++) s[i][j] = 0.f;

        for (int kk = 0; kk < DKH; kk++) {
            float a[4], bb[4];
            #pragma unroll
            for (int i = 0; i < 4; i++) a[i]  = Qs[(tm * 4 + i) * DKH + kk];
            #pragma unroll
            for (int j = 0; j < 4; j++) bb[j] = Ks[(tx * 4 + j) * KSTRIDE + kk];
            #pragma unroll
            for (int i = 0; i < 4; i++)
                #pragma unroll
                for (int j = 0; j < 4; j++) s[i][j] += a[i] * bb[j];
        }

        // Online softmax per row (row group = 16 lanes, xor offsets 1..8)
        #pragma unroll
        for (int i = 0; i < 4; i++) {
            float lm = -1e30f;
            #pragma unroll
            for (int j = 0; j < 4; j++) {
                s[i][j] *= scale;
                lm = fmaxf(lm, s[i][j]);
            }
            #pragma unroll
            for (int off = 1; off < 16; off <<= 1)
                lm = fmaxf(lm, __shfl_xor_sync(0xffffffffu, lm, off));

            float mn = fmaxf(m_i[i], lm);
            float c  = __expf(m_i[i] - mn);
            float ps = 0.f;
            #pragma unroll
            for (int j = 0; j < 4; j++) {
                float p = __expf(s[i][j] - mn);
                Ps[(tm * 4 + i) * FA_BN + tx * 4 + j] = p;
                ps += p;
            }
            #pragma unroll
            for (int off = 1; off < 16; off <<= 1)
                ps += __shfl_xor_sync(0xffffffffu, ps, off);

            l_i[i] = l_i[i] * c + ps;
            m_i[i] = mn;
            #pragma unroll
            for (int j = 0; j < 8; j++) acc[i][j] *= c;
        }
        __syncthreads();   // P visible to all; also guards Ks/Vs reuse ordering

        // O += P @ V   thread: 4 rows x 8 cols
        for (int kk = 0; kk < FA_BN; kk++) {
            float p_[4], v_[8];
            #pragma unroll
            for (int i = 0; i < 4; i++) p_[i] = Ps[(tm * 4 + i) * FA_BN + kk];
            *(float4*)&v_[0] = *(const float4*)&Vs[kk * DKH + tx * 8 + 0];
            *(float4*)&v_[4] = *(const float4*)&Vs[kk * DKH + tx * 8 + 4];
            #pragma unroll
            for (int i = 0; i < 4; i++)
                #pragma unroll
                for (int j = 0; j < 8; j++) acc[i][j] += p_[i] * v_[j];
        }
        __syncthreads();   // before next tile overwrites Ks/Vs/Ps
    }

    // Normalize and store
    #pragma unroll
    for (int i = 0; i < 4; i++) {
        float inv = 1.f / l_i[i];
        size_t row = (size_t)(q0 + tm * 4 + i);
        float4 o0, o1;
        o0.x = acc[i][0] * inv; o0.y = acc[i][1] * inv;
        o0.z = acc[i][2] * inv; o0.w = acc[i][3] * inv;
        o1.x = acc[i][4] * inv; o1.y = acc[i][5] * inv;
        o1.z = acc[i][6] * inv; o1.w = acc[i][7] * inv;
        *(float4*)&O[base + row * DMOD + tx * 8 + 0] = o0;
        *(float4*)&O[base + row * DMOD + tx * 8 + 4] = o1;
    }
}

// ---------------------------------------------------------------------------
// Launch
// ---------------------------------------------------------------------------
extern "C" void kernel_launch(void* const* d_in, const int* in_sizes, int n_in,
                              void* d_out, int out_size)
{
    const float* q  = (const float*)d_in[0];
    const float* k  = (const float*)d_in[1];
    const float* v  = (const float*)d_in[2];
    const float* Wq = (const float*)d_in[3];
    const float* bq = (const float*)d_in[4];
    const float* Wk = (const float*)d_in[5];
    const float* bk = (const float*)d_in[6];
    const float* Wv = (const float*)d_in[7];
    const float* bv = (const float*)d_in[8];
    const float* Wo = (const float*)d_in[9];
    const float* bo = (const float*)d_in[10];
    float* out = (float*)d_out;

    float *Qp, *Kp, *Vp, *AO;
    cudaGetSymbolAddress((void**)&Qp, g_Qp);
    cudaGetSymbolAddress((void**)&Kp, g_Kp);
    cudaGetSymbolAddress((void**)&Vp, g_Vp);
    cudaGetSymbolAddress((void**)&AO, g_AO);

    dim3 gp(DMOD / 128, TOK / 128);   // (16, 32)

    gemm_bias_kernel<<<gp, 256>>>(q, Wq, bq, Qp, TOK, DMOD, DMOD);
    gemm_bias_kernel<<<gp, 256>>>(k, Wk, bk, Kp, TOK, DMOD, DMOD);
    gemm_bias_kernel<<<gp, 256>>>(v, Wv, bv, Vp, TOK, DMOD, DMOD);

    const int FA_SMEM = (FA_BM * DKH + FA_BN * KSTRIDE + FA_BN * DKH +
                         FA_BM * FA_BN) * (int)sizeof(float);   // 114944 B
    cudaFuncSetAttribute(flash_attn_kernel,
                         cudaFuncAttributeMaxDynamicSharedMemorySize, FA_SMEM);
    flash_attn_kernel<<<dim3(SEQ / FA_BM, NHEAD, 2), 256, FA_SMEM>>>(Qp, Kp, Vp, AO);

    gemm_bias_kernel<<<gp, 256>>>(AO, Wo, bo, out, TOK, DMOD, DMOD);
}

// round 5
// speedup vs baseline: 1.5024x; 1.5024x over previous
#include <cuda_runtime.h>
#include <cuda_bf16.h>
#include <cstdint>

#define TOK   4096      // B*S tokens
#define DMOD  2048      // model dim
#define SEQ   2048      // sequence length
#define NHEAD 16
#define DKH   128       // head dim

// Scratch (device globals: allocation-free per harness rules)
__device__ float g_Qp[(size_t)TOK * DMOD];
__device__ float g_Kp[(size_t)TOK * DMOD];
__device__ float g_Vp[(size_t)TOK * DMOD];
__device__ float g_AO[(size_t)TOK * DMOD];
__device__ __nv_bfloat16 g_Wth[(size_t)DMOD * DMOD];   // W^T hi bf16, [N][K]
__device__ __nv_bfloat16 g_Wtl[(size_t)DMOD * DMOD];   // W^T lo bf16, [N][K]
__device__ __nv_bfloat16 g_Ah[(size_t)TOK * DMOD];     // A hi bf16, [M][K]
__device__ __nv_bfloat16 g_Al[(size_t)TOK * DMOD];     // A lo bf16, [M][K]

// ---------------------------------------------------------------------------
// helpers
// ---------------------------------------------------------------------------
__device__ __forceinline__ uint32_t smem_to_u32(const void* p) {
    uint32_t a;
    asm("{ .reg .u64 t; cvta.to.shared.u64 t, %1; cvt.u32.u64 %0, t; }"
        : "=r"(a) : "l"(p));
    return a;
}

__device__ __forceinline__ void cp_async16(uint32_t dst, const void* src) {
    asm volatile("cp.async.cg.shared.global [%0], [%1], 16;"
                 :: "r"(dst), "l"(src));
}

__device__ __forceinline__ uint32_t lds32(uint32_t addr) {
    uint32_t v;
    asm volatile("ld.shared.b32 %0, [%1];" : "=r"(v) : "r"(addr));
    return v;
}

__device__ __forceinline__ void mma_bf16(float* c,
    uint32_t a0, uint32_t a1, uint32_t a2, uint32_t a3,
    uint32_t b0, uint32_t b1)
{
    asm volatile(
        "mma.sync.aligned.m16n8k16.row.col.f32.bf16.bf16.f32 "
        "{%0,%1,%2,%3}, {%4,%5,%6,%7}, {%8,%9}, {%0,%1,%2,%3};"
        : "+f"(c[0]), "+f"(c[1]), "+f"(c[2]), "+f"(c[3])
        : "r"(a0), "r"(a1), "r"(a2), "r"(a3), "r"(b0), "r"(b1));
}

// ---------------------------------------------------------------------------
// W split-transpose: W[K][N] fp32 -> Th[N][K], Tl[N][K] bf16 (hi/lo split)
// ---------------------------------------------------------------------------
__global__ __launch_bounds__(256)
void wsplit_t_kernel(const float* __restrict__ W,
                     __nv_bfloat16* __restrict__ Th,
                     __nv_bfloat16* __restrict__ Tl)
{
    __shared__ float ts[32][33];
    const int tx = threadIdx.x & 31;
    const int ty = threadIdx.x >> 5;
    const int n0 = blockIdx.x * 32;
    const int k0 = blockIdx.y * 32;

    #pragma unroll
    for (int j = 0; j < 32; j += 8)
        ts[ty + j][tx] = W[(size_t)(k0 + ty + j) * DMOD + n0 + tx];
    __syncthreads();

    #pragma unroll
    for (int j = 0; j < 32; j += 8) {
        float x = ts[tx][ty + j];
        __nv_bfloat16 h = __float2bfloat16_rn(x);
        __nv_bfloat16 l = __float2bfloat16_rn(x - __bfloat162float(h));
        size_t o = (size_t)(n0 + ty + j) * DMOD + k0 + tx;
        Th[o] = h;
        Tl[o] = l;
    }
}

// ---------------------------------------------------------------------------
// A split: A[M][K] fp32 -> Ah, Al bf16 (contiguous, 8 elems/thread)
// ---------------------------------------------------------------------------
__global__ __launch_bounds__(256)
void asplit_kernel(const float* __restrict__ A,
                   __nv_bfloat16* __restrict__ Ah,
                   __nv_bfloat16* __restrict__ Al)
{
    size_t i = ((size_t)blockIdx.x * 256 + threadIdx.x) * 8;
    float4 f0 = *(const float4*)(A + i);
    float4 f1 = *(const float4*)(A + i + 4);
    float xs[8] = {f0.x, f0.y, f0.z, f0.w, f1.x, f1.y, f1.z, f1.w};
    uint32_t hp[4], lp[4];
    #pragma unroll
    for (int p = 0; p < 4; ++p) {
        float x = xs[2 * p], y = xs[2 * p + 1];
        __nv_bfloat16 hx = __float2bfloat16_rn(x);
        __nv_bfloat16 hy = __float2bfloat16_rn(y);
        __nv_bfloat16 ox = __float2bfloat16_rn(x - __bfloat162float(hx));
        __nv_bfloat16 oy = __float2bfloat16_rn(y - __bfloat162float(hy));
        hp[p] = (uint32_t)__bfloat16_as_ushort(hx) | ((uint32_t)__bfloat16_as_ushort(hy) << 16);
        lp[p] = (uint32_t)__bfloat16_as_ushort(ox) | ((uint32_t)__bfloat16_as_ushort(oy) << 16);
    }
    *(uint4*)(Ah + i) = make_uint4(hp[0], hp[1], hp[2], hp[3]);
    *(uint4*)(Al + i) = make_uint4(lp[0], lp[1], lp[2], lp[3]);
}

// ---------------------------------------------------------------------------
// mma.sync GEMM: C[M,N] = A @ W + bias via bf16 hi/lo (3 products, f32 accum)
// A as Ah/Al [M][K]; B as Bth/Btl [N][K] (both bf16, K contiguous).
// CTA 128x128, BK=32, 3-stage cp.async pipeline, 256 threads (8 warps 4x2).
// smem tile: rows padded to 80B (32 bf16 = 64B + 16B pad) -> bank-conflict-free.
// ---------------------------------------------------------------------------
#define GT_RSB    80                    // row stride bytes in smem tiles
#define GT_TILE   (128 * GT_RSB)        // 10240 B
#define GT_STAGE  (4 * GT_TILE)         // 40960 B (Ah, Al, Bh, Bl)
#define GT_SMEM   (3 * GT_STAGE)        // 122880 B
#define GT_KCH    64                    // number of BK=32 chunks (K=2048)

__global__ __launch_bounds__(256, 1)
void gemm_mma_kernel(const __nv_bfloat16* __restrict__ Ah,
                     const __nv_bfloat16* __restrict__ Al,
                     const __nv_bfloat16* __restrict__ Bh,
                     const __nv_bfloat16* __restrict__ Bl,
                     const float* __restrict__ bias,
                     float* __restrict__ C)
{
    extern __shared__ char smem[];
    const uint32_t smemu = smem_to_u32(smem);
    const int tid    = threadIdx.x;
    const int lane   = tid & 31;
    const int wid    = tid >> 5;
    const int warp_m = wid & 3;       // 4 warps in M (32 rows each)
    const int warp_n = wid >> 2;      // 2 warps in N (64 cols each)
    const int r4     = lane >> 2;
    const int kq     = lane & 3;
    const int n0 = blockIdx.x << 7;
    const int m0 = blockIdx.y << 7;

    float acc[2][8][4];
    #pragma unroll
    for (int i = 0; i < 2; i++)
        #pragma unroll
        for (int j = 0; j < 8; j++)
            #pragma unroll
            for (int p = 0; p < 4; p++) acc[i][j][p] = 0.f;

    // issue cp.async for chunk c into stage s
    auto issue = [&](int c, int s) {
        const int k0e = c << 5;         // k offset in elements
        #pragma unroll
        for (int it = 0; it < 8; ++it) {
            int idx  = it * 256 + tid;
            int tile = idx >> 9;                 // 0:Ah 1:Al 2:Bh 3:Bl
            int r    = (idx >> 2) & 127;
            int cc   = idx & 3;
            const __nv_bfloat16* src;
            if      (tile == 0) src = Ah + (size_t)(m0 + r) * DMOD + k0e + cc * 8;
            else if (tile == 1) src = Al + (size_t)(m0 + r) * DMOD + k0e + cc * 8;
            else if (tile == 2) src = Bh + (size_t)(n0 + r) * DMOD + k0e + cc * 8;
            else                src = Bl + (size_t)(n0 + r) * DMOD + k0e + cc * 8;
            uint32_t dst = smemu + s * GT_STAGE + tile * GT_TILE + r * GT_RSB + cc * 16;
            cp_async16(dst, src);
        }
    };

    issue(0, 0);
    asm volatile("cp.async.commit_group;" ::: "memory");
    issue(1, 1);
    asm volatile("cp.async.commit_group;" ::: "memory");

    for (int c = 0; c < GT_KCH; ++c) {
        asm volatile("cp.async.wait_group 1;" ::: "memory");
        __syncthreads();

        const uint32_t stg = smemu + (c % 3) * GT_STAGE;
        #pragma unroll
        for (int ks = 0; ks < 2; ++ks) {
            const uint32_t koff = ks * 32 + kq * 4;   // bytes within row
            uint32_t ah[2][4], al[2][4];
            #pragma unroll
            for (int i = 0; i < 2; ++i) {
                uint32_t ab = stg + (warp_m * 32 + i * 16 + r4) * GT_RSB + koff;
                ah[i][0] = lds32(ab);
                ah[i][1] = lds32(ab + 8 * GT_RSB);
                ah[i][2] = lds32(ab + 16);
                ah[i][3] = lds32(ab + 8 * GT_RSB + 16);
                uint32_t ab2 = ab + GT_TILE;
                al[i][0] = lds32(ab2);
                al[i][1] = lds32(ab2 + 8 * GT_RSB);
                al[i][2] = lds32(ab2 + 16);
                al[i][3] = lds32(ab2 + 8 * GT_RSB + 16);
            }
            #pragma unroll
            for (int j = 0; j < 8; ++j) {
                uint32_t bb = stg + 2 * GT_TILE + (warp_n * 64 + j * 8 + r4) * GT_RSB + koff;
                uint32_t bh0 = lds32(bb),           bh1 = lds32(bb + 16);
                uint32_t bl0 = lds32(bb + GT_TILE), bl1 = lds32(bb + GT_TILE + 16);
                #pragma unroll
                for (int i = 0; i < 2; ++i) {
                    mma_bf16(acc[i][j], ah[i][0], ah[i][1], ah[i][2], ah[i][3], bl0, bl1);
                    mma_bf16(acc[i][j], al[i][0], al[i][1], al[i][2], al[i][3], bh0, bh1);
                    mma_bf16(acc[i][j], ah[i][0], ah[i][1], ah[i][2], ah[i][3], bh0, bh1);
                }
            }
        }

        if (c + 2 < GT_KCH) issue(c + 2, (c + 2) % 3);
        asm volatile("cp.async.commit_group;" ::: "memory");
    }

    // Epilogue: bias + store (each lane: 2 cols x 2 rows per (i,j) tile)
    #pragma unroll
    for (int j = 0; j < 8; ++j) {
        int col = n0 + warp_n * 64 + j * 8 + kq * 2;
        float b0 = bias[col], b1 = bias[col + 1];
        #pragma unroll
        for (int i = 0; i < 2; ++i) {
            int row = m0 + warp_m * 32 + i * 16 + r4;
            float2 o0 = make_float2(acc[i][j][0] + b0, acc[i][j][1] + b1);
            float2 o1 = make_float2(acc[i][j][2] + b0, acc[i][j][3] + b1);
            *(float2*)&C[(size_t)row * DMOD + col]       = o0;
            *(float2*)&C[(size_t)(row + 8) * DMOD + col] = o1;
        }
    }
}

// ---------------------------------------------------------------------------
// Flash attention (fp32) — unchanged (R2 baseline, proven correct)
// ---------------------------------------------------------------------------
#define FA_BM 64
#define FA_BN 64
#define KSTRIDE 129

__global__ __launch_bounds__(256, 2)
void flash_attn_kernel(const float* __restrict__ Q, const float* __restrict__ K,
                       const float* __restrict__ V, float* __restrict__ O)
{
    extern __shared__ float sm[];
    float* Qs = sm;
    float* Ks = Qs + FA_BM * DKH;
    float* Vs = Ks + FA_BN * KSTRIDE;
    float* Ps = Vs + FA_BN * DKH;

    const int tid = threadIdx.x;
    const int tx  = tid & 15;
    const int tm  = tid >> 4;
    const int b   = blockIdx.z;
    const int h   = blockIdx.y;
    const int q0  = blockIdx.x * FA_BM;

    const size_t base = ((size_t)b * SEQ) * DMOD + (size_t)h * DKH;
    const float scale = 0.08838834764831845f;

    #pragma unroll
    for (int t = 0; t < 8; t++) {
        int f   = tid + t * 256;
        int row = f >> 5;
        int c4  = (f & 31) << 2;
        *(float4*)&Qs[row * DKH + c4] =
            *(const float4*)&Q[base + (size_t)(q0 + row) * DMOD + c4];
    }

    float acc[4][8];
    #pragma unroll
    for (int i = 0; i < 4; i++)
        #pragma unroll
        for (int j = 0; j < 8; j++) acc[i][j] = 0.f;
    float m_i[4], l_i[4];
    #pragma unroll
    for (int i = 0; i < 4; i++) { m_i[i] = -1e30f; l_i[i] = 0.f; }

    for (int n0 = 0; n0 < SEQ; n0 += FA_BN) {
        #pragma unroll
        for (int t = 0; t < 8; t++) {
            int f   = tid + t * 256;
            int row = f >> 5;
            int c4  = (f & 31) << 2;
            float4 kv = *(const float4*)&K[base + (size_t)(n0 + row) * DMOD + c4];
            Ks[row * KSTRIDE + c4 + 0] = kv.x;
            Ks[row * KSTRIDE + c4 + 1] = kv.y;
            Ks[row * KSTRIDE + c4 + 2] = kv.z;
            Ks[row * KSTRIDE + c4 + 3] = kv.w;
            *(float4*)&Vs[row * DKH + c4] =
                *(const float4*)&V[base + (size_t)(n0 + row) * DMOD + c4];
        }
        __syncthreads();

        float s[4][4];
        #pragma unroll
        for (int i = 0; i < 4; i++)
            #pragma unroll
            for (int j = 0; j < 4; j++) s[i][j] = 0.f;

        for (int kk = 0; kk < DKH; kk++) {
            float a[4], bb[4];
            #pragma unroll
            for (int i = 0; i < 4; i++) a[i]  = Qs[(tm * 4 + i) * DKH + kk];
            #pragma unroll
            for (int j = 0; j < 4; j++) bb[j] = Ks[(tx * 4 + j) * KSTRIDE + kk];
            #pragma unroll
            for (int i = 0; i < 4; i++)
                #pragma unroll
                for (int j = 0; j < 4; j++) s[i][j] += a[i] * bb[j];
        }

        #pragma unroll
        for (int i = 0; i < 4; i++) {
            float lm = -1e30f;
            #pragma unroll
            for (int j = 0; j < 4; j++) {
                s[i][j] *= scale;
                lm = fmaxf(lm, s[i][j]);
            }
            #pragma unroll
            for (int off = 1; off < 16; off <<= 1)
                lm = fmaxf(lm, __shfl_xor_sync(0xffffffffu, lm, off));

            float mn = fmaxf(m_i[i], lm);
            float c  = __expf(m_i[i] - mn);
            float ps = 0.f;
            #pragma unroll
            for (int j = 0; j < 4; j++) {
                float p = __expf(s[i][j] - mn);
                Ps[(tm * 4 + i) * FA_BN + tx * 4 + j] = p;
                ps += p;
            }
            #pragma unroll
            for (int off = 1; off < 16; off <<= 1)
                ps += __shfl_xor_sync(0xffffffffu, ps, off);

            l_i[i] = l_i[i] * c + ps;
            m_i[i] = mn;
            #pragma unroll
            for (int j = 0; j < 8; j++) acc[i][j] *= c;
        }
        __syncthreads();

        for (int kk = 0; kk < FA_BN; kk++) {
            float p_[4], v_[8];
            #pragma unroll
            for (int i = 0; i < 4; i++) p_[i] = Ps[(tm * 4 + i) * FA_BN + kk];
            *(float4*)&v_[0] = *(const float4*)&Vs[kk * DKH + tx * 8 + 0];
            *(float4*)&v_[4] = *(const float4*)&Vs[kk * DKH + tx * 8 + 4];
            #pragma unroll
            for (int i = 0; i < 4; i++)
                #pragma unroll
                for (int j = 0; j < 8; j++) acc[i][j] += p_[i] * v_[j];
        }
        __syncthreads();
    }

    #pragma unroll
    for (int i = 0; i < 4; i++) {
        float inv = 1.f / l_i[i];
        size_t row = (size_t)(q0 + tm * 4 + i);
        float4 o0, o1;
        o0.x = acc[i][0] * inv; o0.y = acc[i][1] * inv;
        o0.z = acc[i][2] * inv; o0.w = acc[i][3] * inv;
        o1.x = acc[i][4] * inv; o1.y = acc[i][5] * inv;
        o1.z = acc[i][6] * inv; o1.w = acc[i][7] * inv;
        *(float4*)&O[base + row * DMOD + tx * 8 + 0] = o0;
        *(float4*)&O[base + row * DMOD + tx * 8 + 4] = o1;
    }
}

// ---------------------------------------------------------------------------
// Launch
// ---------------------------------------------------------------------------
extern "C" void kernel_launch(void* const* d_in, const int* in_sizes, int n_in,
                              void* d_out, int out_size)
{
    const float* q  = (const float*)d_in[0];
    const float* k  = (const float*)d_in[1];
    const float* v  = (const float*)d_in[2];
    const float* Wq = (const float*)d_in[3];
    const float* bq = (const float*)d_in[4];
    const float* Wk = (const float*)d_in[5];
    const float* bk = (const float*)d_in[6];
    const float* Wv = (const float*)d_in[7];
    const float* bv = (const float*)d_in[8];
    const float* Wo = (const float*)d_in[9];
    const float* bo = (const float*)d_in[10];
    float* out = (float*)d_out;

    float *Qp, *Kp, *Vp, *AO;
    __nv_bfloat16 *Wth, *Wtl, *Ah, *Al;
    cudaGetSymbolAddress((void**)&Qp,  g_Qp);
    cudaGetSymbolAddress((void**)&Kp,  g_Kp);
    cudaGetSymbolAddress((void**)&Vp,  g_Vp);
    cudaGetSymbolAddress((void**)&AO,  g_AO);
    cudaGetSymbolAddress((void**)&Wth, g_Wth);
    cudaGetSymbolAddress((void**)&Wtl, g_Wtl);
    cudaGetSymbolAddress((void**)&Ah,  g_Ah);
    cudaGetSymbolAddress((void**)&Al,  g_Al);

    cudaFuncSetAttribute(gemm_mma_kernel,
                         cudaFuncAttributeMaxDynamicSharedMemorySize, GT_SMEM);

    const dim3 gt(DMOD / 32, DMOD / 32);          // W transpose grid
    const dim3 gg(DMOD / 128, TOK / 128);         // gemm grid (16, 32)
    const int  ga = (TOK * DMOD) / (256 * 8);     // asplit grid

    asplit_kernel<<<ga, 256>>>(q, Ah, Al);
    wsplit_t_kernel<<<gt, 256>>>(Wq, Wth, Wtl);
    gemm_mma_kernel<<<gg, 256, GT_SMEM>>>(Ah, Al, Wth, Wtl, bq, Qp);

    asplit_kernel<<<ga, 256>>>(k, Ah, Al);
    wsplit_t_kernel<<<gt, 256>>>(Wk, Wth, Wtl);
    gemm_mma_kernel<<<gg, 256, GT_SMEM>>>(Ah, Al, Wth, Wtl, bk, Kp);

    asplit_kernel<<<ga, 256>>>(v, Ah, Al);
    wsplit_t_kernel<<<gt, 256>>>(Wv, Wth, Wtl);
    gemm_mma_kernel<<<gg, 256, GT_SMEM>>>(Ah, Al, Wth, Wtl, bv, Vp);

    const int FA_SMEM = (FA_BM * DKH + FA_BN * KSTRIDE + FA_BN * DKH +
                         FA_BM * FA_BN) * (int)sizeof(float);
    cudaFuncSetAttribute(flash_attn_kernel,
                         cudaFuncAttributeMaxDynamicSharedMemorySize, FA_SMEM);
    flash_attn_kernel<<<dim3(SEQ / FA_BM, NHEAD, 2), 256, FA_SMEM>>>(Qp, Kp, Vp, AO);

    asplit_kernel<<<ga, 256>>>(AO, Ah, Al);
    wsplit_t_kernel<<<gt, 256>>>(Wo, Wth, Wtl);
    gemm_mma_kernel<<<gg, 256, GT_SMEM>>>(Ah, Al, Wth, Wtl, bo, out);
}

// round 7
// speedup vs baseline: 1.8074x; 1.2030x over previous
#include <cuda_runtime.h>
#include <cuda_bf16.h>
#include <cuda_fp16.h>
#include <cstdint>

#define TOK   4096      // B*S tokens
#define DMOD  2048      // model dim
#define SEQ   2048      // sequence length
#define NHEAD 16
#define DKH   128       // head dim

// Scratch (device globals: allocation-free per harness rules)
__device__ float g_Qp[(size_t)TOK * DMOD];
__device__ float g_Kp[(size_t)TOK * DMOD];
__device__ float g_Vp[(size_t)TOK * DMOD];
__device__ float g_AO[(size_t)TOK * DMOD];
__device__ __nv_bfloat16 g_Wth[(size_t)DMOD * DMOD];   // W^T hi bf16, [N][K]
__device__ __nv_bfloat16 g_Wtl[(size_t)DMOD * DMOD];   // W^T lo bf16, [N][K]
__device__ __nv_bfloat16 g_Ah[(size_t)TOK * DMOD];     // A hi bf16, [M][K]
__device__ __nv_bfloat16 g_Al[(size_t)TOK * DMOD];     // A lo bf16, [M][K]
__device__ __half g_Qh[(size_t)TOK * DMOD];            // Q*scale hi fp16
__device__ __half g_Ql[(size_t)TOK * DMOD];            // Q*scale lo fp16
__device__ __half g_Kh16[(size_t)TOK * DMOD];          // K hi fp16
__device__ __half g_Kl16[(size_t)TOK * DMOD];          // K lo fp16
__device__ __half g_Vth[(size_t)TOK * DMOD];           // V^T hi fp16 [b,h,d,s]
__device__ __half g_Vtl[(size_t)TOK * DMOD];           // V^T lo fp16 [b,h,d,s]

// ---------------------------------------------------------------------------
// helpers
// ---------------------------------------------------------------------------
__device__ __forceinline__ uint32_t smem_to_u32(const void* p) {
    uint32_t a;
    asm("{ .reg .u64 t; cvta.to.shared.u64 t, %1; cvt.u32.u64 %0, t; }"
        : "=r"(a) : "l"(p));
    return a;
}

__device__ __forceinline__ void cp_async16(uint32_t dst, const void* src) {
    asm volatile("cp.async.cg.shared.global [%0], [%1], 16;"
                 :: "r"(dst), "l"(src));
}

__device__ __forceinline__ uint32_t lds32(uint32_t addr) {
    uint32_t v;
    asm volatile("ld.shared.b32 %0, [%1];" : "=r"(v) : "r"(addr));
    return v;
}

__device__ __forceinline__ void mma_bf16(float* c,
    uint32_t a0, uint32_t a1, uint32_t a2, uint32_t a3,
    uint32_t b0, uint32_t b1)
{
    asm volatile(
        "mma.sync.aligned.m16n8k16.row.col.f32.bf16.bf16.f32 "
        "{%0,%1,%2,%3}, {%4,%5,%6,%7}, {%8,%9}, {%0,%1,%2,%3};"
        : "+f"(c[0]), "+f"(c[1]), "+f"(c[2]), "+f"(c[3])
        : "r"(a0), "r"(a1), "r"(a2), "r"(a3), "r"(b0), "r"(b1));
}

__device__ __forceinline__ void mma_f16(float* c,
    uint32_t a0, uint32_t a1, uint32_t a2, uint32_t a3,
    uint32_t b0, uint32_t b1)
{
    asm volatile(
        "mma.sync.aligned.m16n8k16.row.col.f32.f16.f16.f32 "
        "{%0,%1,%2,%3}, {%4,%5,%6,%7}, {%8,%9}, {%0,%1,%2,%3};"
        : "+f"(c[0]), "+f"(c[1]), "+f"(c[2]), "+f"(c[3])
        : "r"(a0), "r"(a1), "r"(a2), "r"(a3), "r"(b0), "r"(b1));
}

// ---------------------------------------------------------------------------
// W split-transpose: W[K][N] fp32 -> Th[N][K], Tl[N][K] bf16 (hi/lo split)
// ---------------------------------------------------------------------------
__global__ __launch_bounds__(256)
void wsplit_t_kernel(const float* __restrict__ W,
                     __nv_bfloat16* __restrict__ Th,
                     __nv_bfloat16* __restrict__ Tl)
{
    __shared__ float ts[32][33];
    const int tx = threadIdx.x & 31;
    const int ty = threadIdx.x >> 5;
    const int n0 = blockIdx.x * 32;
    const int k0 = blockIdx.y * 32;

    #pragma unroll
    for (int j = 0; j < 32; j += 8)
        ts[ty + j][tx] = W[(size_t)(k0 + ty + j) * DMOD + n0 + tx];
    __syncthreads();

    #pragma unroll
    for (int j = 0; j < 32; j += 8) {
        float x = ts[tx][ty + j];
        __nv_bfloat16 h = __float2bfloat16_rn(x);
        __nv_bfloat16 l = __float2bfloat16_rn(x - __bfloat162float(h));
        size_t o = (size_t)(n0 + ty + j) * DMOD + k0 + tx;
        Th[o] = h;
        Tl[o] = l;
    }
}

// ---------------------------------------------------------------------------
// A split: A[M][K] fp32 -> Ah, Al bf16 (contiguous, 8 elems/thread)
// ---------------------------------------------------------------------------
__global__ __launch_bounds__(256)
void asplit_kernel(const float* __restrict__ A,
                   __nv_bfloat16* __restrict__ Ah,
                   __nv_bfloat16* __restrict__ Al)
{
    size_t i = ((size_t)blockIdx.x * 256 + threadIdx.x) * 8;
    float4 f0 = *(const float4*)(A + i);
    float4 f1 = *(const float4*)(A + i + 4);
    float xs[8] = {f0.x, f0.y, f0.z, f0.w, f1.x, f1.y, f1.z, f1.w};
    uint32_t hp[4], lp[4];
    #pragma unroll
    for (int p = 0; p < 4; ++p) {
        float x = xs[2 * p], y = xs[2 * p + 1];
        __nv_bfloat16 hx = __float2bfloat16_rn(x);
        __nv_bfloat16 hy = __float2bfloat16_rn(y);
        __nv_bfloat16 ox = __float2bfloat16_rn(x - __bfloat162float(hx));
        __nv_bfloat16 oy = __float2bfloat16_rn(y - __bfloat162float(hy));
        hp[p] = (uint32_t)__bfloat16_as_ushort(hx) | ((uint32_t)__bfloat16_as_ushort(hy) << 16);
        lp[p] = (uint32_t)__bfloat16_as_ushort(ox) | ((uint32_t)__bfloat16_as_ushort(oy) << 16);
    }
    *(uint4*)(Ah + i) = make_uint4(hp[0], hp[1], hp[2], hp[3]);
    *(uint4*)(Al + i) = make_uint4(lp[0], lp[1], lp[2], lp[3]);
}

// ---------------------------------------------------------------------------
// fp32 -> fp16 hi/lo split (optionally pre-scaled), 8 elems/thread
// ---------------------------------------------------------------------------
__global__ __launch_bounds__(256)
void hsplit_kernel(const float* __restrict__ X, __half* __restrict__ Yh,
                   __half* __restrict__ Yl, float scale)
{
    size_t i = ((size_t)blockIdx.x * 256 + threadIdx.x) * 8;
    float4 f0 = *(const float4*)(X + i);
    float4 f1 = *(const float4*)(X + i + 4);
    float xs[8] = {f0.x, f0.y, f0.z, f0.w, f1.x, f1.y, f1.z, f1.w};
    uint32_t hp[4], lp[4];
    #pragma unroll
    for (int p = 0; p < 4; ++p) {
        float x = xs[2 * p] * scale, y = xs[2 * p + 1] * scale;
        __half hx = __float2half_rn(x), hy = __float2half_rn(y);
        __half ox = __float2half_rn(x - __half2float(hx));
        __half oy = __float2half_rn(y - __half2float(hy));
        hp[p] = (uint32_t)__half_as_ushort(hx) | ((uint32_t)__half_as_ushort(hy) << 16);
        lp[p] = (uint32_t)__half_as_ushort(ox) | ((uint32_t)__half_as_ushort(oy) << 16);
    }
    *(uint4*)(Yh + i) = make_uint4(hp[0], hp[1], hp[2], hp[3]);
    *(uint4*)(Yl + i) = make_uint4(lp[0], lp[1], lp[2], lp[3]);
}

// ---------------------------------------------------------------------------
// V transpose+split: Vp [b,s,h*128+d] fp32 -> Vth/Vtl [(b*16+h)*128+d][s] fp16
// ---------------------------------------------------------------------------
__global__ __launch_bounds__(256)
void vtrans_kernel(const float* __restrict__ Vp,
                   __half* __restrict__ Vh, __half* __restrict__ Vl)
{
    __shared__ float ts[32][33];
    const int tx = threadIdx.x & 31;
    const int ty = threadIdx.x >> 5;
    const int bh = blockIdx.z;
    const int b  = bh >> 4, h = bh & 15;
    const int s0 = blockIdx.x * 32;
    const int d0 = blockIdx.y * 32;

    #pragma unroll
    for (int j = 0; j < 32; j += 8)
        ts[ty + j][tx] = Vp[((size_t)b * SEQ + s0 + ty + j) * DMOD + h * DKH + d0 + tx];
    __syncthreads();

    #pragma unroll
    for (int j = 0; j < 32; j += 8) {
        float x = ts[tx][ty + j];
        __half hh = __float2half_rn(x);
        __half hl = __float2half_rn(x - __half2float(hh));
        size_t o = ((size_t)bh * DKH + d0 + ty + j) * SEQ + s0 + tx;
        Vh[o] = hh;
        Vl[o] = hl;
    }
}

// ---------------------------------------------------------------------------
// mma.sync GEMM (unchanged, passing): C = A @ W + bias via bf16 hi/lo
// ---------------------------------------------------------------------------
#define GT_RSB    80
#define GT_TILE   (128 * GT_RSB)
#define GT_STAGE  (4 * GT_TILE)
#define GT_SMEM   (3 * GT_STAGE)
#define GT_KCH    64

__global__ __launch_bounds__(256, 1)
void gemm_mma_kernel(const __nv_bfloat16* __restrict__ Ah,
                     const __nv_bfloat16* __restrict__ Al,
                     const __nv_bfloat16* __restrict__ Bh,
                     const __nv_bfloat16* __restrict__ Bl,
                     const float* __restrict__ bias,
                     float* __restrict__ C)
{
    extern __shared__ char smem[];
    const uint32_t smemu = smem_to_u32(smem);
    const int tid    = threadIdx.x;
    const int lane   = tid & 31;
    const int wid    = tid >> 5;
    const int warp_m = wid & 3;
    const int warp_n = wid >> 2;
    const int r4     = lane >> 2;
    const int kq     = lane & 3;
    const int n0 = blockIdx.x << 7;
    const int m0 = blockIdx.y << 7;

    float acc[2][8][4];
    #pragma unroll
    for (int i = 0; i < 2; i++)
        #pragma unroll
        for (int j = 0; j < 8; j++)
            #pragma unroll
            for (int p = 0; p < 4; p++) acc[i][j][p] = 0.f;

    auto issue = [&](int c, int s) {
        const int k0e = c << 5;
        #pragma unroll
        for (int it = 0; it < 8; ++it) {
            int idx  = it * 256 + tid;
            int tile = idx >> 9;
            int r    = (idx >> 2) & 127;
            int cc   = idx & 3;
            const __nv_bfloat16* src;
            if      (tile == 0) src = Ah + (size_t)(m0 + r) * DMOD + k0e + cc * 8;
            else if (tile == 1) src = Al + (size_t)(m0 + r) * DMOD + k0e + cc * 8;
            else if (tile == 2) src = Bh + (size_t)(n0 + r) * DMOD + k0e + cc * 8;
            else                src = Bl + (size_t)(n0 + r) * DMOD + k0e + cc * 8;
            uint32_t dst = smemu + s * GT_STAGE + tile * GT_TILE + r * GT_RSB + cc * 16;
            cp_async16(dst, src);
        }
    };

    issue(0, 0);
    asm volatile("cp.async.commit_group;" ::: "memory");
    issue(1, 1);
    asm volatile("cp.async.commit_group;" ::: "memory");

    for (int c = 0; c < GT_KCH; ++c) {
        asm volatile("cp.async.wait_group 1;" ::: "memory");
        __syncthreads();

        const uint32_t stg = smemu + (c % 3) * GT_STAGE;
        #pragma unroll
        for (int ks = 0; ks < 2; ++ks) {
            const uint32_t koff = ks * 32 + kq * 4;
            uint32_t ah[2][4], al[2][4];
            #pragma unroll
            for (int i = 0; i < 2; ++i) {
                uint32_t ab = stg + (warp_m * 32 + i * 16 + r4) * GT_RSB + koff;
                ah[i][0] = lds32(ab);
                ah[i][1] = lds32(ab + 8 * GT_RSB);
                ah[i][2] = lds32(ab + 16);
                ah[i][3] = lds32(ab + 8 * GT_RSB + 16);
                uint32_t ab2 = ab + GT_TILE;
                al[i][0] = lds32(ab2);
                al[i][1] = lds32(ab2 + 8 * GT_RSB);
                al[i][2] = lds32(ab2 + 16);
                al[i][3] = lds32(ab2 + 8 * GT_RSB + 16);
            }
            #pragma unroll
            for (int j = 0; j < 8; ++j) {
                uint32_t bb = stg + 2 * GT_TILE + (warp_n * 64 + j * 8 + r4) * GT_RSB + koff;
                uint32_t bh0 = lds32(bb),           bh1 = lds32(bb + 16);
                uint32_t bl0 = lds32(bb + GT_TILE), bl1 = lds32(bb + GT_TILE + 16);
                #pragma unroll
                for (int i = 0; i < 2; ++i) {
                    mma_bf16(acc[i][j], ah[i][0], ah[i][1], ah[i][2], ah[i][3], bl0, bl1);
                    mma_bf16(acc[i][j], al[i][0], al[i][1], al[i][2], al[i][3], bh0, bh1);
                    mma_bf16(acc[i][j], ah[i][0], ah[i][1], ah[i][2], ah[i][3], bh0, bh1);
                }
            }
        }

        if (c + 2 < GT_KCH) issue(c + 2, (c + 2) % 3);
        asm volatile("cp.async.commit_group;" ::: "memory");
    }

    #pragma unroll
    for (int j = 0; j < 8; ++j) {
        int col = n0 + warp_n * 64 + j * 8 + kq * 2;
        float b0 = bias[col], b1 = bias[col + 1];
        #pragma unroll
        for (int i = 0; i < 2; ++i) {
            int row = m0 + warp_m * 32 + i * 16 + r4;
            float2 o0 = make_float2(acc[i][j][0] + b0, acc[i][j][1] + b1);
            float2 o1 = make_float2(acc[i][j][2] + b0, acc[i][j][3] + b1);
            *(float2*)&C[(size_t)row * DMOD + col]       = o0;
            *(float2*)&C[(size_t)(row + 8) * DMOD + col] = o1;
        }
    }
}

// ---------------------------------------------------------------------------
// Flash attention, fp16 mma. CTA: one (b,h), 128 q rows; 8 warps, each owns
// 16 FULL rows (warp-local softmax; no cross-warp row state — fixes R5 bug).
// QK^T: 3-product hi/lo (exact); V: hi/lo split (exact); P: fp16 (1.5e-4).
// P stays in registers: S c-frag == PV A-frag layout. KV double-buffered.
// ---------------------------------------------------------------------------
#define FL_RSQ  272                   // 128 halves*2B + 16B pad
#define FL_RSV  144                   // 64 halves*2B + 16B pad
#define FL_QHS  0                     // Q hi:  128*272 = 34816
#define FL_QLS  34816                 // Q lo:  34816
#define FL_K0   69632                 // K hi/lo double buf: 4*17408
#define FL_V0   139264                // V hi/lo double buf: 4*18432
#define FL_SMEM 212992

__global__ __launch_bounds__(256, 1)
void flash_mma_kernel(const __half* __restrict__ Qh, const __half* __restrict__ Ql,
                      const __half* __restrict__ Kh, const __half* __restrict__ Kl,
                      const __half* __restrict__ Vh, const __half* __restrict__ Vl,
                      float* __restrict__ O)
{
    extern __shared__ char smem[];
    const uint32_t su = smem_to_u32(smem);
    const int tid  = threadIdx.x;
    const int lane = tid & 31;
    const int wid  = tid >> 5;            // 0..7: rows wid*16..wid*16+15
    const int r4 = lane >> 2, kq = lane & 3;
    const int q0 = blockIdx.x << 7;
    const int h  = blockIdx.y, b = blockIdx.z;
    const size_t qkbase = (size_t)b * SEQ * DMOD + (size_t)h * DKH;
    const size_t vtbase = ((size_t)b * NHEAD + h) * DKH * SEQ;

    auto load_kv = [&](int t, int st) {
        const int n0 = t << 6;
        const uint32_t kd = su + FL_K0 + st * 34816;
        const uint32_t vd = su + FL_V0 + st * 36864;
        #pragma unroll
        for (int u = 0; u < 4; u++) {
            int idx = u * 256 + tid;
            int r = idx >> 4, sg = idx & 15;
            cp_async16(kd + r * FL_RSQ + sg * 16,
                       Kh + qkbase + (size_t)(n0 + r) * DMOD + sg * 8);
            cp_async16(kd + 17408 + r * FL_RSQ + sg * 16,
                       Kl + qkbase + (size_t)(n0 + r) * DMOD + sg * 8);
        }
        #pragma unroll
        for (int u = 0; u < 4; u++) {
            int idx = u * 256 + tid;
            int r = idx >> 3, sg = idx & 7;
            cp_async16(vd + r * FL_RSV + sg * 16,
                       Vh + vtbase + (size_t)r * SEQ + n0 + sg * 8);
            cp_async16(vd + 18432 + r * FL_RSV + sg * 16,
                       Vl + vtbase + (size_t)r * SEQ + n0 + sg * 8);
        }
    };

    // Q hi+lo tiles: 128 rows x 16 segs each
    #pragma unroll
    for (int u = 0; u < 8; u++) {
        int idx = u * 256 + tid;
        int r = idx >> 4, sg = idx & 15;
        cp_async16(su + FL_QHS + r * FL_RSQ + sg * 16,
                   Qh + qkbase + (size_t)(q0 + r) * DMOD + sg * 8);
        cp_async16(su + FL_QLS + r * FL_RSQ + sg * 16,
                   Ql + qkbase + (size_t)(q0 + r) * DMOD + sg * 8);
    }
    asm volatile("cp.async.commit_group;" ::: "memory");
    load_kv(0, 0);
    asm volatile("cp.async.commit_group;" ::: "memory");
    asm volatile("cp.async.wait_group 0;" ::: "memory");
    __syncthreads();

    // Q-hi fragments, register-resident across all KV tiles
    uint32_t aqh[8][4];
    const uint32_t qb = su + FL_QHS + (wid * 16 + r4) * FL_RSQ + kq * 4;
    #pragma unroll
    for (int k = 0; k < 8; k++) {
        aqh[k][0] = lds32(qb + k * 32);
        aqh[k][1] = lds32(qb + k * 32 + 8 * FL_RSQ);
        aqh[k][2] = lds32(qb + k * 32 + 16);
        aqh[k][3] = lds32(qb + k * 32 + 8 * FL_RSQ + 16);
    }

    float oc[16][4];
    #pragma unroll
    for (int nf = 0; nf < 16; nf++)
        #pragma unroll
        for (int p = 0; p < 4; p++) oc[nf][p] = 0.f;
    float m0 = -1e30f, m1 = -1e30f, l0 = 0.f, l1 = 0.f;

    for (int t = 0; t < 32; t++) {
        const int st = t & 1;
        const uint32_t ks = su + FL_K0 + st * 34816;   // K hi (lo at +17408)
        const uint32_t vs = su + FL_V0 + st * 36864;   // V hi (lo at +18432)

        if (t + 1 < 32) {
            load_kv(t + 1, st ^ 1);
            asm volatile("cp.async.commit_group;" ::: "memory");
        }

        // S = Q @ K^T  (3 products: qh*kh + ql*kh + qh*kl)
        float sc[8][4];
        #pragma unroll
        for (int nf = 0; nf < 8; nf++)
            #pragma unroll
            for (int p = 0; p < 4; p++) sc[nf][p] = 0.f;

        const uint32_t qlb = su + FL_QLS + (wid * 16 + r4) * FL_RSQ + kq * 4;
        #pragma unroll
        for (int k = 0; k < 8; k++) {
            uint32_t ql0 = lds32(qlb + k * 32);
            uint32_t ql1 = lds32(qlb + k * 32 + 8 * FL_RSQ);
            uint32_t ql2 = lds32(qlb + k * 32 + 16);
            uint32_t ql3 = lds32(qlb + k * 32 + 8 * FL_RSQ + 16);
            #pragma unroll
            for (int nf = 0; nf < 8; nf++) {
                uint32_t bb = ks + (nf * 8 + r4) * FL_RSQ + kq * 4 + k * 32;
                uint32_t kh0 = lds32(bb),         kh1 = lds32(bb + 16);
                uint32_t kl0 = lds32(bb + 17408), kl1 = lds32(bb + 17408 + 16);
                mma_f16(sc[nf], ql0, ql1, ql2, ql3, kh0, kh1);
                mma_f16(sc[nf], aqh[k][0], aqh[k][1], aqh[k][2], aqh[k][3], kl0, kl1);
                mma_f16(sc[nf], aqh[k][0], aqh[k][1], aqh[k][2], aqh[k][3], kh0, kh1);
            }
        }

        // online softmax — rows r4 / r4+8, FULL 64-col row in this warp
        float mx0 = -1e30f, mx1 = -1e30f;
        #pragma unroll
        for (int nf = 0; nf < 8; nf++) {
            mx0 = fmaxf(mx0, fmaxf(sc[nf][0], sc[nf][1]));
            mx1 = fmaxf(mx1, fmaxf(sc[nf][2], sc[nf][3]));
        }
        mx0 = fmaxf(mx0, __shfl_xor_sync(0xffffffffu, mx0, 1));
        mx0 = fmaxf(mx0, __shfl_xor_sync(0xffffffffu, mx0, 2));
        mx1 = fmaxf(mx1, __shfl_xor_sync(0xffffffffu, mx1, 1));
        mx1 = fmaxf(mx1, __shfl_xor_sync(0xffffffffu, mx1, 2));

        const float mn0 = fmaxf(m0, mx0), mn1 = fmaxf(m1, mx1);
        const float c0 = __expf(m0 - mn0), c1 = __expf(m1 - mn1);
        float s0 = 0.f, s1 = 0.f;
        uint32_t pa[4][4];    // P as A-frags (c-frag == A-frag layout)
        #pragma unroll
        for (int nf = 0; nf < 8; nf++) {
            float p0 = __expf(sc[nf][0] - mn0);
            float p1 = __expf(sc[nf][1] - mn0);
            float p2 = __expf(sc[nf][2] - mn1);
            float p3 = __expf(sc[nf][3] - mn1);
            s0 += p0 + p1; s1 += p2 + p3;
            __half2 hA = __floats2half2_rn(p0, p1);
            __half2 hB = __floats2half2_rn(p2, p3);
            pa[nf >> 1][(nf & 1) ? 2 : 0] = *(uint32_t*)&hA;
            pa[nf >> 1][(nf & 1) ? 3 : 1] = *(uint32_t*)&hB;
        }
        s0 += __shfl_xor_sync(0xffffffffu, s0, 1);
        s0 += __shfl_xor_sync(0xffffffffu, s0, 2);
        s1 += __shfl_xor_sync(0xffffffffu, s1, 1);
        s1 += __shfl_xor_sync(0xffffffffu, s1, 2);
        l0 = l0 * c0 + s0; m0 = mn0;
        l1 = l1 * c1 + s1; m1 = mn1;
        #pragma unroll
        for (int nf = 0; nf < 16; nf++) {
            oc[nf][0] *= c0; oc[nf][1] *= c0;
            oc[nf][2] *= c1; oc[nf][3] *= c1;
        }

        // O += P @ V  (V hi + lo)
        #pragma unroll
        for (int k = 0; k < 4; k++) {
            #pragma unroll
            for (int nf = 0; nf < 16; nf++) {
                uint32_t bb = vs + (nf * 8 + r4) * FL_RSV + kq * 4 + k * 32;
                uint32_t vh0 = lds32(bb),         vh1 = lds32(bb + 16);
                uint32_t vl0 = lds32(bb + 18432), vl1 = lds32(bb + 18432 + 16);
                mma_f16(oc[nf], pa[k][0], pa[k][1], pa[k][2], pa[k][3], vh0, vh1);
                mma_f16(oc[nf], pa[k][0], pa[k][1], pa[k][2], pa[k][3], vl0, vl1);
            }
        }

        if (t + 1 < 32) {
            asm volatile("cp.async.wait_group 0;" ::: "memory");
            __syncthreads();
        }
    }

    // epilogue
    const float inv0 = 1.f / l0, inv1 = 1.f / l1;
    #pragma unroll
    for (int nf = 0; nf < 16; nf++) {
        int col  = nf * 8 + kq * 2;
        int row0 = q0 + wid * 16 + r4;
        float2 o0 = make_float2(oc[nf][0] * inv0, oc[nf][1] * inv0);
        float2 o1 = make_float2(oc[nf][2] * inv1, oc[nf][3] * inv1);
        *(float2*)&O[qkbase + (size_t)row0 * DMOD + col]       = o0;
        *(float2*)&O[qkbase + (size_t)(row0 + 8) * DMOD + col] = o1;
    }
}

// ---------------------------------------------------------------------------
// Launch
// ---------------------------------------------------------------------------
extern "C" void kernel_launch(void* const* d_in, const int* in_sizes, int n_in,
                              void* d_out, int out_size)
{
    const float* q  = (const float*)d_in[0];
    const float* k  = (const float*)d_in[1];
    const float* v  = (const float*)d_in[2];
    const float* Wq = (const float*)d_in[3];
    const float* bq = (const float*)d_in[4];
    const float* Wk = (const float*)d_in[5];
    const float* bk = (const float*)d_in[6];
    const float* Wv = (const float*)d_in[7];
    const float* bv = (const float*)d_in[8];
    const float* Wo = (const float*)d_in[9];
    const float* bo = (const float*)d_in[10];
    float* out = (float*)d_out;

    float *Qp, *Kp, *Vp, *AO;
    __nv_bfloat16 *Wth, *Wtl, *Ah, *Al;
    __half *Qh, *Ql, *Kh, *Kl, *Vth, *Vtl;
    cudaGetSymbolAddress((void**)&Qp,  g_Qp);
    cudaGetSymbolAddress((void**)&Kp,  g_Kp);
    cudaGetSymbolAddress((void**)&Vp,  g_Vp);
    cudaGetSymbolAddress((void**)&AO,  g_AO);
    cudaGetSymbolAddress((void**)&Wth, g_Wth);
    cudaGetSymbolAddress((void**)&Wtl, g_Wtl);
    cudaGetSymbolAddress((void**)&Ah,  g_Ah);
    cudaGetSymbolAddress((void**)&Al,  g_Al);
    cudaGetSymbolAddress((void**)&Qh,  g_Qh);
    cudaGetSymbolAddress((void**)&Ql,  g_Ql);
    cudaGetSymbolAddress((void**)&Kh,  g_Kh16);
    cudaGetSymbolAddress((void**)&Kl,  g_Kl16);
    cudaGetSymbolAddress((void**)&Vth, g_Vth);
    cudaGetSymbolAddress((void**)&Vtl, g_Vtl);

    cudaFuncSetAttribute(gemm_mma_kernel,
                         cudaFuncAttributeMaxDynamicSharedMemorySize, GT_SMEM);
    cudaFuncSetAttribute(flash_mma_kernel,
                         cudaFuncAttributeMaxDynamicSharedMemorySize, FL_SMEM);

    const dim3 gt(DMOD / 32, DMOD / 32);          // W transpose grid
    const dim3 gg(DMOD / 128, TOK / 128);         // gemm grid (16, 32)
    const int  ga = (TOK * DMOD) / (256 * 8);     // elementwise grids
    const float scale = 0.08838834764831845f;     // 1/sqrt(128)

    asplit_kernel<<<ga, 256>>>(q, Ah, Al);
    wsplit_t_kernel<<<gt, 256>>>(Wq, Wth, Wtl);
    gemm_mma_kernel<<<gg, 256, GT_SMEM>>>(Ah, Al, Wth, Wtl, bq, Qp);

    asplit_kernel<<<ga, 256>>>(k, Ah, Al);
    wsplit_t_kernel<<<gt, 256>>>(Wk, Wth, Wtl);
    gemm_mma_kernel<<<gg, 256, GT_SMEM>>>(Ah, Al, Wth, Wtl, bk, Kp);

    asplit_kernel<<<ga, 256>>>(v, Ah, Al);
    wsplit_t_kernel<<<gt, 256>>>(Wv, Wth, Wtl);
    gemm_mma_kernel<<<gg, 256, GT_SMEM>>>(Ah, Al, Wth, Wtl, bv, Vp);

    hsplit_kernel<<<ga, 256>>>(Qp, Qh, Ql, scale);
    hsplit_kernel<<<ga, 256>>>(Kp, Kh, Kl, 1.0f);
    vtrans_kernel<<<dim3(SEQ / 32, DKH / 32, 2 * NHEAD), 256>>>(Vp, Vth, Vtl);

    flash_mma_kernel<<<dim3(SEQ / 128, NHEAD, 2), 256, FL_SMEM>>>(
        Qh, Ql, Kh, Kl, Vth, Vtl, AO);

    asplit_kernel<<<ga, 256>>>(AO, Ah, Al);
    wsplit_t_kernel<<<gt, 256>>>(Wo, Wth, Wtl);
    gemm_mma_kernel<<<gg, 256, GT_SMEM>>>(Ah, Al, Wth, Wtl, bo, out);
}

// round 8
// speedup vs baseline: 3.0409x; 1.6825x over previous
#include <cuda_runtime.h>
#include <cuda_bf16.h>
#include <cuda_fp16.h>
#include <cstdint>

#define TOK   4096      // B*S tokens
#define DMOD  2048      // model dim
#define SEQ   2048      // sequence length
#define NHEAD 16
#define DKH   128       // head dim

// Scratch (device globals: allocation-free per harness rules)
__device__ float g_Vp[(size_t)TOK * DMOD];
__device__ __nv_bfloat16 g_Wth[(size_t)DMOD * DMOD];   // W^T hi bf16, [N][K]
__device__ __nv_bfloat16 g_Wtl[(size_t)DMOD * DMOD];   // W^T lo bf16, [N][K]
__device__ __nv_bfloat16 g_Ah[(size_t)TOK * DMOD];     // A hi bf16, [M][K]
__device__ __nv_bfloat16 g_Al[(size_t)TOK * DMOD];     // A lo bf16, [M][K]
__device__ __half g_Qh[(size_t)TOK * DMOD];            // Q*scale hi fp16
__device__ __half g_Ql[(size_t)TOK * DMOD];            // Q*scale lo fp16
__device__ __half g_Kh16[(size_t)TOK * DMOD];          // K hi fp16
__device__ __half g_Kl16[(size_t)TOK * DMOD];          // K lo fp16
__device__ __half g_Vth[(size_t)TOK * DMOD];           // V^T hi fp16 [b,h,d,s]

// ---------------------------------------------------------------------------
// helpers
// ---------------------------------------------------------------------------
__device__ __forceinline__ uint32_t smem_to_u32(const void* p) {
    uint32_t a;
    asm("{ .reg .u64 t; cvta.to.shared.u64 t, %1; cvt.u32.u64 %0, t; }"
        : "=r"(a) : "l"(p));
    return a;
}

__device__ __forceinline__ void cp_async16(uint32_t dst, const void* src) {
    asm volatile("cp.async.cg.shared.global [%0], [%1], 16;"
                 :: "r"(dst), "l"(src));
}

__device__ __forceinline__ void ldsm_x4(uint32_t& r0, uint32_t& r1,
                                        uint32_t& r2, uint32_t& r3, uint32_t addr) {
    asm volatile("ldmatrix.sync.aligned.m8n8.x4.shared.b16 {%0,%1,%2,%3}, [%4];"
                 : "=r"(r0), "=r"(r1), "=r"(r2), "=r"(r3) : "r"(addr));
}

__device__ __forceinline__ void ldsm_x2(uint32_t& r0, uint32_t& r1, uint32_t addr) {
    asm volatile("ldmatrix.sync.aligned.m8n8.x2.shared.b16 {%0,%1}, [%2];"
                 : "=r"(r0), "=r"(r1) : "r"(addr));
}

__device__ __forceinline__ void mma_bf16(float* c,
    uint32_t a0, uint32_t a1, uint32_t a2, uint32_t a3,
    uint32_t b0, uint32_t b1)
{
    asm volatile(
        "mma.sync.aligned.m16n8k16.row.col.f32.bf16.bf16.f32 "
        "{%0,%1,%2,%3}, {%4,%5,%6,%7}, {%8,%9}, {%0,%1,%2,%3};"
        : "+f"(c[0]), "+f"(c[1]), "+f"(c[2]), "+f"(c[3])
        : "r"(a0), "r"(a1), "r"(a2), "r"(a3), "r"(b0), "r"(b1));
}

__device__ __forceinline__ void mma_f16(float* c,
    uint32_t a0, uint32_t a1, uint32_t a2, uint32_t a3,
    uint32_t b0, uint32_t b1)
{
    asm volatile(
        "mma.sync.aligned.m16n8k16.row.col.f32.f16.f16.f32 "
        "{%0,%1,%2,%3}, {%4,%5,%6,%7}, {%8,%9}, {%0,%1,%2,%3};"
        : "+f"(c[0]), "+f"(c[1]), "+f"(c[2]), "+f"(c[3])
        : "r"(a0), "r"(a1), "r"(a2), "r"(a3), "r"(b0), "r"(b1));
}

// ---------------------------------------------------------------------------
// W split-transpose: W[K][N] fp32 -> Th[N][K], Tl[N][K] bf16 (hi/lo split)
// ---------------------------------------------------------------------------
__global__ __launch_bounds__(256)
void wsplit_t_kernel(const float* __restrict__ W,
                     __nv_bfloat16* __restrict__ Th,
                     __nv_bfloat16* __restrict__ Tl)
{
    __shared__ float ts[32][33];
    const int tx = threadIdx.x & 31;
    const int ty = threadIdx.x >> 5;
    const int n0 = blockIdx.x * 32;
    const int k0 = blockIdx.y * 32;

    #pragma unroll
    for (int j = 0; j < 32; j += 8)
        ts[ty + j][tx] = W[(size_t)(k0 + ty + j) * DMOD + n0 + tx];
    __syncthreads();

    #pragma unroll
    for (int j = 0; j < 32; j += 8) {
        float x = ts[tx][ty + j];
        __nv_bfloat16 h = __float2bfloat16_rn(x);
        __nv_bfloat16 l = __float2bfloat16_rn(x - __bfloat162float(h));
        size_t o = (size_t)(n0 + ty + j) * DMOD + k0 + tx;
        Th[o] = h;
        Tl[o] = l;
    }
}

// ---------------------------------------------------------------------------
// A split: A[M][K] fp32 -> Ah, Al bf16 (contiguous, 8 elems/thread)
// ---------------------------------------------------------------------------
__global__ __launch_bounds__(256)
void asplit_kernel(const float* __restrict__ A,
                   __nv_bfloat16* __restrict__ Ah,
                   __nv_bfloat16* __restrict__ Al)
{
    size_t i = ((size_t)blockIdx.x * 256 + threadIdx.x) * 8;
    float4 f0 = *(const float4*)(A + i);
    float4 f1 = *(const float4*)(A + i + 4);
    float xs[8] = {f0.x, f0.y, f0.z, f0.w, f1.x, f1.y, f1.z, f1.w};
    uint32_t hp[4], lp[4];
    #pragma unroll
    for (int p = 0; p < 4; ++p) {
        float x = xs[2 * p], y = xs[2 * p + 1];
        __nv_bfloat16 hx = __float2bfloat16_rn(x);
        __nv_bfloat16 hy = __float2bfloat16_rn(y);
        __nv_bfloat16 ox = __float2bfloat16_rn(x - __bfloat162float(hx));
        __nv_bfloat16 oy = __float2bfloat16_rn(y - __bfloat162float(hy));
        hp[p] = (uint32_t)__bfloat16_as_ushort(hx) | ((uint32_t)__bfloat16_as_ushort(hy) << 16);
        lp[p] = (uint32_t)__bfloat16_as_ushort(ox) | ((uint32_t)__bfloat16_as_ushort(oy) << 16);
    }
    *(uint4*)(Ah + i) = make_uint4(hp[0], hp[1], hp[2], hp[3]);
    *(uint4*)(Al + i) = make_uint4(lp[0], lp[1], lp[2], lp[3]);
}

// ---------------------------------------------------------------------------
// V transpose: Vp [b,s,h*128+d] fp32 -> Vth [(b*16+h)*128+d][s] fp16 (hi only)
// ---------------------------------------------------------------------------
__global__ __launch_bounds__(256)
void vtrans_kernel(const float* __restrict__ Vp, __half* __restrict__ Vh)
{
    __shared__ float ts[32][33];
    const int tx = threadIdx.x & 31;
    const int ty = threadIdx.x >> 5;
    const int bh = blockIdx.z;
    const int b  = bh >> 4, h = bh & 15;
    const int s0 = blockIdx.x * 32;
    const int d0 = blockIdx.y * 32;

    #pragma unroll
    for (int j = 0; j < 32; j += 8)
        ts[ty + j][tx] = Vp[((size_t)b * SEQ + s0 + ty + j) * DMOD + h * DKH + d0 + tx];
    __syncthreads();

    #pragma unroll
    for (int j = 0; j < 32; j += 8)
        Vh[((size_t)bh * DKH + d0 + ty + j) * SEQ + s0 + tx] =
            __float2half_rn(ts[tx][ty + j]);
}

// ---------------------------------------------------------------------------
// mma.sync GEMM: C = A @ W + bias via bf16 hi/lo, ldmatrix fragment loads.
// OUT=0: fp32 C.   OUT=1: fp16 hi/lo split of (C+bias)*oscale -> Yh, Yl.
// ---------------------------------------------------------------------------
#define GT_RSB    80
#define GT_TILE   (128 * GT_RSB)
#define GT_STAGE  (4 * GT_TILE)
#define GT_SMEM   (3 * GT_STAGE)
#define GT_KCH    64

template<int OUT>
__global__ __launch_bounds__(256, 1)
void gemm_mma_kernel(const __nv_bfloat16* __restrict__ Ah,
                     const __nv_bfloat16* __restrict__ Al,
                     const __nv_bfloat16* __restrict__ Bh,
                     const __nv_bfloat16* __restrict__ Bl,
                     const float* __restrict__ bias,
                     float* __restrict__ C,
                     __half* __restrict__ Yh, __half* __restrict__ Yl,
                     float oscale)
{
    extern __shared__ char smem[];
    const uint32_t smemu = smem_to_u32(smem);
    const int tid    = threadIdx.x;
    const int lane   = tid & 31;
    const int wid    = tid >> 5;
    const int warp_m = wid & 3;
    const int warp_n = wid >> 2;
    const int r4     = lane >> 2;
    const int kq     = lane & 3;
    const int li  = lane & 7;
    const int l8  = (lane >> 3) & 1;
    const int l16 = (lane >> 4) & 1;
    const int n0 = blockIdx.x << 7;
    const int m0 = blockIdx.y << 7;

    float acc[2][8][4];
    #pragma unroll
    for (int i = 0; i < 2; i++)
        #pragma unroll
        for (int j = 0; j < 8; j++)
            #pragma unroll
            for (int p = 0; p < 4; p++) acc[i][j][p] = 0.f;

    auto issue = [&](int c, int s) {
        const int k0e = c << 5;
        #pragma unroll
        for (int it = 0; it < 8; ++it) {
            int idx  = it * 256 + tid;
            int tile = idx >> 9;
            int r    = (idx >> 2) & 127;
            int cc   = idx & 3;
            const __nv_bfloat16* src;
            if      (tile == 0) src = Ah + (size_t)(m0 + r) * DMOD + k0e + cc * 8;
            else if (tile == 1) src = Al + (size_t)(m0 + r) * DMOD + k0e + cc * 8;
            else if (tile == 2) src = Bh + (size_t)(n0 + r) * DMOD + k0e + cc * 8;
            else                src = Bl + (size_t)(n0 + r) * DMOD + k0e + cc * 8;
            uint32_t dst = smemu + s * GT_STAGE + tile * GT_TILE + r * GT_RSB + cc * 16;
            cp_async16(dst, src);
        }
    };

    issue(0, 0);
    asm volatile("cp.async.commit_group;" ::: "memory");
    issue(1, 1);
    asm volatile("cp.async.commit_group;" ::: "memory");

    for (int c = 0; c < GT_KCH; ++c) {
        asm volatile("cp.async.wait_group 1;" ::: "memory");
        __syncthreads();

        const uint32_t stg = smemu + (c % 3) * GT_STAGE;
        #pragma unroll
        for (int ks = 0; ks < 2; ++ks) {
            const uint32_t kb = ks * 32 + l16 * 16;
            uint32_t ah[2][4], al[2][4];
            #pragma unroll
            for (int i = 0; i < 2; ++i) {
                // A-operand ldmatrix.x4: m0..3 = (rows0-7,s0)(rows8-15,s0)(rows0-7,s1)(rows8-15,s1)
                uint32_t aadr = stg + (warp_m * 32 + i * 16 + l8 * 8 + li) * GT_RSB + kb;
                ldsm_x4(ah[i][0], ah[i][1], ah[i][2], ah[i][3], aadr);
                ldsm_x4(al[i][0], al[i][1], al[i][2], al[i][3], aadr + GT_TILE);
            }
            #pragma unroll
            for (int j = 0; j < 8; ++j) {
                // B-operand x4: lanes 0-15 -> Bh (b0,b1), lanes 16-31 -> Bl (bl0,bl1)
                uint32_t badr = stg + (2 + l16) * GT_TILE +
                                (warp_n * 64 + j * 8 + li) * GT_RSB +
                                ks * 32 + ((lane >> 3) & 1) * 16;
                uint32_t bh0, bh1, bl0, bl1;
                ldsm_x4(bh0, bh1, bl0, bl1, badr);
                #pragma unroll
                for (int i = 0; i < 2; ++i) {
                    mma_bf16(acc[i][j], ah[i][0], ah[i][1], ah[i][2], ah[i][3], bl0, bl1);
                    mma_bf16(acc[i][j], al[i][0], al[i][1], al[i][2], al[i][3], bh0, bh1);
                    mma_bf16(acc[i][j], ah[i][0], ah[i][1], ah[i][2], ah[i][3], bh0, bh1);
                }
            }
        }

        if (c + 2 < GT_KCH) issue(c + 2, (c + 2) % 3);
        asm volatile("cp.async.commit_group;" ::: "memory");
    }

    #pragma unroll
    for (int j = 0; j < 8; ++j) {
        int col = n0 + warp_n * 64 + j * 8 + kq * 2;
        float b0 = bias[col], b1 = bias[col + 1];
        #pragma unroll
        for (int i = 0; i < 2; ++i) {
            int row = m0 + warp_m * 32 + i * 16 + r4;
            float y0 = acc[i][j][0] + b0, y1 = acc[i][j][1] + b1;
            float y2 = acc[i][j][2] + b0, y3 = acc[i][j][3] + b1;
            if (OUT == 0) {
                *(float2*)&C[(size_t)row * DMOD + col]       = make_float2(y0, y1);
                *(float2*)&C[(size_t)(row + 8) * DMOD + col] = make_float2(y2, y3);
            } else {
                y0 *= oscale; y1 *= oscale; y2 *= oscale; y3 *= oscale;
                __half h0 = __float2half_rn(y0), h1 = __float2half_rn(y1);
                __half h2 = __float2half_rn(y2), h3 = __float2half_rn(y3);
                __half e0 = __float2half_rn(y0 - __half2float(h0));
                __half e1 = __float2half_rn(y1 - __half2float(h1));
                __half e2 = __float2half_rn(y2 - __half2float(h2));
                __half e3 = __float2half_rn(y3 - __half2float(h3));
                __half2 H0 = __halves2half2(h0, h1), H1 = __halves2half2(h2, h3);
                __half2 L0 = __halves2half2(e0, e1), L1 = __halves2half2(e2, e3);
                *(__half2*)&Yh[(size_t)row * DMOD + col]       = H0;
                *(__half2*)&Yh[(size_t)(row + 8) * DMOD + col] = H1;
                *(__half2*)&Yl[(size_t)row * DMOD + col]       = L0;
                *(__half2*)&Yl[(size_t)(row + 8) * DMOD + col] = L1;
            }
        }
    }
}

// ---------------------------------------------------------------------------
// Flash attention, fp16 mma + ldmatrix. CTA: one (b,h), 128 q rows; 8 warps,
// each owns 16 full rows. QK^T: 3-product hi/lo; P fp16; V fp16 (hi only).
// Output written directly as bf16 hi/lo split (feeds final GEMM).
// ---------------------------------------------------------------------------
#define FL_RSQ  272                   // 128 halves*2B + 16B pad
#define FL_RSV  144                   // 64 halves*2B + 16B pad
#define FL_QHS  0                     // Q hi:  34816
#define FL_QLS  34816                 // Q lo:  34816
#define FL_K0   69632                 // K hi+lo double buf: 2*34816
#define FL_V0   139264                // V hi double buf: 2*18432
#define FL_SMEM 176128

__global__ __launch_bounds__(256, 1)
void flash_mma_kernel(const __half* __restrict__ Qh, const __half* __restrict__ Ql,
                      const __half* __restrict__ Kh, const __half* __restrict__ Kl,
                      const __half* __restrict__ Vh,
                      __nv_bfloat16* __restrict__ Oh, __nv_bfloat16* __restrict__ Ol)
{
    extern __shared__ char smem[];
    const uint32_t su = smem_to_u32(smem);
    const int tid  = threadIdx.x;
    const int lane = tid & 31;
    const int wid  = tid >> 5;
    const int r4 = lane >> 2, kq = lane & 3;
    const int li  = lane & 7;
    const int l8  = (lane >> 3) & 1;
    const int l16 = (lane >> 4) & 1;
    const int q0 = blockIdx.x << 7;
    const int h  = blockIdx.y, b = blockIdx.z;
    const size_t qkbase = (size_t)b * SEQ * DMOD + (size_t)h * DKH;
    const size_t vtbase = ((size_t)b * NHEAD + h) * DKH * SEQ;

    auto load_kv = [&](int t, int st) {
        const int n0 = t << 6;
        const uint32_t kd = su + FL_K0 + st * 34816;
        const uint32_t vd = su + FL_V0 + st * 18432;
        #pragma unroll
        for (int u = 0; u < 4; u++) {
            int idx = u * 256 + tid;
            int r = idx >> 4, sg = idx & 15;
            cp_async16(kd + r * FL_RSQ + sg * 16,
                       Kh + qkbase + (size_t)(n0 + r) * DMOD + sg * 8);
            cp_async16(kd + 17408 + r * FL_RSQ + sg * 16,
                       Kl + qkbase + (size_t)(n0 + r) * DMOD + sg * 8);
        }
        #pragma unroll
        for (int u = 0; u < 4; u++) {
            int idx = u * 256 + tid;
            int r = idx >> 3, sg = idx & 7;
            cp_async16(vd + r * FL_RSV + sg * 16,
                       Vh + vtbase + (size_t)r * SEQ + n0 + sg * 8);
        }
    };

    #pragma unroll
    for (int u = 0; u < 8; u++) {
        int idx = u * 256 + tid;
        int r = idx >> 4, sg = idx & 15;
        cp_async16(su + FL_QHS + r * FL_RSQ + sg * 16,
                   Qh + qkbase + (size_t)(q0 + r) * DMOD + sg * 8);
        cp_async16(su + FL_QLS + r * FL_RSQ + sg * 16,
                   Ql + qkbase + (size_t)(q0 + r) * DMOD + sg * 8);
    }
    asm volatile("cp.async.commit_group;" ::: "memory");
    load_kv(0, 0);
    asm volatile("cp.async.commit_group;" ::: "memory");
    asm volatile("cp.async.wait_group 0;" ::: "memory");
    __syncthreads();

    // A-operand lane address for Q tiles (ldmatrix.x4)
    const uint32_t qrowoff = (wid * 16 + l8 * 8 + li) * FL_RSQ + l16 * 16;

    // Q-hi fragments, register-resident across all KV tiles
    uint32_t aqh[8][4];
    #pragma unroll
    for (int k = 0; k < 8; k++)
        ldsm_x4(aqh[k][0], aqh[k][1], aqh[k][2], aqh[k][3],
                su + FL_QHS + qrowoff + k * 32);

    float oc[16][4];
    #pragma unroll
    for (int nf = 0; nf < 16; nf++)
        #pragma unroll
        for (int p = 0; p < 4; p++) oc[nf][p] = 0.f;
    float m0 = -1e30f, m1 = -1e30f, l0 = 0.f, l1 = 0.f;

    for (int t = 0; t < 32; t++) {
        const int st = t & 1;
        const uint32_t ks = su + FL_K0 + st * 34816;   // K hi (lo at +17408)
        const uint32_t vs = su + FL_V0 + st * 18432;   // V hi

        if (t + 1 < 32) {
            load_kv(t + 1, st ^ 1);
            asm volatile("cp.async.commit_group;" ::: "memory");
        }

        // S = Q @ K^T  (qh*kh + ql*kh + qh*kl)
        float sc[8][4];
        #pragma unroll
        for (int nf = 0; nf < 8; nf++)
            #pragma unroll
            for (int p = 0; p < 4; p++) sc[nf][p] = 0.f;

        #pragma unroll
        for (int k = 0; k < 8; k++) {
            uint32_t ql0, ql1, ql2, ql3;
            ldsm_x4(ql0, ql1, ql2, ql3, su + FL_QLS + qrowoff + k * 32);
            #pragma unroll
            for (int nf = 0; nf < 8; nf++) {
                // x4: lanes0-15 -> Khi (kh0,kh1); lanes16-31 -> Klo (kl0,kl1)
                uint32_t kadr = ks + l16 * 17408 + (nf * 8 + li) * FL_RSQ +
                                ((lane >> 3) & 1) * 16 + k * 32;
                uint32_t kh0, kh1, kl0, kl1;
                ldsm_x4(kh0, kh1, kl0, kl1, kadr);
                mma_f16(sc[nf], ql0, ql1, ql2, ql3, kh0, kh1);
                mma_f16(sc[nf], aqh[k][0], aqh[k][1], aqh[k][2], aqh[k][3], kl0, kl1);
                mma_f16(sc[nf], aqh[k][0], aqh[k][1], aqh[k][2], aqh[k][3], kh0, kh1);
            }
        }

        // online softmax — rows r4 / r4+8, full 64-col row in this warp
        float mx0 = -1e30f, mx1 = -1e30f;
        #pragma unroll
        for (int nf = 0; nf < 8; nf++) {
            mx0 = fmaxf(mx0, fmaxf(sc[nf][0], sc[nf][1]));
            mx1 = fmaxf(mx1, fmaxf(sc[nf][2], sc[nf][3]));
        }
        mx0 = fmaxf(mx0, __shfl_xor_sync(0xffffffffu, mx0, 1));
        mx0 = fmaxf(mx0, __shfl_xor_sync(0xffffffffu, mx0, 2));
        mx1 = fmaxf(mx1, __shfl_xor_sync(0xffffffffu, mx1, 1));
        mx1 = fmaxf(mx1, __shfl_xor_sync(0xffffffffu, mx1, 2));

        const float mn0 = fmaxf(m0, mx0), mn1 = fmaxf(m1, mx1);
        const float c0 = __expf(m0 - mn0), c1 = __expf(m1 - mn1);
        float s0 = 0.f, s1 = 0.f;
        uint32_t pa[4][4];    // P as A-frags (c-frag == A-frag layout)
        #pragma unroll
        for (int nf = 0; nf < 8; nf++) {
            float p0 = __expf(sc[nf][0] - mn0);
            float p1 = __expf(sc[nf][1] - mn0);
            float p2 = __expf(sc[nf][2] - mn1);
            float p3 = __expf(sc[nf][3] - mn1);
            s0 += p0 + p1; s1 += p2 + p3;
            __half2 hA = __floats2half2_rn(p0, p1);
            __half2 hB = __floats2half2_rn(p2, p3);
            pa[nf >> 1][(nf & 1) ? 2 : 0] = *(uint32_t*)&hA;
            pa[nf >> 1][(nf & 1) ? 3 : 1] = *(uint32_t*)&hB;
        }
        s0 += __shfl_xor_sync(0xffffffffu, s0, 1);
        s0 += __shfl_xor_sync(0xffffffffu, s0, 2);
        s1 += __shfl_xor_sync(0xffffffffu, s1, 1);
        s1 += __shfl_xor_sync(0xffffffffu, s1, 2);
        l0 = l0 * c0 + s0; m0 = mn0;
        l1 = l1 * c1 + s1; m1 = mn1;
        #pragma unroll
        for (int nf = 0; nf < 16; nf++) {
            oc[nf][0] *= c0; oc[nf][1] *= c0;
            oc[nf][2] *= c1; oc[nf][3] *= c1;
        }

        // O += P @ V  (V hi only)
        #pragma unroll
        for (int k = 0; k < 4; k++) {
            #pragma unroll
            for (int nf = 0; nf < 16; nf++) {
                uint32_t vadr = vs + (nf * 8 + li) * FL_RSV +
                                ((lane >> 3) & 1) * 16 + k * 32;
                uint32_t vh0, vh1;
                ldsm_x2(vh0, vh1, vadr);
                mma_f16(oc[nf], pa[k][0], pa[k][1], pa[k][2], pa[k][3], vh0, vh1);
            }
        }

        if (t + 1 < 32) {
            asm volatile("cp.async.wait_group 0;" ::: "memory");
            __syncthreads();
        }
    }

    // epilogue: normalize + bf16 hi/lo split, direct to Ah/Al of final GEMM
    const float inv0 = 1.f / l0, inv1 = 1.f / l1;
    #pragma unroll
    for (int nf = 0; nf < 16; nf++) {
        int col  = nf * 8 + kq * 2;
        int row0 = q0 + wid * 16 + r4;
        float y[4] = {oc[nf][0] * inv0, oc[nf][1] * inv0,
                      oc[nf][2] * inv1, oc[nf][3] * inv1};
        uint32_t hp[2], lp[2];
        #pragma unroll
        for (int p = 0; p < 2; p++) {
            __nv_bfloat16 h0 = __float2bfloat16_rn(y[2 * p]);
            __nv_bfloat16 h1 = __float2bfloat16_rn(y[2 * p + 1]);
            __nv_bfloat16 e0 = __float2bfloat16_rn(y[2 * p]     - __bfloat162float(h0));
            __nv_bfloat16 e1 = __float2bfloat16_rn(y[2 * p + 1] - __bfloat162float(h1));
            hp[p] = (uint32_t)__bfloat16_as_ushort(h0) | ((uint32_t)__bfloat16_as_ushort(h1) << 16);
            lp[p] = (uint32_t)__bfloat16_as_ushort(e0) | ((uint32_t)__bfloat16_as_ushort(e1) << 16);
        }
        *(uint32_t*)&Oh[qkbase + (size_t)row0 * DMOD + col]       = hp[0];
        *(uint32_t*)&Oh[qkbase + (size_t)(row0 + 8) * DMOD + col] = hp[1];
        *(uint32_t*)&Ol[qkbase + (size_t)row0 * DMOD + col]       = lp[0];
        *(uint32_t*)&Ol[qkbase + (size_t)(row0 + 8) * DMOD + col] = lp[1];
    }
}

// ---------------------------------------------------------------------------
// Launch
// ---------------------------------------------------------------------------
extern "C" void kernel_launch(void* const* d_in, const int* in_sizes, int n_in,
                              void* d_out, int out_size)
{
    const float* q  = (const float*)d_in[0];
    const float* k  = (const float*)d_in[1];
    const float* v  = (const float*)d_in[2];
    const float* Wq = (const float*)d_in[3];
    const float* bq = (const float*)d_in[4];
    const float* Wk = (const float*)d_in[5];
    const float* bk = (const float*)d_in[6];
    const float* Wv = (const float*)d_in[7];
    const float* bv = (const float*)d_in[8];
    const float* Wo = (const float*)d_in[9];
    const float* bo = (const float*)d_in[10];
    float* out = (float*)d_out;

    float *Vp;
    __nv_bfloat16 *Wth, *Wtl, *Ah, *Al;
    __half *Qh, *Ql, *Kh, *Kl, *Vth;
    cudaGetSymbolAddress((void**)&Vp,  g_Vp);
    cudaGetSymbolAddress((void**)&Wth, g_Wth);
    cudaGetSymbolAddress((void**)&Wtl, g_Wtl);
    cudaGetSymbolAddress((void**)&Ah,  g_Ah);
    cudaGetSymbolAddress((void**)&Al,  g_Al);
    cudaGetSymbolAddress((void**)&Qh,  g_Qh);
    cudaGetSymbolAddress((void**)&Ql,  g_Ql);
    cudaGetSymbolAddress((void**)&Kh,  g_Kh16);
    cudaGetSymbolAddress((void**)&Kl,  g_Kl16);
    cudaGetSymbolAddress((void**)&Vth, g_Vth);

    cudaFuncSetAttribute(gemm_mma_kernel<0>,
                         cudaFuncAttributeMaxDynamicSharedMemorySize, GT_SMEM);
    cudaFuncSetAttribute(gemm_mma_kernel<1>,
                         cudaFuncAttributeMaxDynamicSharedMemorySize, GT_SMEM);
    cudaFuncSetAttribute(flash_mma_kernel,
                         cudaFuncAttributeMaxDynamicSharedMemorySize, FL_SMEM);

    const dim3 gt(DMOD / 32, DMOD / 32);          // W transpose grid
    const dim3 gg(DMOD / 128, TOK / 128);         // gemm grid (16, 32)
    const int  ga = (TOK * DMOD) / (256 * 8);     // elementwise grids
    const float scale = 0.08838834764831845f;     // 1/sqrt(128)

    // Q projection -> fp16 hi/lo (pre-scaled)
    asplit_kernel<<<ga, 256>>>(q, Ah, Al);
    wsplit_t_kernel<<<gt, 256>>>(Wq, Wth, Wtl);
    gemm_mma_kernel<1><<<gg, 256, GT_SMEM>>>(Ah, Al, Wth, Wtl, bq,
                                             nullptr, Qh, Ql, scale);

    // K projection -> fp16 hi/lo
    asplit_kernel<<<ga, 256>>>(k, Ah, Al);
    wsplit_t_kernel<<<gt, 256>>>(Wk, Wth, Wtl);
    gemm_mma_kernel<1><<<gg, 256, GT_SMEM>>>(Ah, Al, Wth, Wtl, bk,
                                             nullptr, Kh, Kl, 1.0f);

    // V projection -> fp32 (for transpose)
    asplit_kernel<<<ga, 256>>>(v, Ah, Al);
    wsplit_t_kernel<<<gt, 256>>>(Wv, Wth, Wtl);
    gemm_mma_kernel<0><<<gg, 256, GT_SMEM>>>(Ah, Al, Wth, Wtl, bv,
                                             Vp, nullptr, nullptr, 1.0f);
    vtrans_kernel<<<dim3(SEQ / 32, DKH / 32, 2 * NHEAD), 256>>>(Vp, Vth);

    // attention -> bf16 hi/lo directly into final-GEMM A operands
    flash_mma_kernel<<<dim3(SEQ / 128, NHEAD, 2), 256, FL_SMEM>>>(
        Qh, Ql, Kh, Kl, Vth, Ah, Al);

    // output projection
    wsplit_t_kernel<<<gt, 256>>>(Wo, Wth, Wtl);
    gemm_mma_kernel<0><<<gg, 256, GT_SMEM>>>(Ah, Al, Wth, Wtl, bo,
                                             out, nullptr, nullptr, 1.0f);
}

// round 9
// speedup vs baseline: 3.1679x; 1.0418x over previous
#include <cuda_runtime.h>
#include <cuda_bf16.h>
#include <cuda_fp16.h>
#include <cstdint>

#define TOK   4096      // B*S tokens
#define DMOD  2048      // model dim
#define SEQ   2048      // sequence length
#define NHEAD 16
#define DKH   128       // head dim

// Scratch (device globals: allocation-free per harness rules)
__device__ float g_Vp[(size_t)TOK * DMOD];
__device__ __nv_bfloat16 g_Wth[(size_t)DMOD * DMOD];   // W^T hi bf16, [N][K]
__device__ __nv_bfloat16 g_Wtl[(size_t)DMOD * DMOD];   // W^T lo bf16, [N][K]
__device__ __nv_bfloat16 g_Ah[(size_t)TOK * DMOD];     // A hi bf16, [M][K]
__device__ __nv_bfloat16 g_Al[(size_t)TOK * DMOD];     // A lo bf16, [M][K]
__device__ __half g_Qh[(size_t)TOK * DMOD];            // Q*scale hi fp16
__device__ __half g_Kh16[(size_t)TOK * DMOD];          // K hi fp16
__device__ __half g_Kl16[(size_t)TOK * DMOD];          // K lo fp16
__device__ __half g_Vth[(size_t)TOK * DMOD];           // V^T hi fp16 [b,h,d,s]

// ---------------------------------------------------------------------------
// helpers
// ---------------------------------------------------------------------------
__device__ __forceinline__ uint32_t smem_to_u32(const void* p) {
    uint32_t a;
    asm("{ .reg .u64 t; cvta.to.shared.u64 t, %1; cvt.u32.u64 %0, t; }"
        : "=r"(a) : "l"(p));
    return a;
}

__device__ __forceinline__ void cp_async16(uint32_t dst, const void* src) {
    asm volatile("cp.async.cg.shared.global [%0], [%1], 16;"
                 :: "r"(dst), "l"(src));
}

__device__ __forceinline__ void ldsm_x4(uint32_t& r0, uint32_t& r1,
                                        uint32_t& r2, uint32_t& r3, uint32_t addr) {
    asm volatile("ldmatrix.sync.aligned.m8n8.x4.shared.b16 {%0,%1,%2,%3}, [%4];"
                 : "=r"(r0), "=r"(r1), "=r"(r2), "=r"(r3) : "r"(addr));
}

__device__ __forceinline__ void mma_bf16(float* c,
    uint32_t a0, uint32_t a1, uint32_t a2, uint32_t a3,
    uint32_t b0, uint32_t b1)
{
    asm volatile(
        "mma.sync.aligned.m16n8k16.row.col.f32.bf16.bf16.f32 "
        "{%0,%1,%2,%3}, {%4,%5,%6,%7}, {%8,%9}, {%0,%1,%2,%3};"
        : "+f"(c[0]), "+f"(c[1]), "+f"(c[2]), "+f"(c[3])
        : "r"(a0), "r"(a1), "r"(a2), "r"(a3), "r"(b0), "r"(b1));
}

__device__ __forceinline__ void mma_f16(float* c,
    uint32_t a0, uint32_t a1, uint32_t a2, uint32_t a3,
    uint32_t b0, uint32_t b1)
{
    asm volatile(
        "mma.sync.aligned.m16n8k16.row.col.f32.f16.f16.f32 "
        "{%0,%1,%2,%3}, {%4,%5,%6,%7}, {%8,%9}, {%0,%1,%2,%3};"
        : "+f"(c[0]), "+f"(c[1]), "+f"(c[2]), "+f"(c[3])
        : "r"(a0), "r"(a1), "r"(a2), "r"(a3), "r"(b0), "r"(b1));
}

// ---------------------------------------------------------------------------
// W split-transpose: W[K][N] fp32 -> Th[N][K], Tl[N][K] bf16 (hi/lo split)
// ---------------------------------------------------------------------------
__global__ __launch_bounds__(256)
void wsplit_t_kernel(const float* __restrict__ W,
                     __nv_bfloat16* __restrict__ Th,
                     __nv_bfloat16* __restrict__ Tl)
{
    __shared__ float ts[32][33];
    const int tx = threadIdx.x & 31;
    const int ty = threadIdx.x >> 5;
    const int n0 = blockIdx.x * 32;
    const int k0 = blockIdx.y * 32;

    #pragma unroll
    for (int j = 0; j < 32; j += 8)
        ts[ty + j][tx] = W[(size_t)(k0 + ty + j) * DMOD + n0 + tx];
    __syncthreads();

    #pragma unroll
    for (int j = 0; j < 32; j += 8) {
        float x = ts[tx][ty + j];
        __nv_bfloat16 h = __float2bfloat16_rn(x);
        __nv_bfloat16 l = __float2bfloat16_rn(x - __bfloat162float(h));
        size_t o = (size_t)(n0 + ty + j) * DMOD + k0 + tx;
        Th[o] = h;
        Tl[o] = l;
    }
}

// ---------------------------------------------------------------------------
// A split: A[M][K] fp32 -> Ah, Al bf16 (contiguous, 8 elems/thread)
// ---------------------------------------------------------------------------
__global__ __launch_bounds__(256)
void asplit_kernel(const float* __restrict__ A,
                   __nv_bfloat16* __restrict__ Ah,
                   __nv_bfloat16* __restrict__ Al)
{
    size_t i = ((size_t)blockIdx.x * 256 + threadIdx.x) * 8;
    float4 f0 = *(const float4*)(A + i);
    float4 f1 = *(const float4*)(A + i + 4);
    float xs[8] = {f0.x, f0.y, f0.z, f0.w, f1.x, f1.y, f1.z, f1.w};
    uint32_t hp[4], lp[4];
    #pragma unroll
    for (int p = 0; p < 4; ++p) {
        float x = xs[2 * p], y = xs[2 * p + 1];
        __nv_bfloat16 hx = __float2bfloat16_rn(x);
        __nv_bfloat16 hy = __float2bfloat16_rn(y);
        __nv_bfloat16 ox = __float2bfloat16_rn(x - __bfloat162float(hx));
        __nv_bfloat16 oy = __float2bfloat16_rn(y - __bfloat162float(hy));
        hp[p] = (uint32_t)__bfloat16_as_ushort(hx) | ((uint32_t)__bfloat16_as_ushort(hy) << 16);
        lp[p] = (uint32_t)__bfloat16_as_ushort(ox) | ((uint32_t)__bfloat16_as_ushort(oy) << 16);
    }
    *(uint4*)(Ah + i) = make_uint4(hp[0], hp[1], hp[2], hp[3]);
    *(uint4*)(Al + i) = make_uint4(lp[0], lp[1], lp[2], lp[3]);
}

// ---------------------------------------------------------------------------
// V transpose: Vp [b,s,h*128+d] fp32 -> Vth [(b*16+h)*128+d][s] fp16 (hi only)
// ---------------------------------------------------------------------------
__global__ __launch_bounds__(256)
void vtrans_kernel(const float* __restrict__ Vp, __half* __restrict__ Vh)
{
    __shared__ float ts[32][33];
    const int tx = threadIdx.x & 31;
    const int ty = threadIdx.x >> 5;
    const int bh = blockIdx.z;
    const int b  = bh >> 4, h = bh & 15;
    const int s0 = blockIdx.x * 32;
    const int d0 = blockIdx.y * 32;

    #pragma unroll
    for (int j = 0; j < 32; j += 8)
        ts[ty + j][tx] = Vp[((size_t)b * SEQ + s0 + ty + j) * DMOD + h * DKH + d0 + tx];
    __syncthreads();

    #pragma unroll
    for (int j = 0; j < 32; j += 8)
        Vh[((size_t)bh * DKH + d0 + ty + j) * SEQ + s0 + tx] =
            __float2half_rn(ts[tx][ty + j]);
}

// ---------------------------------------------------------------------------
// mma.sync GEMM: C = A @ W + bias via bf16 hi/lo, ldmatrix fragment loads.
// OUT=0: fp32 C.   OUT=1: fp16 hi (and lo if Yl) of (C+bias)*oscale.
// ---------------------------------------------------------------------------
#define GT_RSB    80
#define GT_TILE   (128 * GT_RSB)
#define GT_STAGE  (4 * GT_TILE)
#define GT_SMEM   (3 * GT_STAGE)
#define GT_KCH    64

template<int OUT>
__global__ __launch_bounds__(256, 1)
void gemm_mma_kernel(const __nv_bfloat16* __restrict__ Ah,
                     const __nv_bfloat16* __restrict__ Al,
                     const __nv_bfloat16* __restrict__ Bh,
                     const __nv_bfloat16* __restrict__ Bl,
                     const float* __restrict__ bias,
                     float* __restrict__ C,
                     __half* __restrict__ Yh, __half* __restrict__ Yl,
                     float oscale)
{
    extern __shared__ char smem[];
    const uint32_t smemu = smem_to_u32(smem);
    const int tid    = threadIdx.x;
    const int lane   = tid & 31;
    const int wid    = tid >> 5;
    const int warp_m = wid & 3;
    const int warp_n = wid >> 2;
    const int r4     = lane >> 2;
    const int kq     = lane & 3;
    const int li  = lane & 7;
    const int l8  = (lane >> 3) & 1;
    const int l16 = (lane >> 4) & 1;
    const int n0 = blockIdx.x << 7;
    const int m0 = blockIdx.y << 7;

    float acc[2][8][4];
    #pragma unroll
    for (int i = 0; i < 2; i++)
        #pragma unroll
        for (int j = 0; j < 8; j++)
            #pragma unroll
            for (int p = 0; p < 4; p++) acc[i][j][p] = 0.f;

    auto issue = [&](int c, int s) {
        const int k0e = c << 5;
        #pragma unroll
        for (int it = 0; it < 8; ++it) {
            int idx  = it * 256 + tid;
            int tile = idx >> 9;
            int r    = (idx >> 2) & 127;
            int cc   = idx & 3;
            const __nv_bfloat16* src;
            if      (tile == 0) src = Ah + (size_t)(m0 + r) * DMOD + k0e + cc * 8;
            else if (tile == 1) src = Al + (size_t)(m0 + r) * DMOD + k0e + cc * 8;
            else if (tile == 2) src = Bh + (size_t)(n0 + r) * DMOD + k0e + cc * 8;
            else                src = Bl + (size_t)(n0 + r) * DMOD + k0e + cc * 8;
            uint32_t dst = smemu + s * GT_STAGE + tile * GT_TILE + r * GT_RSB + cc * 16;
            cp_async16(dst, src);
        }
    };

    issue(0, 0);
    asm volatile("cp.async.commit_group;" ::: "memory");
    issue(1, 1);
    asm volatile("cp.async.commit_group;" ::: "memory");

    for (int c = 0; c < GT_KCH; ++c) {
        asm volatile("cp.async.wait_group 1;" ::: "memory");
        __syncthreads();

        const uint32_t stg = smemu + (c % 3) * GT_STAGE;
        #pragma unroll
        for (int ks = 0; ks < 2; ++ks) {
            const uint32_t kb = ks * 32 + l16 * 16;
            uint32_t ah[2][4], al[2][4];
            #pragma unroll
            for (int i = 0; i < 2; ++i) {
                uint32_t aadr = stg + (warp_m * 32 + i * 16 + l8 * 8 + li) * GT_RSB + kb;
                ldsm_x4(ah[i][0], ah[i][1], ah[i][2], ah[i][3], aadr);
                ldsm_x4(al[i][0], al[i][1], al[i][2], al[i][3], aadr + GT_TILE);
            }
            #pragma unroll
            for (int j = 0; j < 8; ++j) {
                uint32_t badr = stg + (2 + l16) * GT_TILE +
                                (warp_n * 64 + j * 8 + li) * GT_RSB +
                                ks * 32 + ((lane >> 3) & 1) * 16;
                uint32_t bh0, bh1, bl0, bl1;
                ldsm_x4(bh0, bh1, bl0, bl1, badr);
                #pragma unroll
                for (int i = 0; i < 2; ++i) {
                    mma_bf16(acc[i][j], ah[i][0], ah[i][1], ah[i][2], ah[i][3], bl0, bl1);
                    mma_bf16(acc[i][j], al[i][0], al[i][1], al[i][2], al[i][3], bh0, bh1);
                    mma_bf16(acc[i][j], ah[i][0], ah[i][1], ah[i][2], ah[i][3], bh0, bh1);
                }
            }
        }

        if (c + 2 < GT_KCH) issue(c + 2, (c + 2) % 3);
        asm volatile("cp.async.commit_group;" ::: "memory");
    }

    #pragma unroll
    for (int j = 0; j < 8; ++j) {
        int col = n0 + warp_n * 64 + j * 8 + kq * 2;
        float b0 = bias[col], b1 = bias[col + 1];
        #pragma unroll
        for (int i = 0; i < 2; ++i) {
            int row = m0 + warp_m * 32 + i * 16 + r4;
            float y0 = acc[i][j][0] + b0, y1 = acc[i][j][1] + b1;
            float y2 = acc[i][j][2] + b0, y3 = acc[i][j][3] + b1;
            if (OUT == 0) {
                *(float2*)&C[(size_t)row * DMOD + col]       = make_float2(y0, y1);
                *(float2*)&C[(size_t)(row + 8) * DMOD + col] = make_float2(y2, y3);
            } else {
                y0 *= oscale; y1 *= oscale; y2 *= oscale; y3 *= oscale;
                __half h0 = __float2half_rn(y0), h1 = __float2half_rn(y1);
                __half h2 = __float2half_rn(y2), h3 = __float2half_rn(y3);
                __half2 H0 = __halves2half2(h0, h1), H1 = __halves2half2(h2, h3);
                *(__half2*)&Yh[(size_t)row * DMOD + col]       = H0;
                *(__half2*)&Yh[(size_t)(row + 8) * DMOD + col] = H1;
                if (Yl != nullptr) {
                    __half e0 = __float2half_rn(y0 - __half2float(h0));
                    __half e1 = __float2half_rn(y1 - __half2float(h1));
                    __half e2 = __float2half_rn(y2 - __half2float(h2));
                    __half e3 = __float2half_rn(y3 - __half2float(h3));
                    __half2 L0 = __halves2half2(e0, e1), L1 = __halves2half2(e2, e3);
                    *(__half2*)&Yl[(size_t)row * DMOD + col]       = L0;
                    *(__half2*)&Yl[(size_t)(row + 8) * DMOD + col] = L1;
                }
            }
        }
    }
}

// ---------------------------------------------------------------------------
// Flash attention, fp16 mma + ldmatrix. CTA: one (b,h), 128 q rows; 8 warps,
// each owns 16 full rows. QK^T: 2 products (qh*kh + qh*kl — K corrected,
// Q-lo term dropped: ~2.8e-4 abs score err). P fp16; V fp16 hi only.
// Output written directly as bf16 hi/lo split (feeds final GEMM).
// ---------------------------------------------------------------------------
#define FL_RSQ  272                   // 128 halves*2B + 16B pad
#define FL_RSV  144                   // 64 halves*2B + 16B pad
#define FL_QHS  0                     // Q hi: 34816
#define FL_K0   34816                 // K hi+lo double buf: 2*34816
#define FL_V0   104448                // V hi double buf: 2*18432
#define FL_SMEM 141312

__global__ __launch_bounds__(256, 1)
void flash_mma_kernel(const __half* __restrict__ Qh,
                      const __half* __restrict__ Kh, const __half* __restrict__ Kl,
                      const __half* __restrict__ Vh,
                      __nv_bfloat16* __restrict__ Oh, __nv_bfloat16* __restrict__ Ol)
{
    extern __shared__ char smem[];
    const uint32_t su = smem_to_u32(smem);
    const int tid  = threadIdx.x;
    const int lane = tid & 31;
    const int wid  = tid >> 5;
    const int r4 = lane >> 2, kq = lane & 3;
    const int li  = lane & 7;
    const int l8  = (lane >> 3) & 1;
    const int l16 = (lane >> 4) & 1;
    const int q0 = blockIdx.x << 7;
    const int h  = blockIdx.y, b = blockIdx.z;
    const size_t qkbase = (size_t)b * SEQ * DMOD + (size_t)h * DKH;
    const size_t vtbase = ((size_t)b * NHEAD + h) * DKH * SEQ;

    auto load_kv = [&](int t, int st) {
        const int n0 = t << 6;
        const uint32_t kd = su + FL_K0 + st * 34816;
        const uint32_t vd = su + FL_V0 + st * 18432;
        #pragma unroll
        for (int u = 0; u < 4; u++) {
            int idx = u * 256 + tid;
            int r = idx >> 4, sg = idx & 15;
            cp_async16(kd + r * FL_RSQ + sg * 16,
                       Kh + qkbase + (size_t)(n0 + r) * DMOD + sg * 8);
            cp_async16(kd + 17408 + r * FL_RSQ + sg * 16,
                       Kl + qkbase + (size_t)(n0 + r) * DMOD + sg * 8);
        }
        #pragma unroll
        for (int u = 0; u < 4; u++) {
            int idx = u * 256 + tid;
            int r = idx >> 3, sg = idx & 7;
            cp_async16(vd + r * FL_RSV + sg * 16,
                       Vh + vtbase + (size_t)r * SEQ + n0 + sg * 8);
        }
    };

    // Q hi tile: 128 rows x 16 segs
    #pragma unroll
    for (int u = 0; u < 8; u++) {
        int idx = u * 256 + tid;
        int r = idx >> 4, sg = idx & 15;
        cp_async16(su + FL_QHS + r * FL_RSQ + sg * 16,
                   Qh + qkbase + (size_t)(q0 + r) * DMOD + sg * 8);
    }
    asm volatile("cp.async.commit_group;" ::: "memory");
    load_kv(0, 0);
    asm volatile("cp.async.commit_group;" ::: "memory");
    asm volatile("cp.async.wait_group 0;" ::: "memory");
    __syncthreads();

    // Q-hi fragments, register-resident across all KV tiles
    const uint32_t qrowoff = (wid * 16 + l8 * 8 + li) * FL_RSQ + l16 * 16;
    uint32_t aqh[8][4];
    #pragma unroll
    for (int k = 0; k < 8; k++)
        ldsm_x4(aqh[k][0], aqh[k][1], aqh[k][2], aqh[k][3],
                su + FL_QHS + qrowoff + k * 32);

    float oc[16][4];
    #pragma unroll
    for (int nf = 0; nf < 16; nf++)
        #pragma unroll
        for (int p = 0; p < 4; p++) oc[nf][p] = 0.f;
    float m0 = -1e30f, m1 = -1e30f, l0 = 0.f, l1 = 0.f;

    for (int t = 0; t < 32; t++) {
        const int st = t & 1;
        const uint32_t ks = su + FL_K0 + st * 34816;   // K hi (lo at +17408)
        const uint32_t vs = su + FL_V0 + st * 18432;   // V hi

        if (t + 1 < 32) {
            load_kv(t + 1, st ^ 1);
            asm volatile("cp.async.commit_group;" ::: "memory");
        }

        // S = Q @ K^T  (qh*kl + qh*kh)
        float sc[8][4];
        #pragma unroll
        for (int nf = 0; nf < 8; nf++)
            #pragma unroll
            for (int p = 0; p < 4; p++) sc[nf][p] = 0.f;

        #pragma unroll
        for (int k = 0; k < 8; k++) {
            #pragma unroll
            for (int nf = 0; nf < 8; nf++) {
                // x4: lanes0-15 -> Khi (kh0,kh1); lanes16-31 -> Klo (kl0,kl1)
                uint32_t kadr = ks + l16 * 17408 + (nf * 8 + li) * FL_RSQ +
                                l8 * 16 + k * 32;
                uint32_t kh0, kh1, kl0, kl1;
                ldsm_x4(kh0, kh1, kl0, kl1, kadr);
                mma_f16(sc[nf], aqh[k][0], aqh[k][1], aqh[k][2], aqh[k][3], kl0, kl1);
                mma_f16(sc[nf], aqh[k][0], aqh[k][1], aqh[k][2], aqh[k][3], kh0, kh1);
            }
        }

        // online softmax — rows r4 / r4+8, full 64-col row in this warp
        float mx0 = -1e30f, mx1 = -1e30f;
        #pragma unroll
        for (int nf = 0; nf < 8; nf++) {
            mx0 = fmaxf(mx0, fmaxf(sc[nf][0], sc[nf][1]));
            mx1 = fmaxf(mx1, fmaxf(sc[nf][2], sc[nf][3]));
        }
        mx0 = fmaxf(mx0, __shfl_xor_sync(0xffffffffu, mx0, 1));
        mx0 = fmaxf(mx0, __shfl_xor_sync(0xffffffffu, mx0, 2));
        mx1 = fmaxf(mx1, __shfl_xor_sync(0xffffffffu, mx1, 1));
        mx1 = fmaxf(mx1, __shfl_xor_sync(0xffffffffu, mx1, 2));

        const float mn0 = fmaxf(m0, mx0), mn1 = fmaxf(m1, mx1);
        const float c0 = __expf(m0 - mn0), c1 = __expf(m1 - mn1);
        float s0 = 0.f, s1 = 0.f;
        uint32_t pa[4][4];    // P as A-frags (c-frag == A-frag layout)
        #pragma unroll
        for (int nf = 0; nf < 8; nf++) {
            float p0 = __expf(sc[nf][0] - mn0);
            float p1 = __expf(sc[nf][1] - mn0);
            float p2 = __expf(sc[nf][2] - mn1);
            float p3 = __expf(sc[nf][3] - mn1);
            s0 += p0 + p1; s1 += p2 + p3;
            __half2 hA = __floats2half2_rn(p0, p1);
            __half2 hB = __floats2half2_rn(p2, p3);
            pa[nf >> 1][(nf & 1) ? 2 : 0] = *(uint32_t*)&hA;
            pa[nf >> 1][(nf & 1) ? 3 : 1] = *(uint32_t*)&hB;
        }
        s0 += __shfl_xor_sync(0xffffffffu, s0, 1);
        s0 += __shfl_xor_sync(0xffffffffu, s0, 2);
        s1 += __shfl_xor_sync(0xffffffffu, s1, 1);
        s1 += __shfl_xor_sync(0xffffffffu, s1, 2);
        l0 = l0 * c0 + s0; m0 = mn0;
        l1 = l1 * c1 + s1; m1 = mn1;
        #pragma unroll
        for (int nf = 0; nf < 16; nf++) {
            oc[nf][0] *= c0; oc[nf][1] *= c0;
            oc[nf][2] *= c1; oc[nf][3] *= c1;
        }

        // O += P @ V  (V hi only; x4 loads serve two nf tiles)
        #pragma unroll
        for (int k = 0; k < 4; k++) {
            #pragma unroll
            for (int nf = 0; nf < 16; nf += 2) {
                uint32_t vadr = vs + (nf * 8 + l16 * 8 + li) * FL_RSV +
                                k * 32 + l8 * 16;
                uint32_t v0, v1, v2, v3;
                ldsm_x4(v0, v1, v2, v3, vadr);
                mma_f16(oc[nf],     pa[k][0], pa[k][1], pa[k][2], pa[k][3], v0, v1);
                mma_f16(oc[nf + 1], pa[k][0], pa[k][1], pa[k][2], pa[k][3], v2, v3);
            }
        }

        if (t + 1 < 32) {
            asm volatile("cp.async.wait_group 0;" ::: "memory");
            __syncthreads();
        }
    }

    // epilogue: normalize + bf16 hi/lo split, direct to Ah/Al of final GEMM
    const float inv0 = 1.f / l0, inv1 = 1.f / l1;
    #pragma unroll
    for (int nf = 0; nf < 16; nf++) {
        int col  = nf * 8 + kq * 2;
        int row0 = q0 + wid * 16 + r4;
        float y[4] = {oc[nf][0] * inv0, oc[nf][1] * inv0,
                      oc[nf][2] * inv1, oc[nf][3] * inv1};
        uint32_t hp[2], lp[2];
        #pragma unroll
        for (int p = 0; p < 2; p++) {
            __nv_bfloat16 h0 = __float2bfloat16_rn(y[2 * p]);
            __nv_bfloat16 h1 = __float2bfloat16_rn(y[2 * p + 1]);
            __nv_bfloat16 e0 = __float2bfloat16_rn(y[2 * p]     - __bfloat162float(h0));
            __nv_bfloat16 e1 = __float2bfloat16_rn(y[2 * p + 1] - __bfloat162float(h1));
            hp[p] = (uint32_t)__bfloat16_as_ushort(h0) | ((uint32_t)__bfloat16_as_ushort(h1) << 16);
            lp[p] = (uint32_t)__bfloat16_as_ushort(e0) | ((uint32_t)__bfloat16_as_ushort(e1) << 16);
        }
        *(uint32_t*)&Oh[qkbase + (size_t)row0 * DMOD + col]       = hp[0];
        *(uint32_t*)&Oh[qkbase + (size_t)(row0 + 8) * DMOD + col] = hp[1];
        *(uint32_t*)&Ol[qkbase + (size_t)row0 * DMOD + col]       = lp[0];
        *(uint32_t*)&Ol[qkbase + (size_t)(row0 + 8) * DMOD + col] = lp[1];
    }
}

// ---------------------------------------------------------------------------
// Launch
// ---------------------------------------------------------------------------
extern "C" void kernel_launch(void* const* d_in, const int* in_sizes, int n_in,
                              void* d_out, int out_size)
{
    const float* q  = (const float*)d_in[0];
    const float* k  = (const float*)d_in[1];
    const float* v  = (const float*)d_in[2];
    const float* Wq = (const float*)d_in[3];
    const float* bq = (const float*)d_in[4];
    const float* Wk = (const float*)d_in[5];
    const float* bk = (const float*)d_in[6];
    const float* Wv = (const float*)d_in[7];
    const float* bv = (const float*)d_in[8];
    const float* Wo = (const float*)d_in[9];
    const float* bo = (const float*)d_in[10];
    float* out = (float*)d_out;

    float *Vp;
    __nv_bfloat16 *Wth, *Wtl, *Ah, *Al;
    __half *Qh, *Kh, *Kl, *Vth;
    cudaGetSymbolAddress((void**)&Vp,  g_Vp);
    cudaGetSymbolAddress((void**)&Wth, g_Wth);
    cudaGetSymbolAddress((void**)&Wtl, g_Wtl);
    cudaGetSymbolAddress((void**)&Ah,  g_Ah);
    cudaGetSymbolAddress((void**)&Al,  g_Al);
    cudaGetSymbolAddress((void**)&Qh,  g_Qh);
    cudaGetSymbolAddress((void**)&Kh,  g_Kh16);
    cudaGetSymbolAddress((void**)&Kl,  g_Kl16);
    cudaGetSymbolAddress((void**)&Vth, g_Vth);

    cudaFuncSetAttribute(gemm_mma_kernel<0>,
                         cudaFuncAttributeMaxDynamicSharedMemorySize, GT_SMEM);
    cudaFuncSetAttribute(gemm_mma_kernel<1>,
                         cudaFuncAttributeMaxDynamicSharedMemorySize, GT_SMEM);
    cudaFuncSetAttribute(flash_mma_kernel,
                         cudaFuncAttributeMaxDynamicSharedMemorySize, FL_SMEM);

    const dim3 gt(DMOD / 32, DMOD / 32);          // W transpose grid
    const dim3 gg(DMOD / 128, TOK / 128);         // gemm grid (16, 32)
    const int  ga = (TOK * DMOD) / (256 * 8);     // elementwise grids
    const float scale = 0.08838834764831845f;     // 1/sqrt(128)

    // Q projection -> fp16 hi only (pre-scaled)
    asplit_kernel<<<ga, 256>>>(q, Ah, Al);
    wsplit_t_kernel<<<gt, 256>>>(Wq, Wth, Wtl);
    gemm_mma_kernel<1><<<gg, 256, GT_SMEM>>>(Ah, Al, Wth, Wtl, bq,
                                             nullptr, Qh, nullptr, scale);

    // K projection -> fp16 hi/lo
    asplit_kernel<<<ga, 256>>>(k, Ah, Al);
    wsplit_t_kernel<<<gt, 256>>>(Wk, Wth, Wtl);
    gemm_mma_kernel<1><<<gg, 256, GT_SMEM>>>(Ah, Al, Wth, Wtl, bk,
                                             nullptr, Kh, Kl, 1.0f);

    // V projection -> fp32 (for transpose)
    asplit_kernel<<<ga, 256>>>(v, Ah, Al);
    wsplit_t_kernel<<<gt, 256>>>(Wv, Wth, Wtl);
    gemm_mma_kernel<0><<<gg, 256, GT_SMEM>>>(Ah, Al, Wth, Wtl, bv,
                                             Vp, nullptr, nullptr, 1.0f);
    vtrans_kernel<<<dim3(SEQ / 32, DKH / 32, 2 * NHEAD), 256>>>(Vp, Vth);

    // attention -> bf16 hi/lo directly into final-GEMM A operands
    flash_mma_kernel<<<dim3(SEQ / 128, NHEAD, 2), 256, FL_SMEM>>>(
        Qh, Kh, Kl, Vth, Ah, Al);

    // output projection
    wsplit_t_kernel<<<gt, 256>>>(Wo, Wth, Wtl);
    gemm_mma_kernel<0><<<gg, 256, GT_SMEM>>>(Ah, Al, Wth, Wtl, bo,
                                             out, nullptr, nullptr, 1.0f);
}

// round 10
// speedup vs baseline: 4.0315x; 1.2726x over previous
#include <cuda_runtime.h>
#include <cuda_bf16.h>
#include <cuda_fp16.h>
#include <cstdint>

#define TOK   4096      // B*S tokens
#define DMOD  2048      // model dim
#define SEQ   2048      // sequence length
#define NHEAD 16
#define DKH   128       // head dim

// Scratch (device globals: allocation-free per harness rules)
__device__ float  g_Vp[(size_t)TOK * DMOD];
__device__ __half g_A16[(size_t)TOK * DMOD];    // GEMM A operand fp16
__device__ __half g_Wth[(size_t)DMOD * DMOD];   // W^T hi fp16, [N][K]
__device__ __half g_Wtl[(size_t)DMOD * DMOD];   // W^T lo fp16, [N][K]
__device__ __half g_Qh[(size_t)TOK * DMOD];     // Q*scale hi fp16
__device__ __half g_Kh16[(size_t)TOK * DMOD];   // K hi fp16
__device__ __half g_Kl16[(size_t)TOK * DMOD];   // K lo fp16
__device__ __half g_Vth[(size_t)TOK * DMOD];    // V^T fp16 [b,h,d,s]
__device__ __half g_O16[(size_t)TOK * DMOD];    // attention output fp16

// ---------------------------------------------------------------------------
// helpers
// ---------------------------------------------------------------------------
__device__ __forceinline__ uint32_t smem_to_u32(const void* p) {
    uint32_t a;
    asm("{ .reg .u64 t; cvta.to.shared.u64 t, %1; cvt.u32.u64 %0, t; }"
        : "=r"(a) : "l"(p));
    return a;
}

__device__ __forceinline__ void cp_async16(uint32_t dst, const void* src) {
    asm volatile("cp.async.cg.shared.global [%0], [%1], 16;"
                 :: "r"(dst), "l"(src));
}

__device__ __forceinline__ void ldsm_x4(uint32_t& r0, uint32_t& r1,
                                        uint32_t& r2, uint32_t& r3, uint32_t addr) {
    asm volatile("ldmatrix.sync.aligned.m8n8.x4.shared.b16 {%0,%1,%2,%3}, [%4];"
                 : "=r"(r0), "=r"(r1), "=r"(r2), "=r"(r3) : "r"(addr));
}

__device__ __forceinline__ void mma_f16(float* c,
    uint32_t a0, uint32_t a1, uint32_t a2, uint32_t a3,
    uint32_t b0, uint32_t b1)
{
    asm volatile(
        "mma.sync.aligned.m16n8k16.row.col.f32.f16.f16.f32 "
        "{%0,%1,%2,%3}, {%4,%5,%6,%7}, {%8,%9}, {%0,%1,%2,%3};"
        : "+f"(c[0]), "+f"(c[1]), "+f"(c[2]), "+f"(c[3])
        : "r"(a0), "r"(a1), "r"(a2), "r"(a3), "r"(b0), "r"(b1));
}

// ---------------------------------------------------------------------------
// W split-transpose: W[K][N] fp32 -> Th[N][K], Tl[N][K] fp16 (hi/lo split)
// ---------------------------------------------------------------------------
__global__ __launch_bounds__(256)
void wsplit_t_kernel(const float* __restrict__ W,
                     __half* __restrict__ Th, __half* __restrict__ Tl)
{
    __shared__ float ts[32][33];
    const int tx = threadIdx.x & 31;
    const int ty = threadIdx.x >> 5;
    const int n0 = blockIdx.x * 32;
    const int k0 = blockIdx.y * 32;

    #pragma unroll
    for (int j = 0; j < 32; j += 8)
        ts[ty + j][tx] = W[(size_t)(k0 + ty + j) * DMOD + n0 + tx];
    __syncthreads();

    #pragma unroll
    for (int j = 0; j < 32; j += 8) {
        float x = ts[tx][ty + j];
        __half h = __float2half_rn(x);
        __half l = __float2half_rn(x - __half2float(h));
        size_t o = (size_t)(n0 + ty + j) * DMOD + k0 + tx;
        Th[o] = h;
        Tl[o] = l;
    }
}

// ---------------------------------------------------------------------------
// fp32 -> fp16 elementwise (8/thread)
// ---------------------------------------------------------------------------
__global__ __launch_bounds__(256)
void h16_kernel(const float* __restrict__ X, __half* __restrict__ Y)
{
    size_t i = ((size_t)blockIdx.x * 256 + threadIdx.x) * 8;
    float4 f0 = *(const float4*)(X + i);
    float4 f1 = *(const float4*)(X + i + 4);
    __half2 h0 = __floats2half2_rn(f0.x, f0.y);
    __half2 h1 = __floats2half2_rn(f0.z, f0.w);
    __half2 h2 = __floats2half2_rn(f1.x, f1.y);
    __half2 h3 = __floats2half2_rn(f1.z, f1.w);
    *(uint4*)(Y + i) = make_uint4(*(uint32_t*)&h0, *(uint32_t*)&h1,
                                  *(uint32_t*)&h2, *(uint32_t*)&h3);
}

// ---------------------------------------------------------------------------
// V transpose: Vp [b,s,h*128+d] fp32 -> Vth [(b*16+h)*128+d][s] fp16
// ---------------------------------------------------------------------------
__global__ __launch_bounds__(256)
void vtrans_kernel(const float* __restrict__ Vp, __half* __restrict__ Vh)
{
    __shared__ float ts[32][33];
    const int tx = threadIdx.x & 31;
    const int ty = threadIdx.x >> 5;
    const int bh = blockIdx.z;
    const int b  = bh >> 4, h = bh & 15;
    const int s0 = blockIdx.x * 32;
    const int d0 = blockIdx.y * 32;

    #pragma unroll
    for (int j = 0; j < 32; j += 8)
        ts[ty + j][tx] = Vp[((size_t)b * SEQ + s0 + ty + j) * DMOD + h * DKH + d0 + tx];
    __syncthreads();

    #pragma unroll
    for (int j = 0; j < 32; j += 8)
        Vh[((size_t)bh * DKH + d0 + ty + j) * SEQ + s0 + tx] =
            __float2half_rn(ts[tx][ty + j]);
}

// ---------------------------------------------------------------------------
// fp16 mma GEMM, 2-product: C = A @ (Wh + Wl) + bias.
// A fp16 [M][K] single plane; B fp16 hi/lo [N][K].
// CTA 128x128, BK=32, 3-stage cp.async, 8 warps (4Mx2N), ldmatrix loads.
// OUT=0: fp32 C.   OUT=1: fp16 hi (and lo if Yl) of (C+bias)*oscale.
// ---------------------------------------------------------------------------
#define GT_RSB    80
#define GT_TILE   (128 * GT_RSB)      // 10240
#define GT_STAGE  (3 * GT_TILE)       // 30720 (A, Bh, Bl)
#define GT_SMEM   (3 * GT_STAGE)      // 92160
#define GT_KCH    64

template<int OUT>
__global__ __launch_bounds__(256, 1)
void gemm_mma_kernel(const __half* __restrict__ A,
                     const __half* __restrict__ Bh,
                     const __half* __restrict__ Bl,
                     const float* __restrict__ bias,
                     float* __restrict__ C,
                     __half* __restrict__ Yh, __half* __restrict__ Yl,
                     float oscale)
{
    extern __shared__ char smem[];
    const uint32_t smemu = smem_to_u32(smem);
    const int tid    = threadIdx.x;
    const int lane   = tid & 31;
    const int wid    = tid >> 5;
    const int warp_m = wid & 3;
    const int warp_n = wid >> 2;
    const int r4     = lane >> 2;
    const int kq     = lane & 3;
    const int li  = lane & 7;
    const int l8  = (lane >> 3) & 1;
    const int l16 = (lane >> 4) & 1;
    const int n0 = blockIdx.x << 7;
    const int m0 = blockIdx.y << 7;

    float acc[2][8][4];
    #pragma unroll
    for (int i = 0; i < 2; i++)
        #pragma unroll
        for (int j = 0; j < 8; j++)
            #pragma unroll
            for (int p = 0; p < 4; p++) acc[i][j][p] = 0.f;

    // 3 tiles x 128 rows x 4 segs = 1536 16B units; 6 per thread
    auto issue = [&](int c, int s) {
        const int k0e = c << 5;
        #pragma unroll
        for (int it = 0; it < 6; ++it) {
            int idx  = it * 256 + tid;
            int tile = idx >> 9;               // 0:A 1:Bh 2:Bl
            int r    = (idx >> 2) & 127;
            int cc   = idx & 3;
            const __half* src;
            if      (tile == 0) src = A  + (size_t)(m0 + r) * DMOD + k0e + cc * 8;
            else if (tile == 1) src = Bh + (size_t)(n0 + r) * DMOD + k0e + cc * 8;
            else                src = Bl + (size_t)(n0 + r) * DMOD + k0e + cc * 8;
            uint32_t dst = smemu + s * GT_STAGE + tile * GT_TILE + r * GT_RSB + cc * 16;
            cp_async16(dst, src);
        }
    };

    issue(0, 0);
    asm volatile("cp.async.commit_group;" ::: "memory");
    issue(1, 1);
    asm volatile("cp.async.commit_group;" ::: "memory");

    for (int c = 0; c < GT_KCH; ++c) {
        asm volatile("cp.async.wait_group 1;" ::: "memory");
        __syncthreads();

        const uint32_t stg = smemu + (c % 3) * GT_STAGE;
        #pragma unroll
        for (int ks = 0; ks < 2; ++ks) {
            const uint32_t kb = ks * 32 + l16 * 16;
            uint32_t a[2][4];
            #pragma unroll
            for (int i = 0; i < 2; ++i) {
                uint32_t aadr = stg + (warp_m * 32 + i * 16 + l8 * 8 + li) * GT_RSB + kb;
                ldsm_x4(a[i][0], a[i][1], a[i][2], a[i][3], aadr);
            }
            #pragma unroll
            for (int j = 0; j < 8; ++j) {
                // x4: lanes 0-15 -> Bh (bh0,bh1); lanes 16-31 -> Bl (bl0,bl1)
                uint32_t badr = stg + (1 + l16) * GT_TILE +
                                (warp_n * 64 + j * 8 + li) * GT_RSB +
                                ks * 32 + l8 * 16;
                uint32_t bh0, bh1, bl0, bl1;
                ldsm_x4(bh0, bh1, bl0, bl1, badr);
                #pragma unroll
                for (int i = 0; i < 2; ++i) {
                    mma_f16(acc[i][j], a[i][0], a[i][1], a[i][2], a[i][3], bl0, bl1);
                    mma_f16(acc[i][j], a[i][0], a[i][1], a[i][2], a[i][3], bh0, bh1);
                }
            }
        }

        if (c + 2 < GT_KCH) issue(c + 2, (c + 2) % 3);
        asm volatile("cp.async.commit_group;" ::: "memory");
    }

    #pragma unroll
    for (int j = 0; j < 8; ++j) {
        int col = n0 + warp_n * 64 + j * 8 + kq * 2;
        float b0 = bias[col], b1 = bias[col + 1];
        #pragma unroll
        for (int i = 0; i < 2; ++i) {
            int row = m0 + warp_m * 32 + i * 16 + r4;
            float y0 = acc[i][j][0] + b0, y1 = acc[i][j][1] + b1;
            float y2 = acc[i][j][2] + b0, y3 = acc[i][j][3] + b1;
            if (OUT == 0) {
                *(float2*)&C[(size_t)row * DMOD + col]       = make_float2(y0, y1);
                *(float2*)&C[(size_t)(row + 8) * DMOD + col] = make_float2(y2, y3);
            } else {
                y0 *= oscale; y1 *= oscale; y2 *= oscale; y3 *= oscale;
                __half h0 = __float2half_rn(y0), h1 = __float2half_rn(y1);
                __half h2 = __float2half_rn(y2), h3 = __float2half_rn(y3);
                __half2 H0 = __halves2half2(h0, h1), H1 = __halves2half2(h2, h3);
                *(__half2*)&Yh[(size_t)row * DMOD + col]       = H0;
                *(__half2*)&Yh[(size_t)(row + 8) * DMOD + col] = H1;
                if (Yl != nullptr) {
                    __half e0 = __float2half_rn(y0 - __half2float(h0));
                    __half e1 = __float2half_rn(y1 - __half2float(h1));
                    __half e2 = __float2half_rn(y2 - __half2float(h2));
                    __half e3 = __float2half_rn(y3 - __half2float(h3));
                    __half2 L0 = __halves2half2(e0, e1), L1 = __halves2half2(e2, e3);
                    *(__half2*)&Yl[(size_t)row * DMOD + col]       = L0;
                    *(__half2*)&Yl[(size_t)(row + 8) * DMOD + col] = L1;
                }
            }
        }
    }
}

// ---------------------------------------------------------------------------
// Flash attention (unchanged mainloop from R8): fp16 mma + ldmatrix.
// CTA: one (b,h), 128 q rows; 8 warps, each owns 16 full rows.
// QK^T: qh*kh + qh*kl. P fp16; V fp16. Output: fp16 single plane.
// ---------------------------------------------------------------------------
#define FL_RSQ  272                   // 128 halves*2B + 16B pad
#define FL_RSV  144                   // 64 halves*2B + 16B pad
#define FL_QHS  0                     // Q hi: 34816
#define FL_K0   34816                 // K hi+lo double buf: 2*34816
#define FL_V0   104448                // V double buf: 2*18432
#define FL_SMEM 141312

__global__ __launch_bounds__(256, 1)
void flash_mma_kernel(const __half* __restrict__ Qh,
                      const __half* __restrict__ Kh, const __half* __restrict__ Kl,
                      const __half* __restrict__ Vh,
                      __half* __restrict__ O16)
{
    extern __shared__ char smem[];
    const uint32_t su = smem_to_u32(smem);
    const int tid  = threadIdx.x;
    const int lane = tid & 31;
    const int wid  = tid >> 5;
    const int r4 = lane >> 2, kq = lane & 3;
    const int li  = lane & 7;
    const int l8  = (lane >> 3) & 1;
    const int l16 = (lane >> 4) & 1;
    const int q0 = blockIdx.x << 7;
    const int h  = blockIdx.y, b = blockIdx.z;
    const size_t qkbase = (size_t)b * SEQ * DMOD + (size_t)h * DKH;
    const size_t vtbase = ((size_t)b * NHEAD + h) * DKH * SEQ;

    auto load_kv = [&](int t, int st) {
        const int n0 = t << 6;
        const uint32_t kd = su + FL_K0 + st * 34816;
        const uint32_t vd = su + FL_V0 + st * 18432;
        #pragma unroll
        for (int u = 0; u < 4; u++) {
            int idx = u * 256 + tid;
            int r = idx >> 4, sg = idx & 15;
            cp_async16(kd + r * FL_RSQ + sg * 16,
                       Kh + qkbase + (size_t)(n0 + r) * DMOD + sg * 8);
            cp_async16(kd + 17408 + r * FL_RSQ + sg * 16,
                       Kl + qkbase + (size_t)(n0 + r) * DMOD + sg * 8);
        }
        #pragma unroll
        for (int u = 0; u < 4; u++) {
            int idx = u * 256 + tid;
            int r = idx >> 3, sg = idx & 7;
            cp_async16(vd + r * FL_RSV + sg * 16,
                       Vh + vtbase + (size_t)r * SEQ + n0 + sg * 8);
        }
    };

    #pragma unroll
    for (int u = 0; u < 8; u++) {
        int idx = u * 256 + tid;
        int r = idx >> 4, sg = idx & 15;
        cp_async16(su + FL_QHS + r * FL_RSQ + sg * 16,
                   Qh + qkbase + (size_t)(q0 + r) * DMOD + sg * 8);
    }
    asm volatile("cp.async.commit_group;" ::: "memory");
    load_kv(0, 0);
    asm volatile("cp.async.commit_group;" ::: "memory");
    asm volatile("cp.async.wait_group 0;" ::: "memory");
    __syncthreads();

    const uint32_t qrowoff = (wid * 16 + l8 * 8 + li) * FL_RSQ + l16 * 16;
    uint32_t aqh[8][4];
    #pragma unroll
    for (int k = 0; k < 8; k++)
        ldsm_x4(aqh[k][0], aqh[k][1], aqh[k][2], aqh[k][3],
                su + FL_QHS + qrowoff + k * 32);

    float oc[16][4];
    #pragma unroll
    for (int nf = 0; nf < 16; nf++)
        #pragma unroll
        for (int p = 0; p < 4; p++) oc[nf][p] = 0.f;
    float m0 = -1e30f, m1 = -1e30f, l0 = 0.f, l1 = 0.f;

    for (int t = 0; t < 32; t++) {
        const int st = t & 1;
        const uint32_t ks = su + FL_K0 + st * 34816;
        const uint32_t vs = su + FL_V0 + st * 18432;

        if (t + 1 < 32) {
            load_kv(t + 1, st ^ 1);
            asm volatile("cp.async.commit_group;" ::: "memory");
        }

        float sc[8][4];
        #pragma unroll
        for (int nf = 0; nf < 8; nf++)
            #pragma unroll
            for (int p = 0; p < 4; p++) sc[nf][p] = 0.f;

        #pragma unroll
        for (int k = 0; k < 8; k++) {
            #pragma unroll
            for (int nf = 0; nf < 8; nf++) {
                uint32_t kadr = ks + l16 * 17408 + (nf * 8 + li) * FL_RSQ +
                                l8 * 16 + k * 32;
                uint32_t kh0, kh1, kl0, kl1;
                ldsm_x4(kh0, kh1, kl0, kl1, kadr);
                mma_f16(sc[nf], aqh[k][0], aqh[k][1], aqh[k][2], aqh[k][3], kl0, kl1);
                mma_f16(sc[nf], aqh[k][0], aqh[k][1], aqh[k][2], aqh[k][3], kh0, kh1);
            }
        }

        float mx0 = -1e30f, mx1 = -1e30f;
        #pragma unroll
        for (int nf = 0; nf < 8; nf++) {
            mx0 = fmaxf(mx0, fmaxf(sc[nf][0], sc[nf][1]));
            mx1 = fmaxf(mx1, fmaxf(sc[nf][2], sc[nf][3]));
        }
        mx0 = fmaxf(mx0, __shfl_xor_sync(0xffffffffu, mx0, 1));
        mx0 = fmaxf(mx0, __shfl_xor_sync(0xffffffffu, mx0, 2));
        mx1 = fmaxf(mx1, __shfl_xor_sync(0xffffffffu, mx1, 1));
        mx1 = fmaxf(mx1, __shfl_xor_sync(0xffffffffu, mx1, 2));

        const float mn0 = fmaxf(m0, mx0), mn1 = fmaxf(m1, mx1);
        const float c0 = __expf(m0 - mn0), c1 = __expf(m1 - mn1);
        float s0 = 0.f, s1 = 0.f;
        uint32_t pa[4][4];
        #pragma unroll
        for (int nf = 0; nf < 8; nf++) {
            float p0 = __expf(sc[nf][0] - mn0);
            float p1 = __expf(sc[nf][1] - mn0);
            float p2 = __expf(sc[nf][2] - mn1);
            float p3 = __expf(sc[nf][3] - mn1);
            s0 += p0 + p1; s1 += p2 + p3;
            __half2 hA = __floats2half2_rn(p0, p1);
            __half2 hB = __floats2half2_rn(p2, p3);
            pa[nf >> 1][(nf & 1) ? 2 : 0] = *(uint32_t*)&hA;
            pa[nf >> 1][(nf & 1) ? 3 : 1] = *(uint32_t*)&hB;
        }
        s0 += __shfl_xor_sync(0xffffffffu, s0, 1);
        s0 += __shfl_xor_sync(0xffffffffu, s0, 2);
        s1 += __shfl_xor_sync(0xffffffffu, s1, 1);
        s1 += __shfl_xor_sync(0xffffffffu, s1, 2);
        l0 = l0 * c0 + s0; m0 = mn0;
        l1 = l1 * c1 + s1; m1 = mn1;
        #pragma unroll
        for (int nf = 0; nf < 16; nf++) {
            oc[nf][0] *= c0; oc[nf][1] *= c0;
            oc[nf][2] *= c1; oc[nf][3] *= c1;
        }

        #pragma unroll
        for (int k = 0; k < 4; k++) {
            #pragma unroll
            for (int nf = 0; nf < 16; nf += 2) {
                uint32_t vadr = vs + (nf * 8 + l16 * 8 + li) * FL_RSV +
                                k * 32 + l8 * 16;
                uint32_t v0, v1, v2, v3;
                ldsm_x4(v0, v1, v2, v3, vadr);
                mma_f16(oc[nf],     pa[k][0], pa[k][1], pa[k][2], pa[k][3], v0, v1);
                mma_f16(oc[nf + 1], pa[k][0], pa[k][1], pa[k][2], pa[k][3], v2, v3);
            }
        }

        if (t + 1 < 32) {
            asm volatile("cp.async.wait_group 0;" ::: "memory");
            __syncthreads();
        }
    }

    // epilogue: normalize, fp16 single plane -> final-GEMM A operand
    const float inv0 = 1.f / l0, inv1 = 1.f / l1;
    #pragma unroll
    for (int nf = 0; nf < 16; nf++) {
        int col  = nf * 8 + kq * 2;
        int row0 = q0 + wid * 16 + r4;
        __half2 H0 = __floats2half2_rn(oc[nf][0] * inv0, oc[nf][1] * inv0);
        __half2 H1 = __floats2half2_rn(oc[nf][2] * inv1, oc[nf][3] * inv1);
        *(__half2*)&O16[qkbase + (size_t)row0 * DMOD + col]       = H0;
        *(__half2*)&O16[qkbase + (size_t)(row0 + 8) * DMOD + col] = H1;
    }
}

// ---------------------------------------------------------------------------
// Launch
// ---------------------------------------------------------------------------
extern "C" void kernel_launch(void* const* d_in, const int* in_sizes, int n_in,
                              void* d_out, int out_size)
{
    const float* q  = (const float*)d_in[0];
    const float* k  = (const float*)d_in[1];
    const float* v  = (const float*)d_in[2];
    const float* Wq = (const float*)d_in[3];
    const float* bq = (const float*)d_in[4];
    const float* Wk = (const float*)d_in[5];
    const float* bk = (const float*)d_in[6];
    const float* Wv = (const float*)d_in[7];
    const float* bv = (const float*)d_in[8];
    const float* Wo = (const float*)d_in[9];
    const float* bo = (const float*)d_in[10];
    float* out = (float*)d_out;

    float *Vp;
    __half *A16, *Wth, *Wtl, *Qh, *Kh, *Kl, *Vth, *O16;
    cudaGetSymbolAddress((void**)&Vp,  g_Vp);
    cudaGetSymbolAddress((void**)&A16, g_A16);
    cudaGetSymbolAddress((void**)&Wth, g_Wth);
    cudaGetSymbolAddress((void**)&Wtl, g_Wtl);
    cudaGetSymbolAddress((void**)&Qh,  g_Qh);
    cudaGetSymbolAddress((void**)&Kh,  g_Kh16);
    cudaGetSymbolAddress((void**)&Kl,  g_Kl16);
    cudaGetSymbolAddress((void**)&Vth, g_Vth);
    cudaGetSymbolAddress((void**)&O16, g_O16);

    cudaFuncSetAttribute(gemm_mma_kernel<0>,
                         cudaFuncAttributeMaxDynamicSharedMemorySize, GT_SMEM);
    cudaFuncSetAttribute(gemm_mma_kernel<1>,
                         cudaFuncAttributeMaxDynamicSharedMemorySize, GT_SMEM);
    cudaFuncSetAttribute(flash_mma_kernel,
                         cudaFuncAttributeMaxDynamicSharedMemorySize, FL_SMEM);

    const dim3 gt(DMOD / 32, DMOD / 32);          // W transpose grid
    const dim3 gg(DMOD / 128, TOK / 128);         // gemm grid (16, 32)
    const int  ga = (TOK * DMOD) / (256 * 8);     // elementwise grids
    const float scale = 0.08838834764831845f;     // 1/sqrt(128)

    // Q projection -> fp16 (pre-scaled)
    h16_kernel<<<ga, 256>>>(q, A16);
    wsplit_t_kernel<<<gt, 256>>>(Wq, Wth, Wtl);
    gemm_mma_kernel<1><<<gg, 256, GT_SMEM>>>(A16, Wth, Wtl, bq,
                                             nullptr, Qh, nullptr, scale);

    // K projection -> fp16 hi/lo
    h16_kernel<<<ga, 256>>>(k, A16);
    wsplit_t_kernel<<<gt, 256>>>(Wk, Wth, Wtl);
    gemm_mma_kernel<1><<<gg, 256, GT_SMEM>>>(A16, Wth, Wtl, bk,
                                             nullptr, Kh, Kl, 1.0f);

    // V projection -> fp32 (for transpose)
    h16_kernel<<<ga, 256>>>(v, A16);
    wsplit_t_kernel<<<gt, 256>>>(Wv, Wth, Wtl);
    gemm_mma_kernel<0><<<gg, 256, GT_SMEM>>>(A16, Wth, Wtl, bv,
                                             Vp, nullptr, nullptr, 1.0f);
    vtrans_kernel<<<dim3(SEQ / 32, DKH / 32, 2 * NHEAD), 256>>>(Vp, Vth);

    // attention -> fp16 directly into final-GEMM A operand
    flash_mma_kernel<<<dim3(SEQ / 128, NHEAD, 2), 256, FL_SMEM>>>(
        Qh, Kh, Kl, Vth, O16);

    // output projection
    wsplit_t_kernel<<<gt, 256>>>(Wo, Wth, Wtl);
    gemm_mma_kernel<0><<<gg, 256, GT_SMEM>>>(O16, Wth, Wtl, bo,
                                             out, nullptr, nullptr, 1.0f);
}

// round 11
// speedup vs baseline: 4.3468x; 1.0782x over previous
#include <cuda_runtime.h>
#include <cuda_bf16.h>
#include <cuda_fp16.h>
#include <cstdint>

#define TOK   4096      // B*S tokens
#define DMOD  2048      // model dim
#define SEQ   2048      // sequence length
#define NHEAD 16
#define DKH   128       // head dim

// Scratch (device globals: allocation-free per harness rules)
__device__ __half g_A16[(size_t)TOK * DMOD];    // GEMM A operand fp16
__device__ __half g_Wth[(size_t)DMOD * DMOD];   // W^T hi fp16, [N][K]
__device__ __half g_Wtl[(size_t)DMOD * DMOD];   // W^T lo fp16, [N][K]
__device__ __half g_Qh[(size_t)TOK * DMOD];     // Q*scale fp16
__device__ __half g_Kh16[(size_t)TOK * DMOD];   // K fp16
__device__ __half g_V16[(size_t)TOK * DMOD];    // V proj fp16 [b,s,d]
__device__ __half g_Vth[(size_t)TOK * DMOD];    // V^T fp16 [b,h,d,s]
__device__ __half g_O16[(size_t)TOK * DMOD];    // attention output fp16

// ---------------------------------------------------------------------------
// helpers
// ---------------------------------------------------------------------------
__device__ __forceinline__ uint32_t smem_to_u32(const void* p) {
    uint32_t a;
    asm("{ .reg .u64 t; cvta.to.shared.u64 t, %1; cvt.u32.u64 %0, t; }"
        : "=r"(a) : "l"(p));
    return a;
}

__device__ __forceinline__ void cp_async16(uint32_t dst, const void* src) {
    asm volatile("cp.async.cg.shared.global [%0], [%1], 16;"
                 :: "r"(dst), "l"(src));
}

__device__ __forceinline__ void ldsm_x4(uint32_t& r0, uint32_t& r1,
                                        uint32_t& r2, uint32_t& r3, uint32_t addr) {
    asm volatile("ldmatrix.sync.aligned.m8n8.x4.shared.b16 {%0,%1,%2,%3}, [%4];"
                 : "=r"(r0), "=r"(r1), "=r"(r2), "=r"(r3) : "r"(addr));
}

__device__ __forceinline__ void mma_f16(float* c,
    uint32_t a0, uint32_t a1, uint32_t a2, uint32_t a3,
    uint32_t b0, uint32_t b1)
{
    asm volatile(
        "mma.sync.aligned.m16n8k16.row.col.f32.f16.f16.f32 "
        "{%0,%1,%2,%3}, {%4,%5,%6,%7}, {%8,%9}, {%0,%1,%2,%3};"
        : "+f"(c[0]), "+f"(c[1]), "+f"(c[2]), "+f"(c[3])
        : "r"(a0), "r"(a1), "r"(a2), "r"(a3), "r"(b0), "r"(b1));
}

// ---------------------------------------------------------------------------
// W split-transpose: W[K][N] fp32 -> Th[N][K], Tl[N][K] fp16 (hi/lo split)
// ---------------------------------------------------------------------------
__global__ __launch_bounds__(256)
void wsplit_t_kernel(const float* __restrict__ W,
                     __half* __restrict__ Th, __half* __restrict__ Tl)
{
    __shared__ float ts[32][33];
    const int tx = threadIdx.x & 31;
    const int ty = threadIdx.x >> 5;
    const int n0 = blockIdx.x * 32;
    const int k0 = blockIdx.y * 32;

    #pragma unroll
    for (int j = 0; j < 32; j += 8)
        ts[ty + j][tx] = W[(size_t)(k0 + ty + j) * DMOD + n0 + tx];
    __syncthreads();

    #pragma unroll
    for (int j = 0; j < 32; j += 8) {
        float x = ts[tx][ty + j];
        __half h = __float2half_rn(x);
        __half l = __float2half_rn(x - __half2float(h));
        size_t o = (size_t)(n0 + ty + j) * DMOD + k0 + tx;
        Th[o] = h;
        Tl[o] = l;
    }
}

// ---------------------------------------------------------------------------
// fp32 -> fp16 elementwise (8/thread)
// ---------------------------------------------------------------------------
__global__ __launch_bounds__(256)
void h16_kernel(const float* __restrict__ X, __half* __restrict__ Y)
{
    size_t i = ((size_t)blockIdx.x * 256 + threadIdx.x) * 8;
    float4 f0 = *(const float4*)(X + i);
    float4 f1 = *(const float4*)(X + i + 4);
    __half2 h0 = __floats2half2_rn(f0.x, f0.y);
    __half2 h1 = __floats2half2_rn(f0.z, f0.w);
    __half2 h2 = __floats2half2_rn(f1.x, f1.y);
    __half2 h3 = __floats2half2_rn(f1.z, f1.w);
    *(uint4*)(Y + i) = make_uint4(*(uint32_t*)&h0, *(uint32_t*)&h1,
                                  *(uint32_t*)&h2, *(uint32_t*)&h3);
}

// ---------------------------------------------------------------------------
// V transpose: V16 [b,s,h*128+d] fp16 -> Vth [(b*16+h)*128+d][s] fp16
// ---------------------------------------------------------------------------
__global__ __launch_bounds__(256)
void vtrans_kernel(const __half* __restrict__ Vp, __half* __restrict__ Vh)
{
    __shared__ float ts[32][33];
    const int tx = threadIdx.x & 31;
    const int ty = threadIdx.x >> 5;
    const int bh = blockIdx.z;
    const int b  = bh >> 4, h = bh & 15;
    const int s0 = blockIdx.x * 32;
    const int d0 = blockIdx.y * 32;

    #pragma unroll
    for (int j = 0; j < 32; j += 8)
        ts[ty + j][tx] = __half2float(
            Vp[((size_t)b * SEQ + s0 + ty + j) * DMOD + h * DKH + d0 + tx]);
    __syncthreads();

    #pragma unroll
    for (int j = 0; j < 32; j += 8)
        Vh[((size_t)bh * DKH + d0 + ty + j) * SEQ + s0 + tx] =
            __float2half_rn(ts[tx][ty + j]);
}

// ---------------------------------------------------------------------------
// fp16 mma GEMM, 2-product: C = A @ (Wh + Wl) + bias.
// A fp16 [M][K] single plane; B fp16 hi/lo [N][K].
// CTA 128x128, BK=32, 3-stage cp.async, 8 warps (4Mx2N), ldmatrix loads.
// OUT=0: fp32 C.   OUT=1: fp16 hi (and lo if Yl) of (C+bias)*oscale.
// ---------------------------------------------------------------------------
#define GT_RSB    80
#define GT_TILE   (128 * GT_RSB)      // 10240
#define GT_STAGE  (3 * GT_TILE)       // 30720 (A, Bh, Bl)
#define GT_SMEM   (3 * GT_STAGE)      // 92160
#define GT_KCH    64

template<int OUT>
__global__ __launch_bounds__(256, 1)
void gemm_mma_kernel(const __half* __restrict__ A,
                     const __half* __restrict__ Bh,
                     const __half* __restrict__ Bl,
                     const float* __restrict__ bias,
                     float* __restrict__ C,
                     __half* __restrict__ Yh, __half* __restrict__ Yl,
                     float oscale)
{
    extern __shared__ char smem[];
    const uint32_t smemu = smem_to_u32(smem);
    const int tid    = threadIdx.x;
    const int lane   = tid & 31;
    const int wid    = tid >> 5;
    const int warp_m = wid & 3;
    const int warp_n = wid >> 2;
    const int r4     = lane >> 2;
    const int kq     = lane & 3;
    const int li  = lane & 7;
    const int l8  = (lane >> 3) & 1;
    const int l16 = (lane >> 4) & 1;
    const int n0 = blockIdx.x << 7;
    const int m0 = blockIdx.y << 7;

    float acc[2][8][4];
    #pragma unroll
    for (int i = 0; i < 2; i++)
        #pragma unroll
        for (int j = 0; j < 8; j++)
            #pragma unroll
            for (int p = 0; p < 4; p++) acc[i][j][p] = 0.f;

    // 3 tiles x 128 rows x 4 segs = 1536 16B units; 6 per thread
    auto issue = [&](int c, int s) {
        const int k0e = c << 5;
        #pragma unroll
        for (int it = 0; it < 6; ++it) {
            int idx  = it * 256 + tid;
            int tile = idx >> 9;               // 0:A 1:Bh 2:Bl
            int r    = (idx >> 2) & 127;
            int cc   = idx & 3;
            const __half* src;
            if      (tile == 0) src = A  + (size_t)(m0 + r) * DMOD + k0e + cc * 8;
            else if (tile == 1) src = Bh + (size_t)(n0 + r) * DMOD + k0e + cc * 8;
            else                src = Bl + (size_t)(n0 + r) * DMOD + k0e + cc * 8;
            uint32_t dst = smemu + s * GT_STAGE + tile * GT_TILE + r * GT_RSB + cc * 16;
            cp_async16(dst, src);
        }
    };

    issue(0, 0);
    asm volatile("cp.async.commit_group;" ::: "memory");
    issue(1, 1);
    asm volatile("cp.async.commit_group;" ::: "memory");

    for (int c = 0; c < GT_KCH; ++c) {
        asm volatile("cp.async.wait_group 1;" ::: "memory");
        __syncthreads();

        const uint32_t stg = smemu + (c % 3) * GT_STAGE;
        #pragma unroll
        for (int ks = 0; ks < 2; ++ks) {
            const uint32_t kb = ks * 32 + l16 * 16;
            uint32_t a[2][4];
            #pragma unroll
            for (int i = 0; i < 2; ++i) {
                uint32_t aadr = stg + (warp_m * 32 + i * 16 + l8 * 8 + li) * GT_RSB + kb;
                ldsm_x4(a[i][0], a[i][1], a[i][2], a[i][3], aadr);
            }
            #pragma unroll
            for (int j = 0; j < 8; ++j) {
                // x4: lanes 0-15 -> Bh (bh0,bh1); lanes 16-31 -> Bl (bl0,bl1)
                uint32_t badr = stg + (1 + l16) * GT_TILE +
                                (warp_n * 64 + j * 8 + li) * GT_RSB +
                                ks * 32 + l8 * 16;
                uint32_t bh0, bh1, bl0, bl1;
                ldsm_x4(bh0, bh1, bl0, bl1, badr);
                #pragma unroll
                for (int i = 0; i < 2; ++i) {
                    mma_f16(acc[i][j], a[i][0], a[i][1], a[i][2], a[i][3], bl0, bl1);
                    mma_f16(acc[i][j], a[i][0], a[i][1], a[i][2], a[i][3], bh0, bh1);
                }
            }
        }

        if (c + 2 < GT_KCH) issue(c + 2, (c + 2) % 3);
        asm volatile("cp.async.commit_group;" ::: "memory");
    }

    #pragma unroll
    for (int j = 0; j < 8; ++j) {
        int col = n0 + warp_n * 64 + j * 8 + kq * 2;
        float b0 = bias[col], b1 = bias[col + 1];
        #pragma unroll
        for (int i = 0; i < 2; ++i) {
            int row = m0 + warp_m * 32 + i * 16 + r4;
            float y0 = acc[i][j][0] + b0, y1 = acc[i][j][1] + b1;
            float y2 = acc[i][j][2] + b0, y3 = acc[i][j][3] + b1;
            if (OUT == 0) {
                *(float2*)&C[(size_t)row * DMOD + col]       = make_float2(y0, y1);
                *(float2*)&C[(size_t)(row + 8) * DMOD + col] = make_float2(y2, y3);
            } else {
                y0 *= oscale; y1 *= oscale; y2 *= oscale; y3 *= oscale;
                __half h0 = __float2half_rn(y0), h1 = __float2half_rn(y1);
                __half h2 = __float2half_rn(y2), h3 = __float2half_rn(y3);
                __half2 H0 = __halves2half2(h0, h1), H1 = __halves2half2(h2, h3);
                *(__half2*)&Yh[(size_t)row * DMOD + col]       = H0;
                *(__half2*)&Yh[(size_t)(row + 8) * DMOD + col] = H1;
                if (Yl != nullptr) {
                    __half e0 = __float2half_rn(y0 - __half2float(h0));
                    __half e1 = __float2half_rn(y1 - __half2float(h1));
                    __half e2 = __float2half_rn(y2 - __half2float(h2));
                    __half e3 = __float2half_rn(y3 - __half2float(h3));
                    __half2 L0 = __halves2half2(e0, e1), L1 = __halves2half2(e2, e3);
                    *(__half2*)&Yl[(size_t)row * DMOD + col]       = L0;
                    *(__half2*)&Yl[(size_t)(row + 8) * DMOD + col] = L1;
                }
            }
        }
    }
}

// ---------------------------------------------------------------------------
// Flash attention: fp16 mma + ldmatrix. CTA: one (b,h), 128 q rows; 8 warps,
// each owns 16 full rows. QK^T single product fp16 (Q- and K-lo dropped);
// P fp16; V fp16. Output fp16 single plane. K/V double-buffered cp.async.
// ---------------------------------------------------------------------------
#define FL_RSQ  272                   // 128 halves*2B + 16B pad
#define FL_RSV  144                   // 64 halves*2B + 16B pad
#define FL_QHS  0                     // Q: 34816
#define FL_K0   34816                 // K double buf: 2*17408
#define FL_V0   69632                 // V double buf: 2*18432
#define FL_SMEM 106496

__global__ __launch_bounds__(256, 1)
void flash_mma_kernel(const __half* __restrict__ Qh,
                      const __half* __restrict__ Kh,
                      const __half* __restrict__ Vh,
                      __half* __restrict__ O16)
{
    extern __shared__ char smem[];
    const uint32_t su = smem_to_u32(smem);
    const int tid  = threadIdx.x;
    const int lane = tid & 31;
    const int wid  = tid >> 5;
    const int r4 = lane >> 2, kq = lane & 3;
    const int li  = lane & 7;
    const int l8  = (lane >> 3) & 1;
    const int l16 = (lane >> 4) & 1;
    const int q0 = blockIdx.x << 7;
    const int h  = blockIdx.y, b = blockIdx.z;
    const size_t qkbase = (size_t)b * SEQ * DMOD + (size_t)h * DKH;
    const size_t vtbase = ((size_t)b * NHEAD + h) * DKH * SEQ;

    auto load_kv = [&](int t, int st) {
        const int n0 = t << 6;
        const uint32_t kd = su + FL_K0 + st * 17408;
        const uint32_t vd = su + FL_V0 + st * 18432;
        #pragma unroll
        for (int u = 0; u < 4; u++) {
            int idx = u * 256 + tid;
            int r = idx >> 4, sg = idx & 15;
            cp_async16(kd + r * FL_RSQ + sg * 16,
                       Kh + qkbase + (size_t)(n0 + r) * DMOD + sg * 8);
        }
        #pragma unroll
        for (int u = 0; u < 4; u++) {
            int idx = u * 256 + tid;
            int r = idx >> 3, sg = idx & 7;
            cp_async16(vd + r * FL_RSV + sg * 16,
                       Vh + vtbase + (size_t)r * SEQ + n0 + sg * 8);
        }
    };

    #pragma unroll
    for (int u = 0; u < 8; u++) {
        int idx = u * 256 + tid;
        int r = idx >> 4, sg = idx & 15;
        cp_async16(su + FL_QHS + r * FL_RSQ + sg * 16,
                   Qh + qkbase + (size_t)(q0 + r) * DMOD + sg * 8);
    }
    asm volatile("cp.async.commit_group;" ::: "memory");
    load_kv(0, 0);
    asm volatile("cp.async.commit_group;" ::: "memory");
    asm volatile("cp.async.wait_group 0;" ::: "memory");
    __syncthreads();

    const uint32_t qrowoff = (wid * 16 + l8 * 8 + li) * FL_RSQ + l16 * 16;
    uint32_t aqh[8][4];
    #pragma unroll
    for (int k = 0; k < 8; k++)
        ldsm_x4(aqh[k][0], aqh[k][1], aqh[k][2], aqh[k][3],
                su + FL_QHS + qrowoff + k * 32);

    float oc[16][4];
    #pragma unroll
    for (int nf = 0; nf < 16; nf++)
        #pragma unroll
        for (int p = 0; p < 4; p++) oc[nf][p] = 0.f;
    float m0 = -1e30f, m1 = -1e30f, l0 = 0.f, l1 = 0.f;

    for (int t = 0; t < 32; t++) {
        const int st = t & 1;
        const uint32_t ks = su + FL_K0 + st * 17408;
        const uint32_t vs = su + FL_V0 + st * 18432;

        if (t + 1 < 32) {
            load_kv(t + 1, st ^ 1);
            asm volatile("cp.async.commit_group;" ::: "memory");
        }

        // S = Q @ K^T (single fp16 product; x4 serves two nf tiles)
        float sc[8][4];
        #pragma unroll
        for (int nf = 0; nf < 8; nf++)
            #pragma unroll
            for (int p = 0; p < 4; p++) sc[nf][p] = 0.f;

        #pragma unroll
        for (int k = 0; k < 8; k++) {
            #pragma unroll
            for (int nf = 0; nf < 8; nf += 2) {
                uint32_t kadr = ks + (nf * 8 + l16 * 8 + li) * FL_RSQ +
                                l8 * 16 + k * 32;
                uint32_t k0, k1, k2, k3;
                ldsm_x4(k0, k1, k2, k3, kadr);
                mma_f16(sc[nf],     aqh[k][0], aqh[k][1], aqh[k][2], aqh[k][3], k0, k1);
                mma_f16(sc[nf + 1], aqh[k][0], aqh[k][1], aqh[k][2], aqh[k][3], k2, k3);
            }
        }

        // online softmax — rows r4 / r4+8, full 64-col row in this warp
        float mx0 = -1e30f, mx1 = -1e30f;
        #pragma unroll
        for (int nf = 0; nf < 8; nf++) {
            mx0 = fmaxf(mx0, fmaxf(sc[nf][0], sc[nf][1]));
            mx1 = fmaxf(mx1, fmaxf(sc[nf][2], sc[nf][3]));
        }
        mx0 = fmaxf(mx0, __shfl_xor_sync(0xffffffffu, mx0, 1));
        mx0 = fmaxf(mx0, __shfl_xor_sync(0xffffffffu, mx0, 2));
        mx1 = fmaxf(mx1, __shfl_xor_sync(0xffffffffu, mx1, 1));
        mx1 = fmaxf(mx1, __shfl_xor_sync(0xffffffffu, mx1, 2));

        const float mn0 = fmaxf(m0, mx0), mn1 = fmaxf(m1, mx1);
        const float c0 = __expf(m0 - mn0), c1 = __expf(m1 - mn1);
        float s0 = 0.f, s1 = 0.f;
        uint32_t pa[4][4];    // P as A-frags (c-frag == A-frag layout)
        #pragma unroll
        for (int nf = 0; nf < 8; nf++) {
            float p0 = __expf(sc[nf][0] - mn0);
            float p1 = __expf(sc[nf][1] - mn0);
            float p2 = __expf(sc[nf][2] - mn1);
            float p3 = __expf(sc[nf][3] - mn1);
            s0 += p0 + p1; s1 += p2 + p3;
            __half2 hA = __floats2half2_rn(p0, p1);
            __half2 hB = __floats2half2_rn(p2, p3);
            pa[nf >> 1][(nf & 1) ? 2 : 0] = *(uint32_t*)&hA;
            pa[nf >> 1][(nf & 1) ? 3 : 1] = *(uint32_t*)&hB;
        }
        s0 += __shfl_xor_sync(0xffffffffu, s0, 1);
        s0 += __shfl_xor_sync(0xffffffffu, s0, 2);
        s1 += __shfl_xor_sync(0xffffffffu, s1, 1);
        s1 += __shfl_xor_sync(0xffffffffu, s1, 2);
        l0 = l0 * c0 + s0; m0 = mn0;
        l1 = l1 * c1 + s1; m1 = mn1;
        #pragma unroll
        for (int nf = 0; nf < 16; nf++) {
            oc[nf][0] *= c0; oc[nf][1] *= c0;
            oc[nf][2] *= c1; oc[nf][3] *= c1;
        }

        // O += P @ V (x4 serves two nf tiles)
        #pragma unroll
        for (int k = 0; k < 4; k++) {
            #pragma unroll
            for (int nf = 0; nf < 16; nf += 2) {
                uint32_t vadr = vs + (nf * 8 + l16 * 8 + li) * FL_RSV +
                                k * 32 + l8 * 16;
                uint32_t v0, v1, v2, v3;
                ldsm_x4(v0, v1, v2, v3, vadr);
                mma_f16(oc[nf],     pa[k][0], pa[k][1], pa[k][2], pa[k][3], v0, v1);
                mma_f16(oc[nf + 1], pa[k][0], pa[k][1], pa[k][2], pa[k][3], v2, v3);
            }
        }

        if (t + 1 < 32) {
            asm volatile("cp.async.wait_group 0;" ::: "memory");
            __syncthreads();
        }
    }

    // epilogue: normalize, fp16 single plane -> final-GEMM A operand
    const float inv0 = 1.f / l0, inv1 = 1.f / l1;
    #pragma unroll
    for (int nf = 0; nf < 16; nf++) {
        int col  = nf * 8 + kq * 2;
        int row0 = q0 + wid * 16 + r4;
        __half2 H0 = __floats2half2_rn(oc[nf][0] * inv0, oc[nf][1] * inv0);
        __half2 H1 = __floats2half2_rn(oc[nf][2] * inv1, oc[nf][3] * inv1);
        *(__half2*)&O16[qkbase + (size_t)row0 * DMOD + col]       = H0;
        *(__half2*)&O16[qkbase + (size_t)(row0 + 8) * DMOD + col] = H1;
    }
}

// ---------------------------------------------------------------------------
// Launch
// ---------------------------------------------------------------------------
extern "C" void kernel_launch(void* const* d_in, const int* in_sizes, int n_in,
                              void* d_out, int out_size)
{
    const float* q  = (const float*)d_in[0];
    const float* k  = (const float*)d_in[1];
    const float* v  = (const float*)d_in[2];
    const float* Wq = (const float*)d_in[3];
    const float* bq = (const float*)d_in[4];
    const float* Wk = (const float*)d_in[5];
    const float* bk = (const float*)d_in[6];
    const float* Wv = (const float*)d_in[7];
    const float* bv = (const float*)d_in[8];
    const float* Wo = (const float*)d_in[9];
    const float* bo = (const float*)d_in[10];
    float* out = (float*)d_out;

    __half *A16, *Wth, *Wtl, *Qh, *Kh, *V16, *Vth, *O16;
    cudaGetSymbolAddress((void**)&A16, g_A16);
    cudaGetSymbolAddress((void**)&Wth, g_Wth);
    cudaGetSymbolAddress((void**)&Wtl, g_Wtl);
    cudaGetSymbolAddress((void**)&Qh,  g_Qh);
    cudaGetSymbolAddress((void**)&Kh,  g_Kh16);
    cudaGetSymbolAddress((void**)&V16, g_V16);
    cudaGetSymbolAddress((void**)&Vth, g_Vth);
    cudaGetSymbolAddress((void**)&O16, g_O16);

    cudaFuncSetAttribute(gemm_mma_kernel<0>,
                         cudaFuncAttributeMaxDynamicSharedMemorySize, GT_SMEM);
    cudaFuncSetAttribute(gemm_mma_kernel<1>,
                         cudaFuncAttributeMaxDynamicSharedMemorySize, GT_SMEM);
    cudaFuncSetAttribute(flash_mma_kernel,
                         cudaFuncAttributeMaxDynamicSharedMemorySize, FL_SMEM);

    const dim3 gt(DMOD / 32, DMOD / 32);          // W transpose grid
    const dim3 gg(DMOD / 128, TOK / 128);         // gemm grid (16, 32)
    const int  ga = (TOK * DMOD) / (256 * 8);     // elementwise grids
    const float scale = 0.08838834764831845f;     // 1/sqrt(128)

    // Q projection -> fp16 (pre-scaled)
    h16_kernel<<<ga, 256>>>(q, A16);
    wsplit_t_kernel<<<gt, 256>>>(Wq, Wth, Wtl);
    gemm_mma_kernel<1><<<gg, 256, GT_SMEM>>>(A16, Wth, Wtl, bq,
                                             nullptr, Qh, nullptr, scale);

    // K projection -> fp16 single plane
    h16_kernel<<<ga, 256>>>(k, A16);
    wsplit_t_kernel<<<gt, 256>>>(Wk, Wth, Wtl);
    gemm_mma_kernel<1><<<gg, 256, GT_SMEM>>>(A16, Wth, Wtl, bk,
                                             nullptr, Kh, nullptr, 1.0f);

    // V projection -> fp16, then per-head transpose
    h16_kernel<<<ga, 256>>>(v, A16);
    wsplit_t_kernel<<<gt, 256>>>(Wv, Wth, Wtl);
    gemm_mma_kernel<1><<<gg, 256, GT_SMEM>>>(A16, Wth, Wtl, bv,
                                             nullptr, V16, nullptr, 1.0f);
    vtrans_kernel<<<dim3(SEQ / 32, DKH / 32, 2 * NHEAD), 256>>>(V16, Vth);

    // attention -> fp16 directly into final-GEMM A operand
    flash_mma_kernel<<<dim3(SEQ / 128, NHEAD, 2), 256, FL_SMEM>>>(
        Qh, Kh, Vth, O16);

    // output projection
    wsplit_t_kernel<<<gt, 256>>>(Wo, Wth, Wtl);
    gemm_mma_kernel<0><<<gg, 256, GT_SMEM>>>(O16, Wth, Wtl, bo,
                                             out, nullptr, nullptr, 1.0f);
}

// round 12
// speedup vs baseline: 7.2915x; 1.6774x over previous
#include <cuda_runtime.h>
#include <cuda_bf16.h>
#include <cuda_fp16.h>
#include <cstdint>

#define TOK   4096      // B*S tokens
#define DMOD  2048      // model dim
#define SEQ   2048      // sequence length
#define NHEAD 16
#define DKH   128       // head dim

// Scratch (device globals: allocation-free per harness rules)
__device__ __half g_A16[(size_t)TOK * DMOD];    // GEMM A operand fp16
__device__ __half g_Wt16[(size_t)DMOD * DMOD];  // W^T fp16, [N][K]
__device__ __half g_Qh[(size_t)TOK * DMOD];     // Q*scale fp16
__device__ __half g_Kh16[(size_t)TOK * DMOD];   // K fp16
__device__ __half g_V16[(size_t)TOK * DMOD];    // V proj fp16 [b,s,d]
__device__ __half g_Vth[(size_t)TOK * DMOD];    // V^T fp16 [b,h,d,s]
__device__ __half g_O16[(size_t)TOK * DMOD];    // attention output fp16

// ---------------------------------------------------------------------------
// helpers
// ---------------------------------------------------------------------------
__device__ __forceinline__ uint32_t smem_to_u32(const void* p) {
    uint32_t a;
    asm("{ .reg .u64 t; cvta.to.shared.u64 t, %1; cvt.u32.u64 %0, t; }"
        : "=r"(a) : "l"(p));
    return a;
}

__device__ __forceinline__ void cp_async16(uint32_t dst, const void* src) {
    asm volatile("cp.async.cg.shared.global [%0], [%1], 16;"
                 :: "r"(dst), "l"(src));
}

__device__ __forceinline__ void ldsm_x4(uint32_t& r0, uint32_t& r1,
                                        uint32_t& r2, uint32_t& r3, uint32_t addr) {
    asm volatile("ldmatrix.sync.aligned.m8n8.x4.shared.b16 {%0,%1,%2,%3}, [%4];"
                 : "=r"(r0), "=r"(r1), "=r"(r2), "=r"(r3) : "r"(addr));
}

__device__ __forceinline__ void mma_f16(float* c,
    uint32_t a0, uint32_t a1, uint32_t a2, uint32_t a3,
    uint32_t b0, uint32_t b1)
{
    asm volatile(
        "mma.sync.aligned.m16n8k16.row.col.f32.f16.f16.f32 "
        "{%0,%1,%2,%3}, {%4,%5,%6,%7}, {%8,%9}, {%0,%1,%2,%3};"
        : "+f"(c[0]), "+f"(c[1]), "+f"(c[2]), "+f"(c[3])
        : "r"(a0), "r"(a1), "r"(a2), "r"(a3), "r"(b0), "r"(b1));
}

// ---------------------------------------------------------------------------
// W transpose+convert: W[K][N] fp32 -> T[N][K] fp16
// ---------------------------------------------------------------------------
__global__ __launch_bounds__(256)
void wt_kernel(const float* __restrict__ W, __half* __restrict__ T)
{
    __shared__ float ts[32][33];
    const int tx = threadIdx.x & 31;
    const int ty = threadIdx.x >> 5;
    const int n0 = blockIdx.x * 32;
    const int k0 = blockIdx.y * 32;

    #pragma unroll
    for (int j = 0; j < 32; j += 8)
        ts[ty + j][tx] = W[(size_t)(k0 + ty + j) * DMOD + n0 + tx];
    __syncthreads();

    #pragma unroll
    for (int j = 0; j < 32; j += 8)
        T[(size_t)(n0 + ty + j) * DMOD + k0 + tx] =
            __float2half_rn(ts[tx][ty + j]);
}

// ---------------------------------------------------------------------------
// fp32 -> fp16 elementwise (8/thread)
// ---------------------------------------------------------------------------
__global__ __launch_bounds__(256)
void h16_kernel(const float* __restrict__ X, __half* __restrict__ Y)
{
    size_t i = ((size_t)blockIdx.x * 256 + threadIdx.x) * 8;
    float4 f0 = *(const float4*)(X + i);
    float4 f1 = *(const float4*)(X + i + 4);
    __half2 h0 = __floats2half2_rn(f0.x, f0.y);
    __half2 h1 = __floats2half2_rn(f0.z, f0.w);
    __half2 h2 = __floats2half2_rn(f1.x, f1.y);
    __half2 h3 = __floats2half2_rn(f1.z, f1.w);
    *(uint4*)(Y + i) = make_uint4(*(uint32_t*)&h0, *(uint32_t*)&h1,
                                  *(uint32_t*)&h2, *(uint32_t*)&h3);
}

// ---------------------------------------------------------------------------
// V transpose: V16 [b,s,h*128+d] fp16 -> Vth [(b*16+h)*128+d][s] fp16
// ---------------------------------------------------------------------------
__global__ __launch_bounds__(256)
void vtrans_kernel(const __half* __restrict__ Vp, __half* __restrict__ Vh)
{
    __shared__ float ts[32][33];
    const int tx = threadIdx.x & 31;
    const int ty = threadIdx.x >> 5;
    const int bh = blockIdx.z;
    const int b  = bh >> 4, h = bh & 15;
    const int s0 = blockIdx.x * 32;
    const int d0 = blockIdx.y * 32;

    #pragma unroll
    for (int j = 0; j < 32; j += 8)
        ts[ty + j][tx] = __half2float(
            Vp[((size_t)b * SEQ + s0 + ty + j) * DMOD + h * DKH + d0 + tx]);
    __syncthreads();

    #pragma unroll
    for (int j = 0; j < 32; j += 8)
        Vh[((size_t)bh * DKH + d0 + ty + j) * SEQ + s0 + tx] =
            __float2half_rn(ts[tx][ty + j]);
}

// ---------------------------------------------------------------------------
// fp16 mma GEMM, single product: C = A @ W + bias.
// A fp16 [M][K]; B fp16 [N][K]. CTA 128x128, BK=32, 3-stage cp.async,
// 8 warps (4Mx2N), ldmatrix loads, 2 CTAs/SM.
// OUT=0: fp32 C.   OUT=1: fp16 of (C+bias)*oscale.
// ---------------------------------------------------------------------------
#define GT_RSB    80
#define GT_TILE   (128 * GT_RSB)      // 10240
#define GT_STAGE  (2 * GT_TILE)       // 20480 (A, B)
#define GT_SMEM   (3 * GT_STAGE)      // 61440
#define GT_KCH    64

template<int OUT>
__global__ __launch_bounds__(256, 2)
void gemm_mma_kernel(const __half* __restrict__ A,
                     const __half* __restrict__ B,
                     const float* __restrict__ bias,
                     float* __restrict__ C,
                     __half* __restrict__ Yh,
                     float oscale)
{
    extern __shared__ char smem[];
    const uint32_t smemu = smem_to_u32(smem);
    const int tid    = threadIdx.x;
    const int lane   = tid & 31;
    const int wid    = tid >> 5;
    const int warp_m = wid & 3;
    const int warp_n = wid >> 2;
    const int r4     = lane >> 2;
    const int kq     = lane & 3;
    const int li  = lane & 7;
    const int l8  = (lane >> 3) & 1;
    const int l16 = (lane >> 4) & 1;
    const int n0 = blockIdx.x << 7;
    const int m0 = blockIdx.y << 7;

    float acc[2][8][4];
    #pragma unroll
    for (int i = 0; i < 2; i++)
        #pragma unroll
        for (int j = 0; j < 8; j++)
            #pragma unroll
            for (int p = 0; p < 4; p++) acc[i][j][p] = 0.f;

    // 2 tiles x 128 rows x 4 segs = 1024 16B units; 4 per thread
    auto issue = [&](int c, int s) {
        const int k0e = c << 5;
        #pragma unroll
        for (int it = 0; it < 4; ++it) {
            int idx  = it * 256 + tid;
            int tile = idx >> 9;               // 0:A 1:B
            int r    = (idx >> 2) & 127;
            int cc   = idx & 3;
            const __half* src = (tile == 0)
                ? A + (size_t)(m0 + r) * DMOD + k0e + cc * 8
                : B + (size_t)(n0 + r) * DMOD + k0e + cc * 8;
            uint32_t dst = smemu + s * GT_STAGE + tile * GT_TILE + r * GT_RSB + cc * 16;
            cp_async16(dst, src);
        }
    };

    issue(0, 0);
    asm volatile("cp.async.commit_group;" ::: "memory");
    issue(1, 1);
    asm volatile("cp.async.commit_group;" ::: "memory");

    for (int c = 0; c < GT_KCH; ++c) {
        asm volatile("cp.async.wait_group 1;" ::: "memory");
        __syncthreads();

        const uint32_t stg = smemu + (c % 3) * GT_STAGE;
        #pragma unroll
        for (int ks = 0; ks < 2; ++ks) {
            const uint32_t kb = ks * 32 + l16 * 16;
            uint32_t a[2][4];
            #pragma unroll
            for (int i = 0; i < 2; ++i) {
                uint32_t aadr = stg + (warp_m * 32 + i * 16 + l8 * 8 + li) * GT_RSB + kb;
                ldsm_x4(a[i][0], a[i][1], a[i][2], a[i][3], aadr);
            }
            #pragma unroll
            for (int j = 0; j < 8; j += 2) {
                // paired x4: matrices for n-tiles j (b0,b1) and j+1 (b2,b3)
                uint32_t badr = stg + GT_TILE +
                                (warp_n * 64 + j * 8 + l16 * 8 + li) * GT_RSB +
                                ks * 32 + l8 * 16;
                uint32_t b0, b1, b2, b3;
                ldsm_x4(b0, b1, b2, b3, badr);
                #pragma unroll
                for (int i = 0; i < 2; ++i) {
                    mma_f16(acc[i][j],     a[i][0], a[i][1], a[i][2], a[i][3], b0, b1);
                    mma_f16(acc[i][j + 1], a[i][0], a[i][1], a[i][2], a[i][3], b2, b3);
                }
            }
        }

        if (c + 2 < GT_KCH) issue(c + 2, (c + 2) % 3);
        asm volatile("cp.async.commit_group;" ::: "memory");
    }

    #pragma unroll
    for (int j = 0; j < 8; ++j) {
        int col = n0 + warp_n * 64 + j * 8 + kq * 2;
        float b0 = bias[col], b1 = bias[col + 1];
        #pragma unroll
        for (int i = 0; i < 2; ++i) {
            int row = m0 + warp_m * 32 + i * 16 + r4;
            float y0 = acc[i][j][0] + b0, y1 = acc[i][j][1] + b1;
            float y2 = acc[i][j][2] + b0, y3 = acc[i][j][3] + b1;
            if (OUT == 0) {
                *(float2*)&C[(size_t)row * DMOD + col]       = make_float2(y0, y1);
                *(float2*)&C[(size_t)(row + 8) * DMOD + col] = make_float2(y2, y3);
            } else {
                __half2 H0 = __floats2half2_rn(y0 * oscale, y1 * oscale);
                __half2 H1 = __floats2half2_rn(y2 * oscale, y3 * oscale);
                *(__half2*)&Yh[(size_t)row * DMOD + col]       = H0;
                *(__half2*)&Yh[(size_t)(row + 8) * DMOD + col] = H1;
            }
        }
    }
}

// ---------------------------------------------------------------------------
// Flash attention (unchanged from R10): fp16 mma + ldmatrix.
// CTA: one (b,h), 128 q rows; 8 warps, each owns 16 full rows.
// Single-product QK^T; P fp16; V fp16. Output fp16. K/V double-buffered.
// ---------------------------------------------------------------------------
#define FL_RSQ  272                   // 128 halves*2B + 16B pad
#define FL_RSV  144                   // 64 halves*2B + 16B pad
#define FL_QHS  0                     // Q: 34816
#define FL_K0   34816                 // K double buf: 2*17408
#define FL_V0   69632                 // V double buf: 2*18432
#define FL_SMEM 106496

__global__ __launch_bounds__(256, 1)
void flash_mma_kernel(const __half* __restrict__ Qh,
                      const __half* __restrict__ Kh,
                      const __half* __restrict__ Vh,
                      __half* __restrict__ O16)
{
    extern __shared__ char smem[];
    const uint32_t su = smem_to_u32(smem);
    const int tid  = threadIdx.x;
    const int lane = tid & 31;
    const int wid  = tid >> 5;
    const int r4 = lane >> 2, kq = lane & 3;
    const int li  = lane & 7;
    const int l8  = (lane >> 3) & 1;
    const int l16 = (lane >> 4) & 1;
    const int q0 = blockIdx.x << 7;
    const int h  = blockIdx.y, b = blockIdx.z;
    const size_t qkbase = (size_t)b * SEQ * DMOD + (size_t)h * DKH;
    const size_t vtbase = ((size_t)b * NHEAD + h) * DKH * SEQ;

    auto load_kv = [&](int t, int st) {
        const int n0 = t << 6;
        const uint32_t kd = su + FL_K0 + st * 17408;
        const uint32_t vd = su + FL_V0 + st * 18432;
        #pragma unroll
        for (int u = 0; u < 4; u++) {
            int idx = u * 256 + tid;
            int r = idx >> 4, sg = idx & 15;
            cp_async16(kd + r * FL_RSQ + sg * 16,
                       Kh + qkbase + (size_t)(n0 + r) * DMOD + sg * 8);
        }
        #pragma unroll
        for (int u = 0; u < 4; u++) {
            int idx = u * 256 + tid;
            int r = idx >> 3, sg = idx & 7;
            cp_async16(vd + r * FL_RSV + sg * 16,
                       Vh + vtbase + (size_t)r * SEQ + n0 + sg * 8);
        }
    };

    #pragma unroll
    for (int u = 0; u < 8; u++) {
        int idx = u * 256 + tid;
        int r = idx >> 4, sg = idx & 15;
        cp_async16(su + FL_QHS + r * FL_RSQ + sg * 16,
                   Qh + qkbase + (size_t)(q0 + r) * DMOD + sg * 8);
    }
    asm volatile("cp.async.commit_group;" ::: "memory");
    load_kv(0, 0);
    asm volatile("cp.async.commit_group;" ::: "memory");
    asm volatile("cp.async.wait_group 0;" ::: "memory");
    __syncthreads();

    const uint32_t qrowoff = (wid * 16 + l8 * 8 + li) * FL_RSQ + l16 * 16;
    uint32_t aqh[8][4];
    #pragma unroll
    for (int k = 0; k < 8; k++)
        ldsm_x4(aqh[k][0], aqh[k][1], aqh[k][2], aqh[k][3],
                su + FL_QHS + qrowoff + k * 32);

    float oc[16][4];
    #pragma unroll
    for (int nf = 0; nf < 16; nf++)
        #pragma unroll
        for (int p = 0; p < 4; p++) oc[nf][p] = 0.f;
    float m0 = -1e30f, m1 = -1e30f, l0 = 0.f, l1 = 0.f;

    for (int t = 0; t < 32; t++) {
        const int st = t & 1;
        const uint32_t ks = su + FL_K0 + st * 17408;
        const uint32_t vs = su + FL_V0 + st * 18432;

        if (t + 1 < 32) {
            load_kv(t + 1, st ^ 1);
            asm volatile("cp.async.commit_group;" ::: "memory");
        }

        float sc[8][4];
        #pragma unroll
        for (int nf = 0; nf < 8; nf++)
            #pragma unroll
            for (int p = 0; p < 4; p++) sc[nf][p] = 0.f;

        #pragma unroll
        for (int k = 0; k < 8; k++) {
            #pragma unroll
            for (int nf = 0; nf < 8; nf += 2) {
                uint32_t kadr = ks + (nf * 8 + l16 * 8 + li) * FL_RSQ +
                                l8 * 16 + k * 32;
                uint32_t k0, k1, k2, k3;
                ldsm_x4(k0, k1, k2, k3, kadr);
                mma_f16(sc[nf],     aqh[k][0], aqh[k][1], aqh[k][2], aqh[k][3], k0, k1);
                mma_f16(sc[nf + 1], aqh[k][0], aqh[k][1], aqh[k][2], aqh[k][3], k2, k3);
            }
        }

        float mx0 = -1e30f, mx1 = -1e30f;
        #pragma unroll
        for (int nf = 0; nf < 8; nf++) {
            mx0 = fmaxf(mx0, fmaxf(sc[nf][0], sc[nf][1]));
            mx1 = fmaxf(mx1, fmaxf(sc[nf][2], sc[nf][3]));
        }
        mx0 = fmaxf(mx0, __shfl_xor_sync(0xffffffffu, mx0, 1));
        mx0 = fmaxf(mx0, __shfl_xor_sync(0xffffffffu, mx0, 2));
        mx1 = fmaxf(mx1, __shfl_xor_sync(0xffffffffu, mx1, 1));
        mx1 = fmaxf(mx1, __shfl_xor_sync(0xffffffffu, mx1, 2));

        const float mn0 = fmaxf(m0, mx0), mn1 = fmaxf(m1, mx1);
        const float c0 = __expf(m0 - mn0), c1 = __expf(m1 - mn1);
        float s0 = 0.f, s1 = 0.f;
        uint32_t pa[4][4];
        #pragma unroll
        for (int nf = 0; nf < 8; nf++) {
            float p0 = __expf(sc[nf][0] - mn0);
            float p1 = __expf(sc[nf][1] - mn0);
            float p2 = __expf(sc[nf][2] - mn1);
            float p3 = __expf(sc[nf][3] - mn1);
            s0 += p0 + p1; s1 += p2 + p3;
            __half2 hA = __floats2half2_rn(p0, p1);
            __half2 hB = __floats2half2_rn(p2, p3);
            pa[nf >> 1][(nf & 1) ? 2 : 0] = *(uint32_t*)&hA;
            pa[nf >> 1][(nf & 1) ? 3 : 1] = *(uint32_t*)&hB;
        }
        s0 += __shfl_xor_sync(0xffffffffu, s0, 1);
        s0 += __shfl_xor_sync(0xffffffffu, s0, 2);
        s1 += __shfl_xor_sync(0xffffffffu, s1, 1);
        s1 += __shfl_xor_sync(0xffffffffu, s1, 2);
        l0 = l0 * c0 + s0; m0 = mn0;
        l1 = l1 * c1 + s1; m1 = mn1;
        #pragma unroll
        for (int nf = 0; nf < 16; nf++) {
            oc[nf][0] *= c0; oc[nf][1] *= c0;
            oc[nf][2] *= c1; oc[nf][3] *= c1;
        }

        #pragma unroll
        for (int k = 0; k < 4; k++) {
            #pragma unroll
            for (int nf = 0; nf < 16; nf += 2) {
                uint32_t vadr = vs + (nf * 8 + l16 * 8 + li) * FL_RSV +
                                k * 32 + l8 * 16;
                uint32_t v0, v1, v2, v3;
                ldsm_x4(v0, v1, v2, v3, vadr);
                mma_f16(oc[nf],     pa[k][0], pa[k][1], pa[k][2], pa[k][3], v0, v1);
                mma_f16(oc[nf + 1], pa[k][0], pa[k][1], pa[k][2], pa[k][3], v2, v3);
            }
        }

        if (t + 1 < 32) {
            asm volatile("cp.async.wait_group 0;" ::: "memory");
            __syncthreads();
        }
    }

    const float inv0 = 1.f / l0, inv1 = 1.f / l1;
    #pragma unroll
    for (int nf = 0; nf < 16; nf++) {
        int col  = nf * 8 + kq * 2;
        int row0 = q0 + wid * 16 + r4;
        __half2 H0 = __floats2half2_rn(oc[nf][0] * inv0, oc[nf][1] * inv0);
        __half2 H1 = __floats2half2_rn(oc[nf][2] * inv1, oc[nf][3] * inv1);
        *(__half2*)&O16[qkbase + (size_t)row0 * DMOD + col]       = H0;
        *(__half2*)&O16[qkbase + (size_t)(row0 + 8) * DMOD + col] = H1;
    }
}

// ---------------------------------------------------------------------------
// Launch
// ---------------------------------------------------------------------------
extern "C" void kernel_launch(void* const* d_in, const int* in_sizes, int n_in,
                              void* d_out, int out_size)
{
    const float* q  = (const float*)d_in[0];
    const float* k  = (const float*)d_in[1];
    const float* v  = (const float*)d_in[2];
    const float* Wq = (const float*)d_in[3];
    const float* bq = (const float*)d_in[4];
    const float* Wk = (const float*)d_in[5];
    const float* bk = (const float*)d_in[6];
    const float* Wv = (const float*)d_in[7];
    const float* bv = (const float*)d_in[8];
    const float* Wo = (const float*)d_in[9];
    const float* bo = (const float*)d_in[10];
    float* out = (float*)d_out;

    __half *A16, *Wt16, *Qh, *Kh, *V16, *Vth, *O16;
    cudaGetSymbolAddress((void**)&A16,  g_A16);
    cudaGetSymbolAddress((void**)&Wt16, g_Wt16);
    cudaGetSymbolAddress((void**)&Qh,   g_Qh);
    cudaGetSymbolAddress((void**)&Kh,   g_Kh16);
    cudaGetSymbolAddress((void**)&V16,  g_V16);
    cudaGetSymbolAddress((void**)&Vth,  g_Vth);
    cudaGetSymbolAddress((void**)&O16,  g_O16);

    cudaFuncSetAttribute(gemm_mma_kernel<0>,
                         cudaFuncAttributeMaxDynamicSharedMemorySize, GT_SMEM);
    cudaFuncSetAttribute(gemm_mma_kernel<1>,
                         cudaFuncAttributeMaxDynamicSharedMemorySize, GT_SMEM);
    cudaFuncSetAttribute(flash_mma_kernel,
                         cudaFuncAttributeMaxDynamicSharedMemorySize, FL_SMEM);

    const dim3 gt(DMOD / 32, DMOD / 32);          // W transpose grid
    const dim3 gg(DMOD / 128, TOK / 128);         // gemm grid (16, 32)
    const int  ga = (TOK * DMOD) / (256 * 8);     // elementwise grids
    const float scale = 0.08838834764831845f;     // 1/sqrt(128)

    // Q projection -> fp16 (pre-scaled)
    h16_kernel<<<ga, 256>>>(q, A16);
    wt_kernel<<<gt, 256>>>(Wq, Wt16);
    gemm_mma_kernel<1><<<gg, 256, GT_SMEM>>>(A16, Wt16, bq, nullptr, Qh, scale);

    // K projection -> fp16
    h16_kernel<<<ga, 256>>>(k, A16);
    wt_kernel<<<gt, 256>>>(Wk, Wt16);
    gemm_mma_kernel<1><<<gg, 256, GT_SMEM>>>(A16, Wt16, bk, nullptr, Kh, 1.0f);

    // V projection -> fp16, then per-head transpose
    h16_kernel<<<ga, 256>>>(v, A16);
    wt_kernel<<<gt, 256>>>(Wv, Wt16);
    gemm_mma_kernel<1><<<gg, 256, GT_SMEM>>>(A16, Wt16, bv, nullptr, V16, 1.0f);
    vtrans_kernel<<<dim3(SEQ / 32, DKH / 32, 2 * NHEAD), 256>>>(V16, Vth);

    // attention -> fp16 directly into final-GEMM A operand
    flash_mma_kernel<<<dim3(SEQ / 128, NHEAD, 2), 256, FL_SMEM>>>(
        Qh, Kh, Vth, O16);

    // output projection (fp32 out)
    wt_kernel<<<gt, 256>>>(Wo, Wt16);
    gemm_mma_kernel<0><<<gg, 256, GT_SMEM>>>(O16, Wt16, bo, out, nullptr, 1.0f);
}

// round 13
// speedup vs baseline: 7.5569x; 1.0364x over previous
#include <cuda_runtime.h>
#include <cuda_bf16.h>
#include <cuda_fp16.h>
#include <cstdint>

#define TOK   4096      // B*S tokens
#define DMOD  2048      // model dim
#define SEQ   2048      // sequence length
#define NHEAD 16
#define DKH   128       // head dim

// Scratch (device globals: allocation-free per harness rules)
__device__ __half g_A16[(size_t)TOK * DMOD];    // GEMM A operand fp16
__device__ __half g_Wt16[(size_t)DMOD * DMOD];  // W^T fp16, [N][K]
__device__ __half g_Qh[(size_t)TOK * DMOD];     // Q*scale fp16
__device__ __half g_Kh16[(size_t)TOK * DMOD];   // K fp16
__device__ __half g_V16[(size_t)TOK * DMOD];    // V proj fp16 [b,s,d]
__device__ __half g_Vth[(size_t)TOK * DMOD];    // V^T fp16 [b,h,d,s]
__device__ __half g_O16[(size_t)TOK * DMOD];    // attention output fp16

// ---------------------------------------------------------------------------
// helpers
// ---------------------------------------------------------------------------
__device__ __forceinline__ uint32_t smem_to_u32(const void* p) {
    uint32_t a;
    asm("{ .reg .u64 t; cvta.to.shared.u64 t, %1; cvt.u32.u64 %0, t; }"
        : "=r"(a) : "l"(p));
    return a;
}

__device__ __forceinline__ void cp_async16(uint32_t dst, const void* src) {
    asm volatile("cp.async.cg.shared.global [%0], [%1], 16;"
                 :: "r"(dst), "l"(src));
}

__device__ __forceinline__ void ldsm_x4(uint32_t& r0, uint32_t& r1,
                                        uint32_t& r2, uint32_t& r3, uint32_t addr) {
    asm volatile("ldmatrix.sync.aligned.m8n8.x4.shared.b16 {%0,%1,%2,%3}, [%4];"
                 : "=r"(r0), "=r"(r1), "=r"(r2), "=r"(r3) : "r"(addr));
}

__device__ __forceinline__ void mma_f16(float* c,
    uint32_t a0, uint32_t a1, uint32_t a2, uint32_t a3,
    uint32_t b0, uint32_t b1)
{
    asm volatile(
        "mma.sync.aligned.m16n8k16.row.col.f32.f16.f16.f32 "
        "{%0,%1,%2,%3}, {%4,%5,%6,%7}, {%8,%9}, {%0,%1,%2,%3};"
        : "+f"(c[0]), "+f"(c[1]), "+f"(c[2]), "+f"(c[3])
        : "r"(a0), "r"(a1), "r"(a2), "r"(a3), "r"(b0), "r"(b1));
}

// ---------------------------------------------------------------------------
// W transpose+convert: W[K][N] fp32 -> T[N][K] fp16
// ---------------------------------------------------------------------------
__global__ __launch_bounds__(256)
void wt_kernel(const float* __restrict__ W, __half* __restrict__ T)
{
    __shared__ float ts[32][33];
    const int tx = threadIdx.x & 31;
    const int ty = threadIdx.x >> 5;
    const int n0 = blockIdx.x * 32;
    const int k0 = blockIdx.y * 32;

    #pragma unroll
    for (int j = 0; j < 32; j += 8)
        ts[ty + j][tx] = W[(size_t)(k0 + ty + j) * DMOD + n0 + tx];
    __syncthreads();

    #pragma unroll
    for (int j = 0; j < 32; j += 8)
        T[(size_t)(n0 + ty + j) * DMOD + k0 + tx] =
            __float2half_rn(ts[tx][ty + j]);
}

// ---------------------------------------------------------------------------
// fp32 -> fp16 elementwise (8/thread)
// ---------------------------------------------------------------------------
__global__ __launch_bounds__(256)
void h16_kernel(const float* __restrict__ X, __half* __restrict__ Y)
{
    size_t i = ((size_t)blockIdx.x * 256 + threadIdx.x) * 8;
    float4 f0 = *(const float4*)(X + i);
    float4 f1 = *(const float4*)(X + i + 4);
    __half2 h0 = __floats2half2_rn(f0.x, f0.y);
    __half2 h1 = __floats2half2_rn(f0.z, f0.w);
    __half2 h2 = __floats2half2_rn(f1.x, f1.y);
    __half2 h3 = __floats2half2_rn(f1.z, f1.w);
    *(uint4*)(Y + i) = make_uint4(*(uint32_t*)&h0, *(uint32_t*)&h1,
                                  *(uint32_t*)&h2, *(uint32_t*)&h3);
}

// ---------------------------------------------------------------------------
// V transpose: V16 [b,s,h*128+d] fp16 -> Vth [(b*16+h)*128+d][s] fp16
// ---------------------------------------------------------------------------
__global__ __launch_bounds__(256)
void vtrans_kernel(const __half* __restrict__ Vp, __half* __restrict__ Vh)
{
    __shared__ float ts[32][33];
    const int tx = threadIdx.x & 31;
    const int ty = threadIdx.x >> 5;
    const int bh = blockIdx.z;
    const int b  = bh >> 4, h = bh & 15;
    const int s0 = blockIdx.x * 32;
    const int d0 = blockIdx.y * 32;

    #pragma unroll
    for (int j = 0; j < 32; j += 8)
        ts[ty + j][tx] = __half2float(
            Vp[((size_t)b * SEQ + s0 + ty + j) * DMOD + h * DKH + d0 + tx]);
    __syncthreads();

    #pragma unroll
    for (int j = 0; j < 32; j += 8)
        Vh[((size_t)bh * DKH + d0 + ty + j) * SEQ + s0 + tx] =
            __float2half_rn(ts[tx][ty + j]);
}

// ---------------------------------------------------------------------------
// fp16 mma GEMM, single product: C = A @ W + bias.
// A fp16 [M][K]; B fp16 [N][K]. CTA tile 256x128, BK=32, 3-stage cp.async,
// 512 threads = 16 warps (8Mx2N), warp tile 32x64, ldmatrix loads.
// OUT=0: fp32 C.   OUT=1: fp16 of (C+bias)*oscale.
// ---------------------------------------------------------------------------
#define GT_RSB    80
#define GT_ATILE  (256 * GT_RSB)      // 20480
#define GT_BTILE  (128 * GT_RSB)      // 10240
#define GT_STAGE  (GT_ATILE + GT_BTILE)   // 30720
#define GT_SMEM   (3 * GT_STAGE)      // 92160
#define GT_KCH    64

template<int OUT>
__global__ __launch_bounds__(512, 1)
void gemm_mma_kernel(const __half* __restrict__ A,
                     const __half* __restrict__ B,
                     const float* __restrict__ bias,
                     float* __restrict__ C,
                     __half* __restrict__ Yh,
                     float oscale)
{
    extern __shared__ char smem[];
    const uint32_t smemu = smem_to_u32(smem);
    const int tid    = threadIdx.x;
    const int lane   = tid & 31;
    const int wid    = tid >> 5;
    const int warp_m = wid & 7;       // 8 m-warps: rows warp_m*32..+31
    const int warp_n = wid >> 3;      // 2 n-warps: cols warp_n*64..+63
    const int r4     = lane >> 2;
    const int kq     = lane & 3;
    const int li  = lane & 7;
    const int l8  = (lane >> 3) & 1;
    const int l16 = (lane >> 4) & 1;
    const int n0 = blockIdx.x << 7;   // 128-wide n tile
    const int m0 = blockIdx.y << 8;   // 256-wide m tile

    float acc[2][8][4];
    #pragma unroll
    for (int i = 0; i < 2; i++)
        #pragma unroll
        for (int j = 0; j < 8; j++)
            #pragma unroll
            for (int p = 0; p < 4; p++) acc[i][j][p] = 0.f;

    // A: 256 rows x 4 segs = 1024 units; B: 128 x 4 = 512 units; 3/thread
    auto issue = [&](int c, int s) {
        const int k0e = c << 5;
        #pragma unroll
        for (int it = 0; it < 3; ++it) {
            int idx = it * 512 + tid;          // 0..1535
            const __half* src;
            uint32_t dst;
            if (idx < 1024) {                  // A tile
                int r  = idx >> 2;
                int cc = idx & 3;
                src = A + (size_t)(m0 + r) * DMOD + k0e + cc * 8;
                dst = smemu + s * GT_STAGE + r * GT_RSB + cc * 16;
            } else {                           // B tile
                int u  = idx - 1024;
                int r  = u >> 2;
                int cc = u & 3;
                src = B + (size_t)(n0 + r) * DMOD + k0e + cc * 8;
                dst = smemu + s * GT_STAGE + GT_ATILE + r * GT_RSB + cc * 16;
            }
            cp_async16(dst, src);
        }
    };

    issue(0, 0);
    asm volatile("cp.async.commit_group;" ::: "memory");
    issue(1, 1);
    asm volatile("cp.async.commit_group;" ::: "memory");

    for (int c = 0; c < GT_KCH; ++c) {
        asm volatile("cp.async.wait_group 1;" ::: "memory");
        __syncthreads();

        const uint32_t stg = smemu + (c % 3) * GT_STAGE;
        #pragma unroll
        for (int ks = 0; ks < 2; ++ks) {
            const uint32_t kb = ks * 32 + l16 * 16;
            uint32_t a[2][4];
            #pragma unroll
            for (int i = 0; i < 2; ++i) {
                uint32_t aadr = stg + (warp_m * 32 + i * 16 + l8 * 8 + li) * GT_RSB + kb;
                ldsm_x4(a[i][0], a[i][1], a[i][2], a[i][3], aadr);
            }
            #pragma unroll
            for (int j = 0; j < 8; j += 2) {
                // paired x4: matrices for n-tiles j (b0,b1) and j+1 (b2,b3)
                uint32_t badr = stg + GT_ATILE +
                                (warp_n * 64 + j * 8 + l16 * 8 + li) * GT_RSB +
                                ks * 32 + l8 * 16;
                uint32_t b0, b1, b2, b3;
                ldsm_x4(b0, b1, b2, b3, badr);
                #pragma unroll
                for (int i = 0; i < 2; ++i) {
                    mma_f16(acc[i][j],     a[i][0], a[i][1], a[i][2], a[i][3], b0, b1);
                    mma_f16(acc[i][j + 1], a[i][0], a[i][1], a[i][2], a[i][3], b2, b3);
                }
            }
        }

        if (c + 2 < GT_KCH) issue(c + 2, (c + 2) % 3);
        asm volatile("cp.async.commit_group;" ::: "memory");
    }

    #pragma unroll
    for (int j = 0; j < 8; ++j) {
        int col = n0 + warp_n * 64 + j * 8 + kq * 2;
        float b0 = bias[col], b1 = bias[col + 1];
        #pragma unroll
        for (int i = 0; i < 2; ++i) {
            int row = m0 + warp_m * 32 + i * 16 + r4;
            float y0 = acc[i][j][0] + b0, y1 = acc[i][j][1] + b1;
            float y2 = acc[i][j][2] + b0, y3 = acc[i][j][3] + b1;
            if (OUT == 0) {
                *(float2*)&C[(size_t)row * DMOD + col]       = make_float2(y0, y1);
                *(float2*)&C[(size_t)(row + 8) * DMOD + col] = make_float2(y2, y3);
            } else {
                __half2 H0 = __floats2half2_rn(y0 * oscale, y1 * oscale);
                __half2 H1 = __floats2half2_rn(y2 * oscale, y3 * oscale);
                *(__half2*)&Yh[(size_t)row * DMOD + col]       = H0;
                *(__half2*)&Yh[(size_t)(row + 8) * DMOD + col] = H1;
            }
        }
    }
}

// ---------------------------------------------------------------------------
// Flash attention (frozen since R10): fp16 mma + ldmatrix.
// CTA: one (b,h), 128 q rows; 8 warps, each owns 16 full rows.
// Single-product QK^T; P fp16; V fp16. Output fp16. K/V double-buffered.
// ---------------------------------------------------------------------------
#define FL_RSQ  272                   // 128 halves*2B + 16B pad
#define FL_RSV  144                   // 64 halves*2B + 16B pad
#define FL_QHS  0                     // Q: 34816
#define FL_K0   34816                 // K double buf: 2*17408
#define FL_V0   69632                 // V double buf: 2*18432
#define FL_SMEM 106496

__global__ __launch_bounds__(256, 1)
void flash_mma_kernel(const __half* __restrict__ Qh,
                      const __half* __restrict__ Kh,
                      const __half* __restrict__ Vh,
                      __half* __restrict__ O16)
{
    extern __shared__ char smem[];
    const uint32_t su = smem_to_u32(smem);
    const int tid  = threadIdx.x;
    const int lane = tid & 31;
    const int wid  = tid >> 5;
    const int r4 = lane >> 2, kq = lane & 3;
    const int li  = lane & 7;
    const int l8  = (lane >> 3) & 1;
    const int l16 = (lane >> 4) & 1;
    const int q0 = blockIdx.x << 7;
    const int h  = blockIdx.y, b = blockIdx.z;
    const size_t qkbase = (size_t)b * SEQ * DMOD + (size_t)h * DKH;
    const size_t vtbase = ((size_t)b * NHEAD + h) * DKH * SEQ;

    auto load_kv = [&](int t, int st) {
        const int n0 = t << 6;
        const uint32_t kd = su + FL_K0 + st * 17408;
        const uint32_t vd = su + FL_V0 + st * 18432;
        #pragma unroll
        for (int u = 0; u < 4; u++) {
            int idx = u * 256 + tid;
            int r = idx >> 4, sg = idx & 15;
            cp_async16(kd + r * FL_RSQ + sg * 16,
                       Kh + qkbase + (size_t)(n0 + r) * DMOD + sg * 8);
        }
        #pragma unroll
        for (int u = 0; u < 4; u++) {
            int idx = u * 256 + tid;
            int r = idx >> 3, sg = idx & 7;
            cp_async16(vd + r * FL_RSV + sg * 16,
                       Vh + vtbase + (size_t)r * SEQ + n0 + sg * 8);
        }
    };

    #pragma unroll
    for (int u = 0; u < 8; u++) {
        int idx = u * 256 + tid;
        int r = idx >> 4, sg = idx & 15;
        cp_async16(su + FL_QHS + r * FL_RSQ + sg * 16,
                   Qh + qkbase + (size_t)(q0 + r) * DMOD + sg * 8);
    }
    asm volatile("cp.async.commit_group;" ::: "memory");
    load_kv(0, 0);
    asm volatile("cp.async.commit_group;" ::: "memory");
    asm volatile("cp.async.wait_group 0;" ::: "memory");
    __syncthreads();

    const uint32_t qrowoff = (wid * 16 + l8 * 8 + li) * FL_RSQ + l16 * 16;
    uint32_t aqh[8][4];
    #pragma unroll
    for (int k = 0; k < 8; k++)
        ldsm_x4(aqh[k][0], aqh[k][1], aqh[k][2], aqh[k][3],
                su + FL_QHS + qrowoff + k * 32);

    float oc[16][4];
    #pragma unroll
    for (int nf = 0; nf < 16; nf++)
        #pragma unroll
        for (int p = 0; p < 4; p++) oc[nf][p] = 0.f;
    float m0 = -1e30f, m1 = -1e30f, l0 = 0.f, l1 = 0.f;

    for (int t = 0; t < 32; t++) {
        const int st = t & 1;
        const uint32_t ks = su + FL_K0 + st * 17408;
        const uint32_t vs = su + FL_V0 + st * 18432;

        if (t + 1 < 32) {
            load_kv(t + 1, st ^ 1);
            asm volatile("cp.async.commit_group;" ::: "memory");
        }

        float sc[8][4];
        #pragma unroll
        for (int nf = 0; nf < 8; nf++)
            #pragma unroll
            for (int p = 0; p < 4; p++) sc[nf][p] = 0.f;

        #pragma unroll
        for (int k = 0; k < 8; k++) {
            #pragma unroll
            for (int nf = 0; nf < 8; nf += 2) {
                uint32_t kadr = ks + (nf * 8 + l16 * 8 + li) * FL_RSQ +
                                l8 * 16 + k * 32;
                uint32_t k0, k1, k2, k3;
                ldsm_x4(k0, k1, k2, k3, kadr);
                mma_f16(sc[nf],     aqh[k][0], aqh[k][1], aqh[k][2], aqh[k][3], k0, k1);
                mma_f16(sc[nf + 1], aqh[k][0], aqh[k][1], aqh[k][2], aqh[k][3], k2, k3);
            }
        }

        float mx0 = -1e30f, mx1 = -1e30f;
        #pragma unroll
        for (int nf = 0; nf < 8; nf++) {
            mx0 = fmaxf(mx0, fmaxf(sc[nf][0], sc[nf][1]));
            mx1 = fmaxf(mx1, fmaxf(sc[nf][2], sc[nf][3]));
        }
        mx0 = fmaxf(mx0, __shfl_xor_sync(0xffffffffu, mx0, 1));
        mx0 = fmaxf(mx0, __shfl_xor_sync(0xffffffffu, mx0, 2));
        mx1 = fmaxf(mx1, __shfl_xor_sync(0xffffffffu, mx1, 1));
        mx1 = fmaxf(mx1, __shfl_xor_sync(0xffffffffu, mx1, 2));

        const float mn0 = fmaxf(m0, mx0), mn1 = fmaxf(m1, mx1);
        const float c0 = __expf(m0 - mn0), c1 = __expf(m1 - mn1);
        float s0 = 0.f, s1 = 0.f;
        uint32_t pa[4][4];
        #pragma unroll
        for (int nf = 0; nf < 8; nf++) {
            float p0 = __expf(sc[nf][0] - mn0);
            float p1 = __expf(sc[nf][1] - mn0);
            float p2 = __expf(sc[nf][2] - mn1);
            float p3 = __expf(sc[nf][3] - mn1);
            s0 += p0 + p1; s1 += p2 + p3;
            __half2 hA = __floats2half2_rn(p0, p1);
            __half2 hB = __floats2half2_rn(p2, p3);
            pa[nf >> 1][(nf & 1) ? 2 : 0] = *(uint32_t*)&hA;
            pa[nf >> 1][(nf & 1) ? 3 : 1] = *(uint32_t*)&hB;
        }
        s0 += __shfl_xor_sync(0xffffffffu, s0, 1);
        s0 += __shfl_xor_sync(0xffffffffu, s0, 2);
        s1 += __shfl_xor_sync(0xffffffffu, s1, 1);
        s1 += __shfl_xor_sync(0xffffffffu, s1, 2);
        l0 = l0 * c0 + s0; m0 = mn0;
        l1 = l1 * c1 + s1; m1 = mn1;
        #pragma unroll
        for (int nf = 0; nf < 16; nf++) {
            oc[nf][0] *= c0; oc[nf][1] *= c0;
            oc[nf][2] *= c1; oc[nf][3] *= c1;
        }

        #pragma unroll
        for (int k = 0; k < 4; k++) {
            #pragma unroll
            for (int nf = 0; nf < 16; nf += 2) {
                uint32_t vadr = vs + (nf * 8 + l16 * 8 + li) * FL_RSV +
                                k * 32 + l8 * 16;
                uint32_t v0, v1, v2, v3;
                ldsm_x4(v0, v1, v2, v3, vadr);
                mma_f16(oc[nf],     pa[k][0], pa[k][1], pa[k][2], pa[k][3], v0, v1);
                mma_f16(oc[nf + 1], pa[k][0], pa[k][1], pa[k][2], pa[k][3], v2, v3);
            }
        }

        if (t + 1 < 32) {
            asm volatile("cp.async.wait_group 0;" ::: "memory");
            __syncthreads();
        }
    }

    const float inv0 = 1.f / l0, inv1 = 1.f / l1;
    #pragma unroll
    for (int nf = 0; nf < 16; nf++) {
        int col  = nf * 8 + kq * 2;
        int row0 = q0 + wid * 16 + r4;
        __half2 H0 = __floats2half2_rn(oc[nf][0] * inv0, oc[nf][1] * inv0);
        __half2 H1 = __floats2half2_rn(oc[nf][2] * inv1, oc[nf][3] * inv1);
        *(__half2*)&O16[qkbase + (size_t)row0 * DMOD + col]       = H0;
        *(__half2*)&O16[qkbase + (size_t)(row0 + 8) * DMOD + col] = H1;
    }
}

// ---------------------------------------------------------------------------
// Launch
// ---------------------------------------------------------------------------
extern "C" void kernel_launch(void* const* d_in, const int* in_sizes, int n_in,
                              void* d_out, int out_size)
{
    const float* q  = (const float*)d_in[0];
    const float* k  = (const float*)d_in[1];
    const float* v  = (const float*)d_in[2];
    const float* Wq = (const float*)d_in[3];
    const float* bq = (const float*)d_in[4];
    const float* Wk = (const float*)d_in[5];
    const float* bk = (const float*)d_in[6];
    const float* Wv = (const float*)d_in[7];
    const float* bv = (const float*)d_in[8];
    const float* Wo = (const float*)d_in[9];
    const float* bo = (const float*)d_in[10];
    float* out = (float*)d_out;

    __half *A16, *Wt16, *Qh, *Kh, *V16, *Vth, *O16;
    cudaGetSymbolAddress((void**)&A16,  g_A16);
    cudaGetSymbolAddress((void**)&Wt16, g_Wt16);
    cudaGetSymbolAddress((void**)&Qh,   g_Qh);
    cudaGetSymbolAddress((void**)&Kh,   g_Kh16);
    cudaGetSymbolAddress((void**)&V16,  g_V16);
    cudaGetSymbolAddress((void**)&Vth,  g_Vth);
    cudaGetSymbolAddress((void**)&O16,  g_O16);

    cudaFuncSetAttribute(gemm_mma_kernel<0>,
                         cudaFuncAttributeMaxDynamicSharedMemorySize, GT_SMEM);
    cudaFuncSetAttribute(gemm_mma_kernel<1>,
                         cudaFuncAttributeMaxDynamicSharedMemorySize, GT_SMEM);
    cudaFuncSetAttribute(flash_mma_kernel,
                         cudaFuncAttributeMaxDynamicSharedMemorySize, FL_SMEM);

    const dim3 gt(DMOD / 32, DMOD / 32);          // W transpose grid
    const dim3 gg(DMOD / 128, TOK / 256);         // gemm grid (16, 16)
    const int  ga = (TOK * DMOD) / (256 * 8);     // elementwise grids
    const float scale = 0.08838834764831845f;     // 1/sqrt(128)

    // Q projection -> fp16 (pre-scaled)
    h16_kernel<<<ga, 256>>>(q, A16);
    wt_kernel<<<gt, 256>>>(Wq, Wt16);
    gemm_mma_kernel<1><<<gg, 512, GT_SMEM>>>(A16, Wt16, bq, nullptr, Qh, scale);

    // K projection -> fp16
    h16_kernel<<<ga, 256>>>(k, A16);
    wt_kernel<<<gt, 256>>>(Wk, Wt16);
    gemm_mma_kernel<1><<<gg, 512, GT_SMEM>>>(A16, Wt16, bk, nullptr, Kh, 1.0f);

    // V projection -> fp16, then per-head transpose
    h16_kernel<<<ga, 256>>>(v, A16);
    wt_kernel<<<gt, 256>>>(Wv, Wt16);
    gemm_mma_kernel<1><<<gg, 512, GT_SMEM>>>(A16, Wt16, bv, nullptr, V16, 1.0f);
    vtrans_kernel<<<dim3(SEQ / 32, DKH / 32, 2 * NHEAD), 256>>>(V16, Vth);

    // attention -> fp16 directly into final-GEMM A operand
    flash_mma_kernel<<<dim3(SEQ / 128, NHEAD, 2), 256, FL_SMEM>>>(
        Qh, Kh, Vth, O16);

    // output projection (fp32 out)
    wt_kernel<<<gt, 256>>>(Wo, Wt16);
    gemm_mma_kernel<0><<<gg, 512, GT_SMEM>>>(O16, Wt16, bo, out, nullptr, 1.0f);
}

// round 15
// speedup vs baseline: 7.8959x; 1.0449x over previous
#include <cuda_runtime.h>
#include <cuda_bf16.h>
#include <cuda_fp16.h>
#include <cstdint>

#define TOK   4096      // B*S tokens
#define DMOD  2048      // model dim
#define SEQ   2048      // sequence length
#define NHEAD 16
#define DKH   128       // head dim

// Scratch (device globals: allocation-free per harness rules)
__device__ __half g_X16[3][(size_t)TOK * DMOD]; // q,k,v fp16 inputs
__device__ __half g_Wt4[4][(size_t)DMOD * DMOD];// W^T fp16 [N][K] x {q,k,v,o}
__device__ __half g_Qh[(size_t)TOK * DMOD];     // Q*scale fp16
__device__ __half g_Kh16[(size_t)TOK * DMOD];   // K fp16
__device__ __half g_V16[(size_t)TOK * DMOD];    // V proj fp16 [b,s,d]
__device__ __half g_Vth[(size_t)TOK * DMOD];    // V^T fp16 [b,h,d,s]
__device__ __half g_O16[(size_t)TOK * DMOD];    // attention output fp16

// ---------------------------------------------------------------------------
// helpers
// ---------------------------------------------------------------------------
__device__ __forceinline__ uint32_t smem_to_u32(const void* p) {
    uint32_t a;
    asm("{ .reg .u64 t; cvta.to.shared.u64 t, %1; cvt.u32.u64 %0, t; }"
        : "=r"(a) : "l"(p));
    return a;
}

__device__ __forceinline__ void cp_async16(uint32_t dst, const void* src) {
    asm volatile("cp.async.cg.shared.global [%0], [%1], 16;"
                 :: "r"(dst), "l"(src));
}

__device__ __forceinline__ void ldsm_x4(uint32_t& r0, uint32_t& r1,
                                        uint32_t& r2, uint32_t& r3, uint32_t addr) {
    asm volatile("ldmatrix.sync.aligned.m8n8.x4.shared.b16 {%0,%1,%2,%3}, [%4];"
                 : "=r"(r0), "=r"(r1), "=r"(r2), "=r"(r3) : "r"(addr));
}

__device__ __forceinline__ void mma_f16(float* c,
    uint32_t a0, uint32_t a1, uint32_t a2, uint32_t a3,
    uint32_t b0, uint32_t b1)
{
    asm volatile(
        "mma.sync.aligned.m16n8k16.row.col.f32.f16.f16.f32 "
        "{%0,%1,%2,%3}, {%4,%5,%6,%7}, {%8,%9}, {%0,%1,%2,%3};"
        : "+f"(c[0]), "+f"(c[1]), "+f"(c[2]), "+f"(c[3])
        : "r"(a0), "r"(a1), "r"(a2), "r"(a3), "r"(b0), "r"(b1));
}

// ---------------------------------------------------------------------------
// Batched W transpose+convert: W[K][N] fp32 -> T[N][K] fp16, 4 weights.
// ---------------------------------------------------------------------------
__global__ __launch_bounds__(256)
void wt4_kernel(const float* __restrict__ W0, const float* __restrict__ W1,
                const float* __restrict__ W2, const float* __restrict__ W3,
                __half* __restrict__ T)
{
    __shared__ float ts[32][33];
    const int tx = threadIdx.x & 31;
    const int ty = threadIdx.x >> 5;
    const int n0 = blockIdx.x * 32;
    const int k0 = blockIdx.y * 32;
    const int w  = blockIdx.z;
    const float* W = (w == 0) ? W0 : (w == 1) ? W1 : (w == 2) ? W2 : W3;
    __half* Tw = T + (size_t)w * DMOD * DMOD;

    #pragma unroll
    for (int j = 0; j < 32; j += 8)
        ts[ty + j][tx] = W[(size_t)(k0 + ty + j) * DMOD + n0 + tx];
    __syncthreads();

    #pragma unroll
    for (int j = 0; j < 32; j += 8)
        Tw[(size_t)(n0 + ty + j) * DMOD + k0 + tx] =
            __float2half_rn(ts[tx][ty + j]);
}

// ---------------------------------------------------------------------------
// Batched fp32 -> fp16 elementwise: q,k,v in one launch (blockIdx.y selects)
// ---------------------------------------------------------------------------
__global__ __launch_bounds__(256)
void h16x3_kernel(const float* __restrict__ X0, const float* __restrict__ X1,
                  const float* __restrict__ X2, __half* __restrict__ Y)
{
    const int t = blockIdx.y;
    const float* X = (t == 0) ? X0 : (t == 1) ? X1 : X2;
    __half* Yt = Y + (size_t)t * TOK * DMOD;
    size_t i = ((size_t)blockIdx.x * 256 + threadIdx.x) * 8;
    float4 f0 = *(const float4*)(X + i);
    float4 f1 = *(const float4*)(X + i + 4);
    __half2 h0 = __floats2half2_rn(f0.x, f0.y);
    __half2 h1 = __floats2half2_rn(f0.z, f0.w);
    __half2 h2 = __floats2half2_rn(f1.x, f1.y);
    __half2 h3 = __floats2half2_rn(f1.z, f1.w);
    *(uint4*)(Yt + i) = make_uint4(*(uint32_t*)&h0, *(uint32_t*)&h1,
                                   *(uint32_t*)&h2, *(uint32_t*)&h3);
}

// ---------------------------------------------------------------------------
// V transpose: V16 [b,s,h*128+d] fp16 -> Vth [(b*16+h)*128+d][s] fp16
// ---------------------------------------------------------------------------
__global__ __launch_bounds__(256)
void vtrans_kernel(const __half* __restrict__ Vp, __half* __restrict__ Vh)
{
    __shared__ float ts[32][33];
    const int tx = threadIdx.x & 31;
    const int ty = threadIdx.x >> 5;
    const int bh = blockIdx.z;
    const int b  = bh >> 4, h = bh & 15;
    const int s0 = blockIdx.x * 32;
    const int d0 = blockIdx.y * 32;

    #pragma unroll
    for (int j = 0; j < 32; j += 8)
        ts[ty + j][tx] = __half2float(
            Vp[((size_t)b * SEQ + s0 + ty + j) * DMOD + h * DKH + d0 + tx]);
    __syncthreads();

    #pragma unroll
    for (int j = 0; j < 32; j += 8)
        Vh[((size_t)bh * DKH + d0 + ty + j) * SEQ + s0 + tx] =
            __float2half_rn(ts[tx][ty + j]);
}

// ---------------------------------------------------------------------------
// fp16 mma GEMM, single product: C = A @ W + bias.
// A fp16 [M][K]; B fp16 [N][K]. CTA tile 256x128, BK=64, 3-stage cp.async,
// 512 threads = 16 warps (8Mx2N), warp tile 32x64, ldmatrix loads.
// Same per-output k-accumulation order as BK=32 (bit-identical results).
// OUT=0: fp32 C.   OUT=1: fp16 of (C+bias)*oscale.
// ---------------------------------------------------------------------------
#define GT_RSB    144                 // 64 halves*2B + 16B pad (144/16=9, odd)
#define GT_ATILE  (256 * GT_RSB)      // 36864
#define GT_BTILE  (128 * GT_RSB)      // 18432
#define GT_STAGE  (GT_ATILE + GT_BTILE)   // 55296
#define GT_SMEM   (3 * GT_STAGE)      // 165888
#define GT_KCH    32                  // BK=64 chunks over K=2048

template<int OUT>
__global__ __launch_bounds__(512, 1)
void gemm_mma_kernel(const __half* __restrict__ A,
                     const __half* __restrict__ B,
                     const float* __restrict__ bias,
                     float* __restrict__ C,
                     __half* __restrict__ Yh,
                     float oscale)
{
    extern __shared__ char smem[];
    const uint32_t smemu = smem_to_u32(smem);
    const int tid    = threadIdx.x;
    const int lane   = tid & 31;
    const int wid    = tid >> 5;
    const int warp_m = wid & 7;       // 8 m-warps: rows warp_m*32..+31
    const int warp_n = wid >> 3;      // 2 n-warps: cols warp_n*64..+63
    const int r4     = lane >> 2;
    const int kq     = lane & 3;
    const int li  = lane & 7;
    const int l8  = (lane >> 3) & 1;
    const int l16 = (lane >> 4) & 1;
    const int n0 = blockIdx.x << 7;   // 128-wide n tile
    const int m0 = blockIdx.y << 8;   // 256-wide m tile

    float acc[2][8][4];
    #pragma unroll
    for (int i = 0; i < 2; i++)
        #pragma unroll
        for (int j = 0; j < 8; j++)
            #pragma unroll
            for (int p = 0; p < 4; p++) acc[i][j][p] = 0.f;

    // A: 256 rows x 8 segs = 2048 units; B: 128 x 8 = 1024; 6/thread
    auto issue = [&](int c, int s) {
        const int k0e = c << 6;
        #pragma unroll
        for (int it = 0; it < 6; ++it) {
            int idx = it * 512 + tid;          // 0..3071
            const __half* src;
            uint32_t dst;
            if (idx < 2048) {                  // A tile
                int r  = idx >> 3;
                int cc = idx & 7;
                src = A + (size_t)(m0 + r) * DMOD + k0e + cc * 8;
                dst = smemu + s * GT_STAGE + r * GT_RSB + cc * 16;
            } else {                           // B tile
                int u  = idx - 2048;
                int r  = u >> 3;
                int cc = u & 7;
                src = B + (size_t)(n0 + r) * DMOD + k0e + cc * 8;
                dst = smemu + s * GT_STAGE + GT_ATILE + r * GT_RSB + cc * 16;
            }
            cp_async16(dst, src);
        }
    };

    issue(0, 0);
    asm volatile("cp.async.commit_group;" ::: "memory");
    issue(1, 1);
    asm volatile("cp.async.commit_group;" ::: "memory");

    for (int c = 0; c < GT_KCH; ++c) {
        asm volatile("cp.async.wait_group 1;" ::: "memory");
        __syncthreads();

        const uint32_t stg = smemu + (c % 3) * GT_STAGE;
        #pragma unroll
        for (int ks = 0; ks < 4; ++ks) {
            const uint32_t kb = ks * 32 + l16 * 16;
            uint32_t a[2][4];
            #pragma unroll
            for (int i = 0; i < 2; ++i) {
                uint32_t aadr = stg + (warp_m * 32 + i * 16 + l8 * 8 + li) * GT_RSB + kb;
                ldsm_x4(a[i][0], a[i][1], a[i][2], a[i][3], aadr);
            }
            #pragma unroll
            for (int j = 0; j < 8; j += 2) {
                // paired x4: matrices for n-tiles j (b0,b1) and j+1 (b2,b3)
                uint32_t badr = stg + GT_ATILE +
                                (warp_n * 64 + j * 8 + l16 * 8 + li) * GT_RSB +
                                ks * 32 + l8 * 16;
                uint32_t b0, b1, b2, b3;
                ldsm_x4(b0, b1, b2, b3, badr);
                #pragma unroll
                for (int i = 0; i < 2; ++i) {
                    mma_f16(acc[i][j],     a[i][0], a[i][1], a[i][2], a[i][3], b0, b1);
                    mma_f16(acc[i][j + 1], a[i][0], a[i][1], a[i][2], a[i][3], b2, b3);
                }
            }
        }

        if (c + 2 < GT_KCH) issue(c + 2, (c + 2) % 3);
        asm volatile("cp.async.commit_group;" ::: "memory");
    }

    #pragma unroll
    for (int j = 0; j < 8; ++j) {
        int col = n0 + warp_n * 64 + j * 8 + kq * 2;
        float b0 = bias[col], b1 = bias[col + 1];
        #pragma unroll
        for (int i = 0; i < 2; ++i) {
            int row = m0 + warp_m * 32 + i * 16 + r4;
            float y0 = acc[i][j][0] + b0, y1 = acc[i][j][1] + b1;
            float y2 = acc[i][j][2] + b0, y3 = acc[i][j][3] + b1;
            if (OUT == 0) {
                *(float2*)&C[(size_t)row * DMOD + col]       = make_float2(y0, y1);
                *(float2*)&C[(size_t)(row + 8) * DMOD + col] = make_float2(y2, y3);
            } else {
                __half2 H0 = __floats2half2_rn(y0 * oscale, y1 * oscale);
                __half2 H1 = __floats2half2_rn(y2 * oscale, y3 * oscale);
                *(__half2*)&Yh[(size_t)row * DMOD + col]       = H0;
                *(__half2*)&Yh[(size_t)(row + 8) * DMOD + col] = H1;
            }
        }
    }
}

// ---------------------------------------------------------------------------
// Flash attention (frozen since R10): fp16 mma + ldmatrix.
// CTA: one (b,h), 128 q rows; 8 warps, each owns 16 full rows.
// Single-product QK^T; P fp16; V fp16. Output fp16. K/V double-buffered.
// ---------------------------------------------------------------------------
#define FL_RSQ  272                   // 128 halves*2B + 16B pad
#define FL_RSV  144                   // 64 halves*2B + 16B pad
#define FL_QHS  0                     // Q: 34816
#define FL_K0   34816                 // K double buf: 2*17408
#define FL_V0   69632                 // V double buf: 2*18432
#define FL_SMEM 106496

__global__ __launch_bounds__(256, 1)
void flash_mma_kernel(const __half* __restrict__ Qh,
                      const __half* __restrict__ Kh,
                      const __half* __restrict__ Vh,
                      __half* __restrict__ O16)
{
    extern __shared__ char smem[];
    const uint32_t su = smem_to_u32(smem);
    const int tid  = threadIdx.x;
    const int lane = tid & 31;
    const int wid  = tid >> 5;
    const int r4 = lane >> 2, kq = lane & 3;
    const int li  = lane & 7;
    const int l8  = (lane >> 3) & 1;
    const int l16 = (lane >> 4) & 1;
    const int q0 = blockIdx.x << 7;
    const int h  = blockIdx.y, b = blockIdx.z;
    const size_t qkbase = (size_t)b * SEQ * DMOD + (size_t)h * DKH;
    const size_t vtbase = ((size_t)b * NHEAD + h) * DKH * SEQ;

    auto load_kv = [&](int t, int st) {
        const int n0 = t << 6;
        const uint32_t kd = su + FL_K0 + st * 17408;
        const uint32_t vd = su + FL_V0 + st * 18432;
        #pragma unroll
        for (int u = 0; u < 4; u++) {
            int idx = u * 256 + tid;
            int r = idx >> 4, sg = idx & 15;
            cp_async16(kd + r * FL_RSQ + sg * 16,
                       Kh + qkbase + (size_t)(n0 + r) * DMOD + sg * 8);
        }
        #pragma unroll
        for (int u = 0; u < 4; u++) {
            int idx = u * 256 + tid;
            int r = idx >> 3, sg = idx & 7;
            cp_async16(vd + r * FL_RSV + sg * 16,
                       Vh + vtbase + (size_t)r * SEQ + n0 + sg * 8);
        }
    };

    #pragma unroll
    for (int u = 0; u < 8; u++) {
        int idx = u * 256 + tid;
        int r = idx >> 4, sg = idx & 15;
        cp_async16(su + FL_QHS + r * FL_RSQ + sg * 16,
                   Qh + qkbase + (size_t)(q0 + r) * DMOD + sg * 8);
    }
    asm volatile("cp.async.commit_group;" ::: "memory");
    load_kv(0, 0);
    asm volatile("cp.async.commit_group;" ::: "memory");
    asm volatile("cp.async.wait_group 0;" ::: "memory");
    __syncthreads();

    const uint32_t qrowoff = (wid * 16 + l8 * 8 + li) * FL_RSQ + l16 * 16;
    uint32_t aqh[8][4];
    #pragma unroll
    for (int k = 0; k < 8; k++)
        ldsm_x4(aqh[k][0], aqh[k][1], aqh[k][2], aqh[k][3],
                su + FL_QHS + qrowoff + k * 32);

    float oc[16][4];
    #pragma unroll
    for (int nf = 0; nf < 16; nf++)
        #pragma unroll
        for (int p = 0; p < 4; p++) oc[nf][p] = 0.f;
    float m0 = -1e30f, m1 = -1e30f, l0 = 0.f, l1 = 0.f;

    for (int t = 0; t < 32; t++) {
        const int st = t & 1;
        const uint32_t ks = su + FL_K0 + st * 17408;
        const uint32_t vs = su + FL_V0 + st * 18432;

        if (t + 1 < 32) {
            load_kv(t + 1, st ^ 1);
            asm volatile("cp.async.commit_group;" ::: "memory");
        }

        float sc[8][4];
        #pragma unroll
        for (int nf = 0; nf < 8; nf++)
            #pragma unroll
            for (int p = 0; p < 4; p++) sc[nf][p] = 0.f;

        #pragma unroll
        for (int k = 0; k < 8; k++) {
            #pragma unroll
            for (int nf = 0; nf < 8; nf += 2) {
                uint32_t kadr = ks + (nf * 8 + l16 * 8 + li) * FL_RSQ +
                                l8 * 16 + k * 32;
                uint32_t k0, k1, k2, k3;
                ldsm_x4(k0, k1, k2, k3, kadr);
                mma_f16(sc[nf],     aqh[k][0], aqh[k][1], aqh[k][2], aqh[k][3], k0, k1);
                mma_f16(sc[nf + 1], aqh[k][0], aqh[k][1], aqh[k][2], aqh[k][3], k2, k3);
            }
        }

        float mx0 = -1e30f, mx1 = -1e30f;
        #pragma unroll
        for (int nf = 0; nf < 8; nf++) {
            mx0 = fmaxf(mx0, fmaxf(sc[nf][0], sc[nf][1]));
            mx1 = fmaxf(mx1, fmaxf(sc[nf][2], sc[nf][3]));
        }
        mx0 = fmaxf(mx0, __shfl_xor_sync(0xffffffffu, mx0, 1));
        mx0 = fmaxf(mx0, __shfl_xor_sync(0xffffffffu, mx0, 2));
        mx1 = fmaxf(mx1, __shfl_xor_sync(0xffffffffu, mx1, 1));
        mx1 = fmaxf(mx1, __shfl_xor_sync(0xffffffffu, mx1, 2));

        const float mn0 = fmaxf(m0, mx0), mn1 = fmaxf(m1, mx1);
        const float c0 = __expf(m0 - mn0), c1 = __expf(m1 - mn1);
        float s0 = 0.f, s1 = 0.f;
        uint32_t pa[4][4];
        #pragma unroll
        for (int nf = 0; nf < 8; nf++) {
            float p0 = __expf(sc[nf][0] - mn0);
            float p1 = __expf(sc[nf][1] - mn0);
            float p2 = __expf(sc[nf][2] - mn1);
            float p3 = __expf(sc[nf][3] - mn1);
            s0 += p0 + p1; s1 += p2 + p3;
            __half2 hA = __floats2half2_rn(p0, p1);
            __half2 hB = __floats2half2_rn(p2, p3);
            pa[nf >> 1][(nf & 1) ? 2 : 0] = *(uint32_t*)&hA;
            pa[nf >> 1][(nf & 1) ? 3 : 1] = *(uint32_t*)&hB;
        }
        s0 += __shfl_xor_sync(0xffffffffu, s0, 1);
        s0 += __shfl_xor_sync(0xffffffffu, s0, 2);
        s1 += __shfl_xor_sync(0xffffffffu, s1, 1);
        s1 += __shfl_xor_sync(0xffffffffu, s1, 2);
        l0 = l0 * c0 + s0; m0 = mn0;
        l1 = l1 * c1 + s1; m1 = mn1;
        #pragma unroll
        for (int nf = 0; nf < 16; nf++) {
            oc[nf][0] *= c0; oc[nf][1] *= c0;
            oc[nf][2] *= c1; oc[nf][3] *= c1;
        }

        #pragma unroll
        for (int k = 0; k < 4; k++) {
            #pragma unroll
            for (int nf = 0; nf < 16; nf += 2) {
                uint32_t vadr = vs + (nf * 8 + l16 * 8 + li) * FL_RSV +
                                k * 32 + l8 * 16;
                uint32_t v0, v1, v2, v3;
                ldsm_x4(v0, v1, v2, v3, vadr);
                mma_f16(oc[nf],     pa[k][0], pa[k][1], pa[k][2], pa[k][3], v0, v1);
                mma_f16(oc[nf + 1], pa[k][0], pa[k][1], pa[k][2], pa[k][3], v2, v3);
            }
        }

        if (t + 1 < 32) {
            asm volatile("cp.async.wait_group 0;" ::: "memory");
            __syncthreads();
        }
    }

    const float inv0 = 1.f / l0, inv1 = 1.f / l1;
    #pragma unroll
    for (int nf = 0; nf < 16; nf++) {
        int col  = nf * 8 + kq * 2;
        int row0 = q0 + wid * 16 + r4;
        __half2 H0 = __floats2half2_rn(oc[nf][0] * inv0, oc[nf][1] * inv0);
        __half2 H1 = __floats2half2_rn(oc[nf][2] * inv1, oc[nf][3] * inv1);
        *(__half2*)&O16[qkbase + (size_t)row0 * DMOD + col]       = H0;
        *(__half2*)&O16[qkbase + (size_t)(row0 + 8) * DMOD + col] = H1;
    }
}

// ---------------------------------------------------------------------------
// Launch
// ---------------------------------------------------------------------------
extern "C" void kernel_launch(void* const* d_in, const int* in_sizes, int n_in,
                              void* d_out, int out_size)
{
    const float* q  = (const float*)d_in[0];
    const float* k  = (const float*)d_in[1];
    const float* v  = (const float*)d_in[2];
    const float* Wq = (const float*)d_in[3];
    const float* bq = (const float*)d_in[4];
    const float* Wk = (const float*)d_in[5];
    const float* bk = (const float*)d_in[6];
    const float* Wv = (const float*)d_in[7];
    const float* bv = (const float*)d_in[8];
    const float* Wo = (const float*)d_in[9];
    const float* bo = (const float*)d_in[10];
    float* out = (float*)d_out;

    __half *X16, *Wt4, *Qh, *Kh, *V16, *Vth, *O16;
    cudaGetSymbolAddress((void**)&X16,  g_X16);
    cudaGetSymbolAddress((void**)&Wt4,  g_Wt4);
    cudaGetSymbolAddress((void**)&Qh,   g_Qh);
    cudaGetSymbolAddress((void**)&Kh,   g_Kh16);
    cudaGetSymbolAddress((void**)&V16,  g_V16);
    cudaGetSymbolAddress((void**)&Vth,  g_Vth);
    cudaGetSymbolAddress((void**)&O16,  g_O16);

    const size_t XP = (size_t)TOK * DMOD;       // per-tensor plane
    const size_t WP = (size_t)DMOD * DMOD;

    cudaFuncSetAttribute(gemm_mma_kernel<0>,
                         cudaFuncAttributeMaxDynamicSharedMemorySize, GT_SMEM);
    cudaFuncSetAttribute(gemm_mma_kernel<1>,
                         cudaFuncAttributeMaxDynamicSharedMemorySize, GT_SMEM);
    cudaFuncSetAttribute(flash_mma_kernel,
                         cudaFuncAttributeMaxDynamicSharedMemorySize, FL_SMEM);

    const dim3 gt(DMOD / 32, DMOD / 32, 4);       // batched W transpose
    const dim3 gg(DMOD / 128, TOK / 256);         // gemm grid (16, 16)
    const dim3 gh((TOK * DMOD) / (256 * 8), 3);   // batched h16
    const float scale = 0.08838834764831845f;     // 1/sqrt(128)

    // all conversions upfront (2 launches)
    h16x3_kernel<<<gh, 256>>>(q, k, v, X16);
    wt4_kernel<<<gt, 256>>>(Wq, Wk, Wv, Wo, Wt4);

    // projections back-to-back
    gemm_mma_kernel<1><<<gg, 512, GT_SMEM>>>(X16,          Wt4,          bq,
                                             nullptr, Qh,  scale);
    gemm_mma_kernel<1><<<gg, 512, GT_SMEM>>>(X16 + XP,     Wt4 + WP,     bk,
                                             nullptr, Kh,  1.0f);
    gemm_mma_kernel<1><<<gg, 512, GT_SMEM>>>(X16 + 2 * XP, Wt4 + 2 * WP, bv,
                                             nullptr, V16, 1.0f);
    vtrans_kernel<<<dim3(SEQ / 32, DKH / 32, 2 * NHEAD), 256>>>(V16, Vth);

    // attention -> fp16 directly into final-GEMM A operand
    flash_mma_kernel<<<dim3(SEQ / 128, NHEAD, 2), 256, FL_SMEM>>>(
        Qh, Kh, Vth, O16);

    // output projection (fp32 out)
    gemm_mma_kernel<0><<<gg, 512, GT_SMEM>>>(O16, Wt4 + 3 * WP, bo,
                                             out, nullptr, 1.0f);
}